// round 4
// baseline (speedup 1.0000x reference)
#include <cuda_runtime.h>
#include <cuda_bf16.h>

// Problem constants
#define BB 2
#define SS 2048
#define DD 1024
#define HH 16
#define HSZ 64
#define BS (BB * SS)        // 4096 rows
#define D3 (3 * DD)         // 3072
#define DFF (4 * DD)        // 4096

// ---------------- scratch (static device memory; no allocations) ----------------
__device__ float g_xn[BS * DD];
__device__ float g_qkv[BS * D3];
__device__ float g_attn[BS * DD];
__device__ float g_h[BS * DD];
__device__ float g_hn[BS * DD];
__device__ float g_ff[BS * DFF];
__device__ float g_wqkvT[D3 * DD];
__device__ float g_wprojT[DD * DD];
__device__ float g_w1T[DFF * DD];
__device__ float g_w2T[DD * DFF];

// round-to-nearest tf32 (bit pattern is a valid fp32)
__device__ __forceinline__ float f2tf32(float x) {
    unsigned u;
    asm("cvt.rna.tf32.f32 %0, %1;" : "=r"(u) : "f"(x));
    return __uint_as_float(u);
}

// ---------------- LayerNorm (outputs tf32-rounded) ----------------
__global__ void ln_kernel(const float* __restrict__ in, const float* __restrict__ gamma,
                          const float* __restrict__ beta, float* __restrict__ out) {
    int row = blockIdx.x;
    int tid = threadIdx.x;
    float4 xv = ((const float4*)(in + (size_t)row * DD))[tid];

    __shared__ float red[256];
    red[tid] = xv.x + xv.y + xv.z + xv.w;
    __syncthreads();
    #pragma unroll
    for (int off = 128; off > 0; off >>= 1) {
        if (tid < off) red[tid] += red[tid + off];
        __syncthreads();
    }
    float mu = red[0] * (1.0f / DD);
    __syncthreads();

    float dx = xv.x - mu, dy = xv.y - mu, dz = xv.z - mu, dw = xv.w - mu;
    red[tid] = dx * dx + dy * dy + dz * dz + dw * dw;
    __syncthreads();
    #pragma unroll
    for (int off = 128; off > 0; off >>= 1) {
        if (tid < off) red[tid] += red[tid + off];
        __syncthreads();
    }
    float rstd = rsqrtf(red[0] * (1.0f / DD) + 1e-5f);

    float4 gv = ((const float4*)gamma)[tid];
    float4 bv = ((const float4*)beta)[tid];
    float4 ov;
    ov.x = f2tf32(dx * rstd * gv.x + bv.x);
    ov.y = f2tf32(dy * rstd * gv.y + bv.y);
    ov.z = f2tf32(dz * rstd * gv.z + bv.z);
    ov.w = f2tf32(dw * rstd * gv.w + bv.w);
    ((float4*)(out + (size_t)row * DD))[tid] = ov;
}

// ---------------- build wqkvT [3072][1024] (tf32-rounded) ----------------------
__global__ void build_wqkvT_kernel(const float* __restrict__ wq, const float* __restrict__ wk,
                                   const float* __restrict__ wv, float* __restrict__ out) {
    __shared__ float sm[64][65];
    int dblk = blockIdx.x;
    int h = blockIdx.y;
    int part = blockIdx.z;
    const float* w = (part == 0) ? wq : (part == 1) ? wk : wv;
    int tid = threadIdx.x;
    int d0 = dblk * 64;

    int kk = tid & 63;
    int g4 = tid >> 6;
    #pragma unroll
    for (int i = 0; i < 16; i++) {
        int dl = g4 + i * 4;
        sm[dl][kk] = w[((size_t)(h * DD + d0 + dl)) * HSZ + kk];
    }
    __syncthreads();
    int dc = tid & 63;
    #pragma unroll
    for (int i = 0; i < 16; i++) {
        int kk2 = g4 + i * 4;
        out[(size_t)(part * DD + h * HSZ + kk2) * DD + d0 + dc] = f2tf32(sm[dc][kk2]);
    }
}

// ---------------- generic transpose: in[R][C] -> out[C][R] (tf32-rounded) ------
__global__ void transpose_kernel(const float* __restrict__ in, float* __restrict__ out,
                                 int R, int C) {
    __shared__ float t[32][33];
    int x = blockIdx.x * 32 + threadIdx.x;
    int y = blockIdx.y * 32 + threadIdx.y;
    #pragma unroll
    for (int i = 0; i < 32; i += 8)
        t[threadIdx.y + i][threadIdx.x] = in[(size_t)(y + i) * C + x];
    __syncthreads();
    x = blockIdx.y * 32 + threadIdx.x;
    y = blockIdx.x * 32 + threadIdx.y;
    #pragma unroll
    for (int i = 0; i < 32; i += 8)
        out[(size_t)(y + i) * R + x] = f2tf32(t[threadIdx.x][threadIdx.y + i]);
}

// ---------------- tf32 tensor-core GEMM helpers -------------------------------
__device__ __forceinline__ void ldsm_x4(unsigned& r0, unsigned& r1, unsigned& r2, unsigned& r3,
                                        unsigned addr) {
    asm volatile("ldmatrix.sync.aligned.m8n8.x4.shared.b16 {%0,%1,%2,%3}, [%4];"
                 : "=r"(r0), "=r"(r1), "=r"(r2), "=r"(r3) : "r"(addr));
}

__device__ __forceinline__ void mma_tf32(float c[4], unsigned a0, unsigned a1, unsigned a2,
                                         unsigned a3, unsigned b0, unsigned b1) {
    asm volatile(
        "mma.sync.aligned.m16n8k8.row.col.f32.tf32.tf32.f32 "
        "{%0,%1,%2,%3}, {%4,%5,%6,%7}, {%8,%9}, {%0,%1,%2,%3};"
        : "+f"(c[0]), "+f"(c[1]), "+f"(c[2]), "+f"(c[3])
        : "r"(a0), "r"(a1), "r"(a2), "r"(a3), "r"(b0), "r"(b1));
}

#define CPA16(dst, src) \
    asm volatile("cp.async.cg.shared.global [%0], [%1], 16;" :: "r"(dst), "l"(src))

// ---------------- tf32 GEMM: 256x128 tile, BK=32, 512 thr, 3-stage pipeline ----
// stage stride = 49152 B (A 32KB + B 16KB). warp tile 64x32 (4m x 4n warps).
#define GEMM_SMEM (3 * 49152)

// MODE: 0 = plain, 1 = relu + tf32-round, 2 = tf32-round
template <int MODE>
__global__ __launch_bounds__(512, 1)
void gemm_tc(const float* __restrict__ A, const float* __restrict__ Bt,
             const float* __restrict__ bias, const float* __restrict__ res,
             float* __restrict__ C, int M, int N, int K) {
    extern __shared__ unsigned smem_u[];
    unsigned sbase = (unsigned)__cvta_generic_to_shared(smem_u);

    int tid = threadIdx.x;
    int l = tid & 31;
    int wid = tid >> 5;       // 0..15
    int warp_m = wid >> 2;    // 0..3
    int warp_n = wid & 3;     // 0..3
    int bx = blockIdx.x * 128;
    int by = blockIdx.y * 256;

    float acc[4][4][4];
    #pragma unroll
    for (int i = 0; i < 4; i++)
        #pragma unroll
        for (int j = 0; j < 4; j++)
            #pragma unroll
            for (int k = 0; k < 4; k++) acc[i][j][k] = 0.0f;

    // gmem -> smem: lm = row (0..63), kc = 16B chunk; A 4 passes, B 2 passes
    int lm = tid >> 3;
    int kc = tid & 7;
    unsigned physw = (unsigned)((kc ^ (lm & 7)) * 4);
    const float* aptr = A + (size_t)(by + lm) * K + kc * 4;
    const float* bptr = Bt + (size_t)(bx + lm) * K + kc * 4;

    int NT = K / 32;

    int rA = warp_m * 64 + (l & 7) + ((l >> 3) & 1) * 8;
    int rB = warp_n * 32 + (l & 7) + ((l >> 4) & 1) * 8;
    int selA = (l >> 4) & 1;
    int selB = (l >> 3) & 1;
    int l7 = l & 7;

    auto issue = [&](int kt) {
        unsigned sA = sbase + (unsigned)(kt % 3) * 49152u;
        unsigned sB = sA + 32768u;
        const float* ap = aptr + kt * 32;
        const float* bp = bptr + kt * 32;
        #pragma unroll
        for (int i = 0; i < 4; i++) {
            unsigned off = ((lm + 64 * i) * 32 + physw) * 4;
            CPA16(sA + off, ap + (size_t)(64 * i) * K);
        }
        #pragma unroll
        for (int i = 0; i < 2; i++) {
            unsigned off = ((lm + 64 * i) * 32 + physw) * 4;
            CPA16(sB + off, bp + (size_t)(64 * i) * K);
        }
        asm volatile("cp.async.commit_group;");
    };

    issue(0);
    issue(1);

    for (int kt = 0; kt < NT; kt++) {
        if (kt < NT - 1) {
            asm volatile("cp.async.wait_group 1;" ::: "memory");
        } else {
            asm volatile("cp.async.wait_group 0;" ::: "memory");
        }
        __syncthreads();   // stage kt visible to all; prior reads of (kt+2)%3 done

        if (kt + 2 < NT) issue(kt + 2);

        unsigned sA = sbase + (unsigned)(kt % 3) * 49152u;
        unsigned sB = sA + 32768u;

        #pragma unroll
        for (int ks = 0; ks < 4; ks++) {
            int physA = (2 * ks + selA) ^ l7;
            int physB = (2 * ks + selB) ^ l7;
            unsigned aBase = sA + (unsigned)(rA * 32 + physA * 4) * 4;
            unsigned bBase = sB + (unsigned)(rB * 32 + physB * 4) * 4;

            unsigned a[4][4], bf[2][4];
            #pragma unroll
            for (int mt = 0; mt < 4; mt++)
                ldsm_x4(a[mt][0], a[mt][1], a[mt][2], a[mt][3], aBase + mt * 2048u);
            #pragma unroll
            for (int np = 0; np < 2; np++)
                ldsm_x4(bf[np][0], bf[np][1], bf[np][2], bf[np][3], bBase + np * 2048u);

            #pragma unroll
            for (int mt = 0; mt < 4; mt++)
                #pragma unroll
                for (int nt = 0; nt < 4; nt++)
                    mma_tf32(acc[mt][nt], a[mt][0], a[mt][1], a[mt][2], a[mt][3],
                             bf[nt >> 1][(nt & 1) * 2], bf[nt >> 1][(nt & 1) * 2 + 1]);
        }
        __syncthreads();
    }

    int g = l >> 2, tg = l & 3;
    #pragma unroll
    for (int mt = 0; mt < 4; mt++) {
        int r0 = by + warp_m * 64 + mt * 16 + g;
        #pragma unroll
        for (int nt = 0; nt < 4; nt++) {
            int col = bx + warp_n * 32 + nt * 8 + tg * 2;
            float2 v0 = make_float2(acc[mt][nt][0], acc[mt][nt][1]);
            float2 v1 = make_float2(acc[mt][nt][2], acc[mt][nt][3]);
            if (bias != nullptr) {
                float2 bv = *(const float2*)&bias[col];
                v0.x += bv.x; v0.y += bv.y; v1.x += bv.x; v1.y += bv.y;
            }
            if (res != nullptr) {
                float2 q0 = *(const float2*)&res[(size_t)r0 * N + col];
                float2 q1 = *(const float2*)&res[(size_t)(r0 + 8) * N + col];
                v0.x += q0.x; v0.y += q0.y; v1.x += q1.x; v1.y += q1.y;
            }
            if (MODE == 1) {
                v0.x = f2tf32(fmaxf(v0.x, 0.0f)); v0.y = f2tf32(fmaxf(v0.y, 0.0f));
                v1.x = f2tf32(fmaxf(v1.x, 0.0f)); v1.y = f2tf32(fmaxf(v1.y, 0.0f));
            } else if (MODE == 2) {
                v0.x = f2tf32(v0.x); v0.y = f2tf32(v0.y);
                v1.x = f2tf32(v1.x); v1.y = f2tf32(v1.y);
            }
            *(float2*)&C[(size_t)r0 * N + col] = v0;
            *(float2*)&C[(size_t)(r0 + 8) * N + col] = v1;
        }
    }
}

// ---------------- tf32 tensor-core flash attention ----------------------------
// 128-query tile per CTA, 8 warps x 16 rows; 64-key tiles.
// smem (floats): Q[128][64] @0, K[64][64] @8192, VT[64][64] @12288, P[128][64] @16384
#define ATT_SMEM (24576 * 4)

__global__ __launch_bounds__(256, 2)
void attn_tc(const float* __restrict__ qkv, float* __restrict__ out) {
    extern __shared__ float sm[];
    unsigned ub = (unsigned)__cvta_generic_to_shared(sm);
    unsigned uQ = ub, uK = ub + 8192u * 4, uV = ub + 12288u * 4, uP = ub + 16384u * 4;

    int tid = threadIdx.x;
    int l = tid & 31, w = tid >> 5;
    int b = blockIdx.y >> 4, h = blockIdx.y & 15;
    int q0 = ((int)gridDim.x - 1 - (int)blockIdx.x) * 128;
    int nk = q0 / 64 + 2;

    const float* base = qkv + (size_t)b * SS * D3 + h * HSZ;

    int lr = tid >> 4, lc = tid & 15;
    unsigned lphys = (unsigned)(lc ^ (lr & 7));
    {
        #pragma unroll
        for (int p = 0; p < 8; p++) {
            int row = lr + p * 16;
            CPA16(uQ + (unsigned)(row * 256) + lphys * 16,
                  base + (size_t)(q0 + row) * D3 + lc * 4);
        }
    }
    auto issueK = [&](int k0) {
        #pragma unroll
        for (int p = 0; p < 4; p++) {
            int row = lr + p * 16;
            CPA16(uK + (unsigned)(row * 256) + lphys * 16,
                  base + (size_t)(k0 + row) * D3 + DD + lc * 4);
        }
        asm volatile("cp.async.commit_group;");
    };
    int vs = tid & 63, vdg = tid >> 6;
    float vreg[16];
    auto loadV = [&](int k0) {
        const float* vp = base + (size_t)(k0 + vs) * D3 + 2 * DD + vdg * 16;
        #pragma unroll
        for (int ii = 0; ii < 4; ii++)
            *(float4*)&vreg[ii * 4] = ((const float4*)vp)[ii];
    };
    issueK(0);
    loadV(0);

    float m2[2] = {-1e30f, -1e30f};
    float l2[2] = {0.0f, 0.0f};
    float oacc[8][4];
    #pragma unroll
    for (int i = 0; i < 8; i++)
        #pragma unroll
        for (int j = 0; j < 4; j++) oacc[i][j] = 0.0f;

    int l7 = l & 7;
    int selA = (l >> 4) & 1, selB = (l >> 3) & 1;
    int rA = w * 16 + (l & 7) + ((l >> 3) & 1) * 8;
    int rB = (l & 7) + ((l >> 4) & 1) * 8;
    int rloc = w * 16 + (l >> 2);

    for (int kt = 0; kt < nk; kt++) {
        int k0 = kt * 64;

        __syncthreads();
        #pragma unroll
        for (int ii = 0; ii < 4; ii++)
            #pragma unroll
            for (int j = 0; j < 4; j++) {
                int d = vdg * 16 + ii * 4 + j;
                int phys = (vs >> 2) ^ (d & 7);
                sm[12288 + d * 64 + phys * 4 + (vs & 3)] = vreg[ii * 4 + j];
            }
        asm volatile("cp.async.wait_group 0;" ::: "memory");
        __syncthreads();

        float sacc[8][4];
        #pragma unroll
        for (int i = 0; i < 8; i++)
            #pragma unroll
            for (int j = 0; j < 4; j++) sacc[i][j] = 0.0f;

        #pragma unroll
        for (int ks = 0; ks < 8; ks++) {
            int pA = (2 * ks + selA) ^ l7;
            int pB = (2 * ks + selB) ^ l7;
            unsigned a0, a1, a2, a3;
            ldsm_x4(a0, a1, a2, a3, uQ + (unsigned)(rA * 256 + pA * 16));
            unsigned bf[4][4];
            #pragma unroll
            for (int np = 0; np < 4; np++)
                ldsm_x4(bf[np][0], bf[np][1], bf[np][2], bf[np][3],
                        uK + (unsigned)((rB + np * 16) * 256 + pB * 16));
            #pragma unroll
            for (int nt = 0; nt < 8; nt++)
                mma_tf32(sacc[nt], a0, a1, a2, a3,
                         bf[nt >> 1][(nt & 1) * 2], bf[nt >> 1][(nt & 1) * 2 + 1]);
        }

        #pragma unroll
        for (int nt = 0; nt < 8; nt++)
            #pragma unroll
            for (int e = 0; e < 4; e++) sacc[nt][e] *= 0.125f;
        if (kt >= nk - 2) {
            #pragma unroll
            for (int nt = 0; nt < 8; nt++)
                #pragma unroll
                for (int e = 0; e < 4; e++) {
                    int r = q0 + rloc + ((e >> 1) << 3);
                    int c = k0 + nt * 8 + 2 * (l & 3) + (e & 1);
                    if (c > r) sacc[nt][e] = -1e30f;
                }
        }

        #pragma unroll
        for (int i = 0; i < 2; i++) {
            float tm = -1e30f;
            #pragma unroll
            for (int nt = 0; nt < 8; nt++)
                tm = fmaxf(tm, fmaxf(sacc[nt][2 * i], sacc[nt][2 * i + 1]));
            tm = fmaxf(tm, __shfl_xor_sync(0xffffffffu, tm, 1));
            tm = fmaxf(tm, __shfl_xor_sync(0xffffffffu, tm, 2));
            float mn = fmaxf(m2[i], tm);
            float alpha = __expf(m2[i] - mn);
            m2[i] = mn;
            float ls = 0.0f;
            #pragma unroll
            for (int nt = 0; nt < 8; nt++) {
                float p0 = __expf(sacc[nt][2 * i] - mn);
                float p1 = __expf(sacc[nt][2 * i + 1] - mn);
                sacc[nt][2 * i] = p0;
                sacc[nt][2 * i + 1] = p1;
                ls += p0 + p1;
            }
            ls += __shfl_xor_sync(0xffffffffu, ls, 1);
            ls += __shfl_xor_sync(0xffffffffu, ls, 2);
            l2[i] = l2[i] * alpha + ls;
            #pragma unroll
            for (int nt = 0; nt < 8; nt++) {
                oacc[nt][2 * i] *= alpha;
                oacc[nt][2 * i + 1] *= alpha;
            }
        }

        {
            int colb = 2 * (l & 3);
            #pragma unroll
            for (int nt = 0; nt < 8; nt++) {
                int phys = (2 * nt + ((l & 3) >> 1)) ^ ((l >> 2) & 7);
                float2 v0 = make_float2(f2tf32(sacc[nt][0]), f2tf32(sacc[nt][1]));
                float2 v1 = make_float2(f2tf32(sacc[nt][2]), f2tf32(sacc[nt][3]));
                *(float2*)&sm[16384 + rloc * 64 + phys * 4 + (colb & 3)] = v0;
                *(float2*)&sm[16384 + (rloc + 8) * 64 + phys * 4 + (colb & 3)] = v1;
            }
        }
        __syncthreads();

        if (kt + 1 < nk) {
            issueK(k0 + 64);
            loadV(k0 + 64);
        }

        #pragma unroll
        for (int ks = 0; ks < 8; ks++) {
            int pA = (2 * ks + selA) ^ l7;
            int pB = (2 * ks + selB) ^ l7;
            unsigned a0, a1, a2, a3;
            ldsm_x4(a0, a1, a2, a3, uP + (unsigned)(rA * 256 + pA * 16));
            unsigned bf[4][4];
            #pragma unroll
            for (int np = 0; np < 4; np++)
                ldsm_x4(bf[np][0], bf[np][1], bf[np][2], bf[np][3],
                        uV + (unsigned)((rB + np * 16) * 256 + pB * 16));
            #pragma unroll
            for (int nt = 0; nt < 8; nt++)
                mma_tf32(oacc[nt], a0, a1, a2, a3,
                         bf[nt >> 1][(nt & 1) * 2], bf[nt >> 1][(nt & 1) * 2 + 1]);
        }
    }

    float inv0 = 1.0f / l2[0];
    float inv1 = 1.0f / l2[1];
    int r = q0 + rloc;
    int dcol = h * HSZ + 2 * (l & 3);
    #pragma unroll
    for (int nt = 0; nt < 8; nt++) {
        float2 v0 = make_float2(f2tf32(oacc[nt][0] * inv0), f2tf32(oacc[nt][1] * inv0));
        float2 v1 = make_float2(f2tf32(oacc[nt][2] * inv1), f2tf32(oacc[nt][3] * inv1));
        *(float2*)&out[(size_t)(b * SS + r) * DD + dcol + nt * 8] = v0;
        *(float2*)&out[(size_t)(b * SS + r + 8) * DD + dcol + nt * 8] = v1;
    }
}

// ---------------- launch ----------------
extern "C" void kernel_launch(void* const* d_in, const int* in_sizes, int n_in,
                              void* d_out, int out_size) {
    const float* x     = (const float*)d_in[0];
    const float* wq    = (const float*)d_in[1];
    const float* wk    = (const float*)d_in[2];
    const float* wv    = (const float*)d_in[3];
    const float* wproj = (const float*)d_in[4];
    const float* bproj = (const float*)d_in[5];
    const float* w1    = (const float*)d_in[6];
    const float* b1    = (const float*)d_in[7];
    const float* w2    = (const float*)d_in[8];
    const float* b2    = (const float*)d_in[9];
    const float* ln1_g = (const float*)d_in[10];
    const float* ln1_b = (const float*)d_in[11];
    const float* ln2_g = (const float*)d_in[12];
    const float* ln2_b = (const float*)d_in[13];
    float* out = (float*)d_out;

    float *p_xn, *p_qkv, *p_attn, *p_h, *p_hn, *p_ff;
    float *p_wqkvT, *p_wprojT, *p_w1T, *p_w2T;
    cudaGetSymbolAddress((void**)&p_xn, g_xn);
    cudaGetSymbolAddress((void**)&p_qkv, g_qkv);
    cudaGetSymbolAddress((void**)&p_attn, g_attn);
    cudaGetSymbolAddress((void**)&p_h, g_h);
    cudaGetSymbolAddress((void**)&p_hn, g_hn);
    cudaGetSymbolAddress((void**)&p_ff, g_ff);
    cudaGetSymbolAddress((void**)&p_wqkvT, g_wqkvT);
    cudaGetSymbolAddress((void**)&p_wprojT, g_wprojT);
    cudaGetSymbolAddress((void**)&p_w1T, g_w1T);
    cudaGetSymbolAddress((void**)&p_w2T, g_w2T);

    cudaFuncSetAttribute(gemm_tc<0>, cudaFuncAttributeMaxDynamicSharedMemorySize, GEMM_SMEM);
    cudaFuncSetAttribute(gemm_tc<1>, cudaFuncAttributeMaxDynamicSharedMemorySize, GEMM_SMEM);
    cudaFuncSetAttribute(gemm_tc<2>, cudaFuncAttributeMaxDynamicSharedMemorySize, GEMM_SMEM);
    cudaFuncSetAttribute(attn_tc, cudaFuncAttributeMaxDynamicSharedMemorySize, ATT_SMEM);

    // prep: LN1 + weight transposes (tf32-rounded)
    ln_kernel<<<BS, 256>>>(x, ln1_g, ln1_b, p_xn);
    build_wqkvT_kernel<<<dim3(16, 16, 3), 256>>>(wq, wk, wv, p_wqkvT);
    transpose_kernel<<<dim3(DD / 32, DD / 32), dim3(32, 8)>>>(wproj, p_wprojT, DD, DD);
    transpose_kernel<<<dim3(DFF / 32, DD / 32), dim3(32, 8)>>>(w1, p_w1T, DD, DFF);
    transpose_kernel<<<dim3(DD / 32, DFF / 32), dim3(32, 8)>>>(w2, p_w2T, DFF, DD);

    // QKV GEMM (epilogue tf32-rounds q/k/v for the tf32 attention)
    gemm_tc<2><<<dim3(D3 / 128, BS / 256), 512, GEMM_SMEM>>>(
        p_xn, p_wqkvT, nullptr, nullptr, p_qkv, BS, D3, DD);

    // tensor-core flash attention
    attn_tc<<<dim3(SS / 128, BB * HH), 256, ATT_SMEM>>>(p_qkv, p_attn);

    // proj + bias + residual(x)
    gemm_tc<0><<<dim3(DD / 128, BS / 256), 512, GEMM_SMEM>>>(
        p_attn, p_wprojT, bproj, x, p_h, BS, DD, DD);

    // LN2
    ln_kernel<<<BS, 256>>>(p_h, ln2_g, ln2_b, p_hn);

    // FF1 + bias + relu (+tf32 round)
    gemm_tc<1><<<dim3(DFF / 128, BS / 256), 512, GEMM_SMEM>>>(
        p_hn, p_w1T, b1, nullptr, p_ff, BS, DFF, DD);

    // FF2 + bias + residual(h) -> out
    gemm_tc<0><<<dim3(DD / 128, BS / 256), 512, GEMM_SMEM>>>(
        p_ff, p_w2T, b2, p_h, out, BS, DD, DFF);
}

// round 5
// speedup vs baseline: 1.0707x; 1.0707x over previous
#include <cuda_runtime.h>
#include <cuda_bf16.h>

// Problem constants
#define BB 2
#define SS 2048
#define DD 1024
#define HH 16
#define HSZ 64
#define BS (BB * SS)        // 4096 rows
#define D3 (3 * DD)         // 3072
#define DFF (4 * DD)        // 4096

// ---------------- scratch (static device memory; no allocations) ----------------
__device__ float g_xn[BS * DD];
__device__ float g_qkv[BS * D3];
__device__ float g_attn[BS * DD];
__device__ float g_h[BS * DD];
__device__ float g_hn[BS * DD];
__device__ float g_ff[BS * DFF];
__device__ float g_wqkvT[D3 * DD];
__device__ float g_wprojT[DD * DD];
__device__ float g_w1T[DFF * DD];
__device__ float g_w2T[DD * DFF];

// round-to-nearest tf32 (bit pattern is a valid fp32)
__device__ __forceinline__ float f2tf32(float x) {
    unsigned u;
    asm("cvt.rna.tf32.f32 %0, %1;" : "=r"(u) : "f"(x));
    return __uint_as_float(u);
}

// ---------------- LayerNorm (outputs tf32-rounded) ----------------
__global__ void ln_kernel(const float* __restrict__ in, const float* __restrict__ gamma,
                          const float* __restrict__ beta, float* __restrict__ out) {
    int row = blockIdx.x;
    int tid = threadIdx.x;
    float4 xv = ((const float4*)(in + (size_t)row * DD))[tid];

    __shared__ float red[256];
    red[tid] = xv.x + xv.y + xv.z + xv.w;
    __syncthreads();
    #pragma unroll
    for (int off = 128; off > 0; off >>= 1) {
        if (tid < off) red[tid] += red[tid + off];
        __syncthreads();
    }
    float mu = red[0] * (1.0f / DD);
    __syncthreads();

    float dx = xv.x - mu, dy = xv.y - mu, dz = xv.z - mu, dw = xv.w - mu;
    red[tid] = dx * dx + dy * dy + dz * dz + dw * dw;
    __syncthreads();
    #pragma unroll
    for (int off = 128; off > 0; off >>= 1) {
        if (tid < off) red[tid] += red[tid + off];
        __syncthreads();
    }
    float rstd = rsqrtf(red[0] * (1.0f / DD) + 1e-5f);

    float4 gv = ((const float4*)gamma)[tid];
    float4 bv = ((const float4*)beta)[tid];
    float4 ov;
    ov.x = f2tf32(dx * rstd * gv.x + bv.x);
    ov.y = f2tf32(dy * rstd * gv.y + bv.y);
    ov.z = f2tf32(dz * rstd * gv.z + bv.z);
    ov.w = f2tf32(dw * rstd * gv.w + bv.w);
    ((float4*)(out + (size_t)row * DD))[tid] = ov;
}

// ---------------- build wqkvT [3072][1024] (tf32-rounded) ----------------------
__global__ void build_wqkvT_kernel(const float* __restrict__ wq, const float* __restrict__ wk,
                                   const float* __restrict__ wv, float* __restrict__ out) {
    __shared__ float sm[64][65];
    int dblk = blockIdx.x;
    int h = blockIdx.y;
    int part = blockIdx.z;
    const float* w = (part == 0) ? wq : (part == 1) ? wk : wv;
    int tid = threadIdx.x;
    int d0 = dblk * 64;

    int kk = tid & 63;
    int g4 = tid >> 6;
    #pragma unroll
    for (int i = 0; i < 16; i++) {
        int dl = g4 + i * 4;
        sm[dl][kk] = w[((size_t)(h * DD + d0 + dl)) * HSZ + kk];
    }
    __syncthreads();
    int dc = tid & 63;
    #pragma unroll
    for (int i = 0; i < 16; i++) {
        int kk2 = g4 + i * 4;
        out[(size_t)(part * DD + h * HSZ + kk2) * DD + d0 + dc] = f2tf32(sm[dc][kk2]);
    }
}

// ---------------- generic transpose: in[R][C] -> out[C][R] (tf32-rounded) ------
__global__ void transpose_kernel(const float* __restrict__ in, float* __restrict__ out,
                                 int R, int C) {
    __shared__ float t[32][33];
    int x = blockIdx.x * 32 + threadIdx.x;
    int y = blockIdx.y * 32 + threadIdx.y;
    #pragma unroll
    for (int i = 0; i < 32; i += 8)
        t[threadIdx.y + i][threadIdx.x] = in[(size_t)(y + i) * C + x];
    __syncthreads();
    x = blockIdx.y * 32 + threadIdx.x;
    y = blockIdx.x * 32 + threadIdx.y;
    #pragma unroll
    for (int i = 0; i < 32; i += 8)
        out[(size_t)(y + i) * R + x] = f2tf32(t[threadIdx.x][threadIdx.y + i]);
}

// ---------------- tf32 tensor-core GEMM helpers -------------------------------
__device__ __forceinline__ void ldsm_x4(unsigned& r0, unsigned& r1, unsigned& r2, unsigned& r3,
                                        unsigned addr) {
    asm volatile("ldmatrix.sync.aligned.m8n8.x4.shared.b16 {%0,%1,%2,%3}, [%4];"
                 : "=r"(r0), "=r"(r1), "=r"(r2), "=r"(r3) : "r"(addr));
}

__device__ __forceinline__ void mma_tf32(float c[4], unsigned a0, unsigned a1, unsigned a2,
                                         unsigned a3, unsigned b0, unsigned b1) {
    asm volatile(
        "mma.sync.aligned.m16n8k8.row.col.f32.tf32.tf32.f32 "
        "{%0,%1,%2,%3}, {%4,%5,%6,%7}, {%8,%9}, {%0,%1,%2,%3};"
        : "+f"(c[0]), "+f"(c[1]), "+f"(c[2]), "+f"(c[3])
        : "r"(a0), "r"(a1), "r"(a2), "r"(a3), "r"(b0), "r"(b1));
}

#define CPA16(dst, src) \
    asm volatile("cp.async.cg.shared.global [%0], [%1], 16;" :: "r"(dst), "l"(src))

// ---------------- tf32 GEMM: 128x128 tile, BK=32, 256 thr, 3-stage pipeline ----
// stage stride = 32768 B (A 16KB + B 16KB). warp tile 64x32 (2m x 4n warps).
#define GEMM_SMEM (3 * 32768)

// MODE: 0 = plain, 1 = relu + tf32-round, 2 = tf32-round
template <int MODE>
__global__ __launch_bounds__(256, 2)
void gemm_tc(const float* __restrict__ A, const float* __restrict__ Bt,
             const float* __restrict__ bias, const float* __restrict__ res,
             float* __restrict__ C, int M, int N, int K) {
    extern __shared__ unsigned smem_u[];
    unsigned sbase = (unsigned)__cvta_generic_to_shared(smem_u);

    int tid = threadIdx.x;
    int l = tid & 31;
    int wid = tid >> 5;
    int warp_m = wid >> 2;   // 0..1
    int warp_n = wid & 3;    // 0..3
    int bx = blockIdx.x * 128;
    int by = blockIdx.y * 128;

    float acc[4][4][4];
    #pragma unroll
    for (int i = 0; i < 4; i++)
        #pragma unroll
        for (int j = 0; j < 4; j++)
            #pragma unroll
            for (int k = 0; k < 4; k++) acc[i][j][k] = 0.0f;

    int lm = tid >> 3;
    int kc = tid & 7;
    unsigned physw = (unsigned)((kc ^ (lm & 7)) * 4);
    const float* aptr = A + (size_t)(by + lm) * K + kc * 4;
    const float* bptr = Bt + (size_t)(bx + lm) * K + kc * 4;

    int NT = K / 32;

    int rA = warp_m * 64 + (l & 7) + ((l >> 3) & 1) * 8;
    int rB = warp_n * 32 + (l & 7) + ((l >> 4) & 1) * 8;
    int selA = (l >> 4) & 1;
    int selB = (l >> 3) & 1;
    int l7 = l & 7;

    auto issue = [&](int kt) {
        unsigned sA = sbase + (unsigned)(kt % 3) * 32768u;
        unsigned sB = sA + 16384u;
        const float* ap = aptr + kt * 32;
        const float* bp = bptr + kt * 32;
        #pragma unroll
        for (int i = 0; i < 4; i++) {
            unsigned off = ((lm + 32 * i) * 32 + physw) * 4;
            CPA16(sA + off, ap + (size_t)(32 * i) * K);
            CPA16(sB + off, bp + (size_t)(32 * i) * K);
        }
        asm volatile("cp.async.commit_group;");
    };

    issue(0);
    issue(1);

    for (int kt = 0; kt < NT; kt++) {
        if (kt < NT - 1) {
            asm volatile("cp.async.wait_group 1;" ::: "memory");
        } else {
            asm volatile("cp.async.wait_group 0;" ::: "memory");
        }
        __syncthreads();   // stage kt visible; reads of stage (kt-1) done by all

        if (kt + 2 < NT) issue(kt + 2);   // writes buffer (kt+2)%3 == (kt-1)%3, now free

        unsigned sA = sbase + (unsigned)(kt % 3) * 32768u;
        unsigned sB = sA + 16384u;

        #pragma unroll
        for (int ks = 0; ks < 4; ks++) {
            int physA = (2 * ks + selA) ^ l7;
            int physB = (2 * ks + selB) ^ l7;
            unsigned aBase = sA + (unsigned)(rA * 32 + physA * 4) * 4;
            unsigned bBase = sB + (unsigned)(rB * 32 + physB * 4) * 4;

            unsigned a[4][4], bf[2][4];
            #pragma unroll
            for (int mt = 0; mt < 4; mt++)
                ldsm_x4(a[mt][0], a[mt][1], a[mt][2], a[mt][3], aBase + mt * 2048u);
            #pragma unroll
            for (int np = 0; np < 2; np++)
                ldsm_x4(bf[np][0], bf[np][1], bf[np][2], bf[np][3], bBase + np * 2048u);

            #pragma unroll
            for (int mt = 0; mt < 4; mt++)
                #pragma unroll
                for (int nt = 0; nt < 4; nt++)
                    mma_tf32(acc[mt][nt], a[mt][0], a[mt][1], a[mt][2], a[mt][3],
                             bf[nt >> 1][(nt & 1) * 2], bf[nt >> 1][(nt & 1) * 2 + 1]);
        }
        __syncthreads();
    }

    int g = l >> 2, tg = l & 3;
    #pragma unroll
    for (int mt = 0; mt < 4; mt++) {
        int r0 = by + warp_m * 64 + mt * 16 + g;
        #pragma unroll
        for (int nt = 0; nt < 4; nt++) {
            int col = bx + warp_n * 32 + nt * 8 + tg * 2;
            float2 v0 = make_float2(acc[mt][nt][0], acc[mt][nt][1]);
            float2 v1 = make_float2(acc[mt][nt][2], acc[mt][nt][3]);
            if (bias != nullptr) {
                float2 bv = *(const float2*)&bias[col];
                v0.x += bv.x; v0.y += bv.y; v1.x += bv.x; v1.y += bv.y;
            }
            if (res != nullptr) {
                float2 q0 = *(const float2*)&res[(size_t)r0 * N + col];
                float2 q1 = *(const float2*)&res[(size_t)(r0 + 8) * N + col];
                v0.x += q0.x; v0.y += q0.y; v1.x += q1.x; v1.y += q1.y;
            }
            if (MODE == 1) {
                v0.x = f2tf32(fmaxf(v0.x, 0.0f)); v0.y = f2tf32(fmaxf(v0.y, 0.0f));
                v1.x = f2tf32(fmaxf(v1.x, 0.0f)); v1.y = f2tf32(fmaxf(v1.y, 0.0f));
            } else if (MODE == 2) {
                v0.x = f2tf32(v0.x); v0.y = f2tf32(v0.y);
                v1.x = f2tf32(v1.x); v1.y = f2tf32(v1.y);
            }
            *(float2*)&C[(size_t)r0 * N + col] = v0;
            *(float2*)&C[(size_t)(r0 + 8) * N + col] = v1;
        }
    }
}

// ---------------- tf32 tensor-core flash attention ----------------------------
// 128-query tile per CTA, 8 warps x 16 rows; 64-key tiles.
// smem (floats): Q[128][64] @0, K[64][64] @8192, VT[64][64] @12288, P[128][64] @16384
#define ATT_SMEM (24576 * 4)

__global__ __launch_bounds__(256, 2)
void attn_tc(const float* __restrict__ qkv, float* __restrict__ out) {
    extern __shared__ float sm[];
    unsigned ub = (unsigned)__cvta_generic_to_shared(sm);
    unsigned uQ = ub, uK = ub + 8192u * 4, uV = ub + 12288u * 4, uP = ub + 16384u * 4;

    int tid = threadIdx.x;
    int l = tid & 31, w = tid >> 5;
    int b = blockIdx.y >> 4, h = blockIdx.y & 15;
    int q0 = ((int)gridDim.x - 1 - (int)blockIdx.x) * 128;
    int nk = q0 / 64 + 2;

    const float* base = qkv + (size_t)b * SS * D3 + h * HSZ;

    int lr = tid >> 4, lc = tid & 15;
    unsigned lphys = (unsigned)(lc ^ (lr & 7));
    {
        #pragma unroll
        for (int p = 0; p < 8; p++) {
            int row = lr + p * 16;
            CPA16(uQ + (unsigned)(row * 256) + lphys * 16,
                  base + (size_t)(q0 + row) * D3 + lc * 4);
        }
    }
    auto issueK = [&](int k0) {
        #pragma unroll
        for (int p = 0; p < 4; p++) {
            int row = lr + p * 16;
            CPA16(uK + (unsigned)(row * 256) + lphys * 16,
                  base + (size_t)(k0 + row) * D3 + DD + lc * 4);
        }
        asm volatile("cp.async.commit_group;");
    };
    int vs = tid & 63, vdg = tid >> 6;
    float vreg[16];
    auto loadV = [&](int k0) {
        const float* vp = base + (size_t)(k0 + vs) * D3 + 2 * DD + vdg * 16;
        #pragma unroll
        for (int ii = 0; ii < 4; ii++)
            *(float4*)&vreg[ii * 4] = ((const float4*)vp)[ii];
    };
    issueK(0);
    loadV(0);

    float m2[2] = {-1e30f, -1e30f};
    float l2[2] = {0.0f, 0.0f};
    float oacc[8][4];
    #pragma unroll
    for (int i = 0; i < 8; i++)
        #pragma unroll
        for (int j = 0; j < 4; j++) oacc[i][j] = 0.0f;

    int l7 = l & 7;
    int selA = (l >> 4) & 1, selB = (l >> 3) & 1;
    int rA = w * 16 + (l & 7) + ((l >> 3) & 1) * 8;
    int rB = (l & 7) + ((l >> 4) & 1) * 8;
    int rloc = w * 16 + (l >> 2);

    for (int kt = 0; kt < nk; kt++) {
        int k0 = kt * 64;

        __syncthreads();
        #pragma unroll
        for (int ii = 0; ii < 4; ii++)
            #pragma unroll
            for (int j = 0; j < 4; j++) {
                int d = vdg * 16 + ii * 4 + j;
                int phys = (vs >> 2) ^ (d & 7);
                sm[12288 + d * 64 + phys * 4 + (vs & 3)] = vreg[ii * 4 + j];
            }
        asm volatile("cp.async.wait_group 0;" ::: "memory");
        __syncthreads();

        float sacc[8][4];
        #pragma unroll
        for (int i = 0; i < 8; i++)
            #pragma unroll
            for (int j = 0; j < 4; j++) sacc[i][j] = 0.0f;

        #pragma unroll
        for (int ks = 0; ks < 8; ks++) {
            int pA = (2 * ks + selA) ^ l7;
            int pB = (2 * ks + selB) ^ l7;
            unsigned a0, a1, a2, a3;
            ldsm_x4(a0, a1, a2, a3, uQ + (unsigned)(rA * 256 + pA * 16));
            unsigned bf[4][4];
            #pragma unroll
            for (int np = 0; np < 4; np++)
                ldsm_x4(bf[np][0], bf[np][1], bf[np][2], bf[np][3],
                        uK + (unsigned)((rB + np * 16) * 256 + pB * 16));
            #pragma unroll
            for (int nt = 0; nt < 8; nt++)
                mma_tf32(sacc[nt], a0, a1, a2, a3,
                         bf[nt >> 1][(nt & 1) * 2], bf[nt >> 1][(nt & 1) * 2 + 1]);
        }

        #pragma unroll
        for (int nt = 0; nt < 8; nt++)
            #pragma unroll
            for (int e = 0; e < 4; e++) sacc[nt][e] *= 0.125f;
        if (kt >= nk - 2) {
            #pragma unroll
            for (int nt = 0; nt < 8; nt++)
                #pragma unroll
                for (int e = 0; e < 4; e++) {
                    int r = q0 + rloc + ((e >> 1) << 3);
                    int c = k0 + nt * 8 + 2 * (l & 3) + (e & 1);
                    if (c > r) sacc[nt][e] = -1e30f;
                }
        }

        #pragma unroll
        for (int i = 0; i < 2; i++) {
            float tm = -1e30f;
            #pragma unroll
            for (int nt = 0; nt < 8; nt++)
                tm = fmaxf(tm, fmaxf(sacc[nt][2 * i], sacc[nt][2 * i + 1]));
            tm = fmaxf(tm, __shfl_xor_sync(0xffffffffu, tm, 1));
            tm = fmaxf(tm, __shfl_xor_sync(0xffffffffu, tm, 2));
            float mn = fmaxf(m2[i], tm);
            float alpha = __expf(m2[i] - mn);
            m2[i] = mn;
            float ls = 0.0f;
            #pragma unroll
            for (int nt = 0; nt < 8; nt++) {
                float p0 = __expf(sacc[nt][2 * i] - mn);
                float p1 = __expf(sacc[nt][2 * i + 1] - mn);
                sacc[nt][2 * i] = p0;
                sacc[nt][2 * i + 1] = p1;
                ls += p0 + p1;
            }
            ls += __shfl_xor_sync(0xffffffffu, ls, 1);
            ls += __shfl_xor_sync(0xffffffffu, ls, 2);
            l2[i] = l2[i] * alpha + ls;
            #pragma unroll
            for (int nt = 0; nt < 8; nt++) {
                oacc[nt][2 * i] *= alpha;
                oacc[nt][2 * i + 1] *= alpha;
            }
        }

        {
            int colb = 2 * (l & 3);
            #pragma unroll
            for (int nt = 0; nt < 8; nt++) {
                int phys = (2 * nt + ((l & 3) >> 1)) ^ ((l >> 2) & 7);
                float2 v0 = make_float2(f2tf32(sacc[nt][0]), f2tf32(sacc[nt][1]));
                float2 v1 = make_float2(f2tf32(sacc[nt][2]), f2tf32(sacc[nt][3]));
                *(float2*)&sm[16384 + rloc * 64 + phys * 4 + (colb & 3)] = v0;
                *(float2*)&sm[16384 + (rloc + 8) * 64 + phys * 4 + (colb & 3)] = v1;
            }
        }
        __syncthreads();

        if (kt + 1 < nk) {
            issueK(k0 + 64);
            loadV(k0 + 64);
        }

        #pragma unroll
        for (int ks = 0; ks < 8; ks++) {
            int pA = (2 * ks + selA) ^ l7;
            int pB = (2 * ks + selB) ^ l7;
            unsigned a0, a1, a2, a3;
            ldsm_x4(a0, a1, a2, a3, uP + (unsigned)(rA * 256 + pA * 16));
            unsigned bf[4][4];
            #pragma unroll
            for (int np = 0; np < 4; np++)
                ldsm_x4(bf[np][0], bf[np][1], bf[np][2], bf[np][3],
                        uV + (unsigned)((rB + np * 16) * 256 + pB * 16));
            #pragma unroll
            for (int nt = 0; nt < 8; nt++)
                mma_tf32(oacc[nt], a0, a1, a2, a3,
                         bf[nt >> 1][(nt & 1) * 2], bf[nt >> 1][(nt & 1) * 2 + 1]);
        }
    }

    float inv0 = 1.0f / l2[0];
    float inv1 = 1.0f / l2[1];
    int r = q0 + rloc;
    int dcol = h * HSZ + 2 * (l & 3);
    #pragma unroll
    for (int nt = 0; nt < 8; nt++) {
        float2 v0 = make_float2(f2tf32(oacc[nt][0] * inv0), f2tf32(oacc[nt][1] * inv0));
        float2 v1 = make_float2(f2tf32(oacc[nt][2] * inv1), f2tf32(oacc[nt][3] * inv1));
        *(float2*)&out[(size_t)(b * SS + r) * DD + dcol + nt * 8] = v0;
        *(float2*)&out[(size_t)(b * SS + r + 8) * DD + dcol + nt * 8] = v1;
    }
}

// ---------------- launch ----------------
extern "C" void kernel_launch(void* const* d_in, const int* in_sizes, int n_in,
                              void* d_out, int out_size) {
    const float* x     = (const float*)d_in[0];
    const float* wq    = (const float*)d_in[1];
    const float* wk    = (const float*)d_in[2];
    const float* wv    = (const float*)d_in[3];
    const float* wproj = (const float*)d_in[4];
    const float* bproj = (const float*)d_in[5];
    const float* w1    = (const float*)d_in[6];
    const float* b1    = (const float*)d_in[7];
    const float* w2    = (const float*)d_in[8];
    const float* b2    = (const float*)d_in[9];
    const float* ln1_g = (const float*)d_in[10];
    const float* ln1_b = (const float*)d_in[11];
    const float* ln2_g = (const float*)d_in[12];
    const float* ln2_b = (const float*)d_in[13];
    float* out = (float*)d_out;

    float *p_xn, *p_qkv, *p_attn, *p_h, *p_hn, *p_ff;
    float *p_wqkvT, *p_wprojT, *p_w1T, *p_w2T;
    cudaGetSymbolAddress((void**)&p_xn, g_xn);
    cudaGetSymbolAddress((void**)&p_qkv, g_qkv);
    cudaGetSymbolAddress((void**)&p_attn, g_attn);
    cudaGetSymbolAddress((void**)&p_h, g_h);
    cudaGetSymbolAddress((void**)&p_hn, g_hn);
    cudaGetSymbolAddress((void**)&p_ff, g_ff);
    cudaGetSymbolAddress((void**)&p_wqkvT, g_wqkvT);
    cudaGetSymbolAddress((void**)&p_wprojT, g_wprojT);
    cudaGetSymbolAddress((void**)&p_w1T, g_w1T);
    cudaGetSymbolAddress((void**)&p_w2T, g_w2T);

    cudaFuncSetAttribute(gemm_tc<0>, cudaFuncAttributeMaxDynamicSharedMemorySize, GEMM_SMEM);
    cudaFuncSetAttribute(gemm_tc<1>, cudaFuncAttributeMaxDynamicSharedMemorySize, GEMM_SMEM);
    cudaFuncSetAttribute(gemm_tc<2>, cudaFuncAttributeMaxDynamicSharedMemorySize, GEMM_SMEM);
    cudaFuncSetAttribute(attn_tc, cudaFuncAttributeMaxDynamicSharedMemorySize, ATT_SMEM);

    // prep (transposes first so profiled launch slot #5 = QKV gemm_tc)
    build_wqkvT_kernel<<<dim3(16, 16, 3), 256>>>(wq, wk, wv, p_wqkvT);          // 0
    transpose_kernel<<<dim3(DD / 32, DD / 32), dim3(32, 8)>>>(wproj, p_wprojT, DD, DD);   // 1
    transpose_kernel<<<dim3(DFF / 32, DD / 32), dim3(32, 8)>>>(w1, p_w1T, DD, DFF);       // 2
    transpose_kernel<<<dim3(DD / 32, DFF / 32), dim3(32, 8)>>>(w2, p_w2T, DFF, DD);       // 3
    ln_kernel<<<BS, 256>>>(x, ln1_g, ln1_b, p_xn);                              // 4

    // QKV GEMM (epilogue tf32-rounds q/k/v for the tf32 attention)            // 5 (profiled)
    gemm_tc<2><<<dim3(D3 / 128, BS / 128), 256, GEMM_SMEM>>>(
        p_xn, p_wqkvT, nullptr, nullptr, p_qkv, BS, D3, DD);

    // tensor-core flash attention
    attn_tc<<<dim3(SS / 128, BB * HH), 256, ATT_SMEM>>>(p_qkv, p_attn);

    // proj + bias + residual(x)
    gemm_tc<0><<<dim3(DD / 128, BS / 128), 256, GEMM_SMEM>>>(
        p_attn, p_wprojT, bproj, x, p_h, BS, DD, DD);

    // LN2
    ln_kernel<<<BS, 256>>>(p_h, ln2_g, ln2_b, p_hn);

    // FF1 + bias + relu (+tf32 round)
    gemm_tc<1><<<dim3(DFF / 128, BS / 128), 256, GEMM_SMEM>>>(
        p_hn, p_w1T, b1, nullptr, p_ff, BS, DFF, DD);

    // FF2 + bias + residual(h) -> out
    gemm_tc<0><<<dim3(DD / 128, BS / 128), 256, GEMM_SMEM>>>(
        p_ff, p_w2T, b2, p_h, out, BS, DD, DFF);
}

// round 7
// speedup vs baseline: 1.4515x; 1.3557x over previous
#include <cuda_runtime.h>
#include <cuda_fp16.h>

// Problem constants
#define BB 2
#define SS 2048
#define DD 1024
#define HH 16
#define HSZ 64
#define BS (BB * SS)        // 4096 rows
#define D3 (3 * DD)         // 3072
#define DFF (4 * DD)        // 4096

// ---------------- scratch (static device memory; no allocations) ----------------
__device__ __half g_xn[BS * DD];
__device__ float  g_qkv[BS * D3];
__device__ __half g_attn[BS * DD];
__device__ float  g_h[BS * DD];
__device__ __half g_hn[BS * DD];
__device__ __half g_ff[BS * DFF];
__device__ __half g_wqkvT[D3 * DD];
__device__ __half g_wprojT[DD * DD];
__device__ __half g_w1T[DFF * DD];
__device__ __half g_w2T[DD * DFF];

// round-to-nearest tf32 (bit pattern is a valid fp32)
__device__ __forceinline__ float f2tf32(float x) {
    unsigned u;
    asm("cvt.rna.tf32.f32 %0, %1;" : "=r"(u) : "f"(x));
    return __uint_as_float(u);
}

// ---------------- LayerNorm (fp32 in -> fp16 out) ----------------
__global__ void ln_kernel(const float* __restrict__ in, const float* __restrict__ gamma,
                          const float* __restrict__ beta, __half* __restrict__ out) {
    int row = blockIdx.x;
    int tid = threadIdx.x;
    float4 xv = ((const float4*)(in + (size_t)row * DD))[tid];

    __shared__ float red[256];
    red[tid] = xv.x + xv.y + xv.z + xv.w;
    __syncthreads();
    #pragma unroll
    for (int off = 128; off > 0; off >>= 1) {
        if (tid < off) red[tid] += red[tid + off];
        __syncthreads();
    }
    float mu = red[0] * (1.0f / DD);
    __syncthreads();

    float dx = xv.x - mu, dy = xv.y - mu, dz = xv.z - mu, dw = xv.w - mu;
    red[tid] = dx * dx + dy * dy + dz * dz + dw * dw;
    __syncthreads();
    #pragma unroll
    for (int off = 128; off > 0; off >>= 1) {
        if (tid < off) red[tid] += red[tid + off];
        __syncthreads();
    }
    float rstd = rsqrtf(red[0] * (1.0f / DD) + 1e-5f);

    float4 gv = ((const float4*)gamma)[tid];
    float4 bv = ((const float4*)beta)[tid];
    __half2 h0 = __floats2half2_rn(dx * rstd * gv.x + bv.x, dy * rstd * gv.y + bv.y);
    __half2 h1 = __floats2half2_rn(dz * rstd * gv.z + bv.z, dw * rstd * gv.w + bv.w);
    ((__half2*)(out + (size_t)row * DD))[tid * 2] = h0;
    ((__half2*)(out + (size_t)row * DD))[tid * 2 + 1] = h1;
}

// ---------------- build wqkvT [3072][1024] (fp16) ----------------
__global__ void build_wqkvT_kernel(const float* __restrict__ wq, const float* __restrict__ wk,
                                   const float* __restrict__ wv, __half* __restrict__ out) {
    __shared__ float sm[64][65];
    int dblk = blockIdx.x;
    int h = blockIdx.y;
    int part = blockIdx.z;
    const float* w = (part == 0) ? wq : (part == 1) ? wk : wv;
    int tid = threadIdx.x;
    int d0 = dblk * 64;

    int kk = tid & 63;
    int g4 = tid >> 6;
    #pragma unroll
    for (int i = 0; i < 16; i++) {
        int dl = g4 + i * 4;
        sm[dl][kk] = w[((size_t)(h * DD + d0 + dl)) * HSZ + kk];
    }
    __syncthreads();
    int dc = tid & 63;
    #pragma unroll
    for (int i = 0; i < 16; i++) {
        int kk2 = g4 + i * 4;
        out[(size_t)(part * DD + h * HSZ + kk2) * DD + d0 + dc] = __float2half_rn(sm[dc][kk2]);
    }
}

// ---------------- generic transpose: in[R][C] -> out[C][R] (fp16) ------
__global__ void transpose_kernel(const float* __restrict__ in, __half* __restrict__ out,
                                 int R, int C) {
    __shared__ float t[32][33];
    int x = blockIdx.x * 32 + threadIdx.x;
    int y = blockIdx.y * 32 + threadIdx.y;
    #pragma unroll
    for (int i = 0; i < 32; i += 8)
        t[threadIdx.y + i][threadIdx.x] = in[(size_t)(y + i) * C + x];
    __syncthreads();
    x = blockIdx.y * 32 + threadIdx.x;
    y = blockIdx.x * 32 + threadIdx.y;
    #pragma unroll
    for (int i = 0; i < 32; i += 8)
        out[(size_t)(y + i) * R + x] = __float2half_rn(t[threadIdx.x][threadIdx.y + i]);
}

// ---------------- tensor-core helpers -------------------------------
__device__ __forceinline__ void ldsm_x4(unsigned& r0, unsigned& r1, unsigned& r2, unsigned& r3,
                                        unsigned addr) {
    asm volatile("ldmatrix.sync.aligned.m8n8.x4.shared.b16 {%0,%1,%2,%3}, [%4];"
                 : "=r"(r0), "=r"(r1), "=r"(r2), "=r"(r3) : "r"(addr));
}

__device__ __forceinline__ void mma_f16(float c[4], unsigned a0, unsigned a1, unsigned a2,
                                        unsigned a3, unsigned b0, unsigned b1) {
    asm volatile(
        "mma.sync.aligned.m16n8k16.row.col.f32.f16.f16.f32 "
        "{%0,%1,%2,%3}, {%4,%5,%6,%7}, {%8,%9}, {%0,%1,%2,%3};"
        : "+f"(c[0]), "+f"(c[1]), "+f"(c[2]), "+f"(c[3])
        : "r"(a0), "r"(a1), "r"(a2), "r"(a3), "r"(b0), "r"(b1));
}

__device__ __forceinline__ void mma_tf32(float c[4], unsigned a0, unsigned a1, unsigned a2,
                                         unsigned a3, unsigned b0, unsigned b1) {
    asm volatile(
        "mma.sync.aligned.m16n8k8.row.col.f32.tf32.tf32.f32 "
        "{%0,%1,%2,%3}, {%4,%5,%6,%7}, {%8,%9}, {%0,%1,%2,%3};"
        : "+f"(c[0]), "+f"(c[1]), "+f"(c[2]), "+f"(c[3])
        : "r"(a0), "r"(a1), "r"(a2), "r"(a3), "r"(b0), "r"(b1));
}

#define CPA16(dst, src) \
    asm volatile("cp.async.cg.shared.global [%0], [%1], 16;" :: "r"(dst), "l"(src))

// ---------------- fp16 GEMM: 128x128 tile, BK=64 halves, 256 thr, 2-stage ------
// stage stride = 32768 B (A 16KB + B 16KB). rows = 128B = 8 x 16B chunks,
// swizzle: phys_chunk = chunk ^ (row&7). warp tile 64x32 (2m x 4n warps).
#define GEMM_SMEM (2 * 32768)

// MODE: 0 = fp32 out (+res), 1 = fp16 out + relu, 3 = fp32 out tf32-rounded
template <int MODE>
__global__ __launch_bounds__(256, 2)
void gemm_tc(const __half* __restrict__ A, const __half* __restrict__ Bt,
             const float* __restrict__ bias, const float* __restrict__ res,
             void* __restrict__ Cv, int M, int N, int K) {
    extern __shared__ unsigned smem_u[];
    unsigned sbase = (unsigned)__cvta_generic_to_shared(smem_u);

    int tid = threadIdx.x;
    int l = tid & 31;
    int wid = tid >> 5;
    int warp_m = wid >> 2;   // 0..1
    int warp_n = wid & 3;    // 0..3
    int bx = blockIdx.x * 128;
    int by = blockIdx.y * 128;

    float acc[4][4][4];
    #pragma unroll
    for (int i = 0; i < 4; i++)
        #pragma unroll
        for (int j = 0; j < 4; j++)
            #pragma unroll
            for (int k = 0; k < 4; k++) acc[i][j][k] = 0.0f;

    int lm = tid >> 3;                 // row 0..31 (4 passes of 32)
    int kc = tid & 7;                  // 16B chunk
    unsigned physc = (unsigned)(kc ^ (lm & 7));
    const __half* aptr = A + (size_t)(by + lm) * K + kc * 8;
    const __half* bptr = Bt + (size_t)(bx + lm) * K + kc * 8;

    int NT = K / 64;

    int rowfrag = (l & 7) + ((l >> 3) & 1) * 8;
    int sel = (l >> 4) & 1;
    int l7 = l & 7;
    int rA = warp_m * 64 + rowfrag;
    int rB = warp_n * 32 + rowfrag;

    auto issue = [&](int kt) {
        unsigned sA = sbase + (unsigned)(kt & 1) * 32768u;
        unsigned sB = sA + 16384u;
        const __half* ap = aptr + kt * 64;
        const __half* bp = bptr + kt * 64;
        #pragma unroll
        for (int i = 0; i < 4; i++) {
            unsigned off = ((unsigned)(lm + 32 * i) * 8 + physc) * 16;
            CPA16(sA + off, ap + (size_t)(32 * i) * K);
            CPA16(sB + off, bp + (size_t)(32 * i) * K);
        }
        asm volatile("cp.async.commit_group;");
    };

    issue(0);
    if (NT > 1) issue(1);

    for (int kt = 0; kt < NT; kt++) {
        if (kt < NT - 1) {
            asm volatile("cp.async.wait_group 1;" ::: "memory");
        } else {
            asm volatile("cp.async.wait_group 0;" ::: "memory");
        }
        __syncthreads();

        unsigned sA = sbase + (unsigned)(kt & 1) * 32768u;
        unsigned sB = sA + 16384u;

        #pragma unroll
        for (int ks = 0; ks < 4; ks++) {
            unsigned phys = (unsigned)((2 * ks + sel) ^ l7) * 16u;
            unsigned aBase = sA + (unsigned)rA * 128u + phys;
            unsigned bBase = sB + (unsigned)rB * 128u + phys;

            unsigned a[4][4], bf[2][4];
            #pragma unroll
            for (int mt = 0; mt < 4; mt++)
                ldsm_x4(a[mt][0], a[mt][1], a[mt][2], a[mt][3], aBase + mt * 2048u);
            #pragma unroll
            for (int np = 0; np < 2; np++)
                ldsm_x4(bf[np][0], bf[np][1], bf[np][2], bf[np][3], bBase + np * 2048u);

            #pragma unroll
            for (int mt = 0; mt < 4; mt++)
                #pragma unroll
                for (int nt = 0; nt < 4; nt++)
                    mma_f16(acc[mt][nt], a[mt][0], a[mt][1], a[mt][2], a[mt][3],
                            bf[nt >> 1][nt & 1], bf[nt >> 1][(nt & 1) + 2]);
        }
        __syncthreads();
        if (kt + 2 < NT) issue(kt + 2);
    }

    int g = l >> 2, tg = l & 3;
    #pragma unroll
    for (int mt = 0; mt < 4; mt++) {
        int r0 = by + warp_m * 64 + mt * 16 + g;
        #pragma unroll
        for (int nt = 0; nt < 4; nt++) {
            int col = bx + warp_n * 32 + nt * 8 + tg * 2;
            float2 v0 = make_float2(acc[mt][nt][0], acc[mt][nt][1]);
            float2 v1 = make_float2(acc[mt][nt][2], acc[mt][nt][3]);
            if (bias != nullptr) {
                float2 bv = *(const float2*)&bias[col];
                v0.x += bv.x; v0.y += bv.y; v1.x += bv.x; v1.y += bv.y;
            }
            if (MODE == 1) {
                __half* C = (__half*)Cv;
                v0.x = fmaxf(v0.x, 0.0f); v0.y = fmaxf(v0.y, 0.0f);
                v1.x = fmaxf(v1.x, 0.0f); v1.y = fmaxf(v1.y, 0.0f);
                *(__half2*)&C[(size_t)r0 * N + col] = __floats2half2_rn(v0.x, v0.y);
                *(__half2*)&C[(size_t)(r0 + 8) * N + col] = __floats2half2_rn(v1.x, v1.y);
            } else {
                if (res != nullptr) {
                    float2 q0 = *(const float2*)&res[(size_t)r0 * N + col];
                    float2 q1 = *(const float2*)&res[(size_t)(r0 + 8) * N + col];
                    v0.x += q0.x; v0.y += q0.y; v1.x += q1.x; v1.y += q1.y;
                }
                if (MODE == 3) {
                    v0.x = f2tf32(v0.x); v0.y = f2tf32(v0.y);
                    v1.x = f2tf32(v1.x); v1.y = f2tf32(v1.y);
                }
                float* C = (float*)Cv;
                *(float2*)&C[(size_t)r0 * N + col] = v0;
                *(float2*)&C[(size_t)(r0 + 8) * N + col] = v1;
            }
        }
    }
}

// ---------------- tf32 tensor-core flash attention (VALIDATED R5 version) ------
// 128-query tile per CTA, 8 warps x 16 rows; 64-key tiles. fp32 qkv in, fp16 out.
// smem (floats): Q[128][64] @0, K[64][64] @8192, VT[64][64] @12288, P[128][64] @16384
#define ATT_SMEM (24576 * 4)

__global__ __launch_bounds__(256, 2)
void attn_tc(const float* __restrict__ qkv, __half* __restrict__ out) {
    extern __shared__ float sm[];
    unsigned ub = (unsigned)__cvta_generic_to_shared(sm);
    unsigned uQ = ub, uK = ub + 8192u * 4, uV = ub + 12288u * 4, uP = ub + 16384u * 4;

    int tid = threadIdx.x;
    int l = tid & 31, w = tid >> 5;
    int b = blockIdx.y >> 4, h = blockIdx.y & 15;
    int q0 = ((int)gridDim.x - 1 - (int)blockIdx.x) * 128;
    int nk = q0 / 64 + 2;

    const float* base = qkv + (size_t)b * SS * D3 + h * HSZ;

    int lr = tid >> 4, lc = tid & 15;
    unsigned lphys = (unsigned)(lc ^ (lr & 7));
    {
        #pragma unroll
        for (int p = 0; p < 8; p++) {
            int row = lr + p * 16;
            CPA16(uQ + (unsigned)(row * 256) + lphys * 16,
                  base + (size_t)(q0 + row) * D3 + lc * 4);
        }
    }
    auto issueK = [&](int k0) {
        #pragma unroll
        for (int p = 0; p < 4; p++) {
            int row = lr + p * 16;
            CPA16(uK + (unsigned)(row * 256) + lphys * 16,
                  base + (size_t)(k0 + row) * D3 + DD + lc * 4);
        }
        asm volatile("cp.async.commit_group;");
    };
    int vs = tid & 63, vdg = tid >> 6;
    float vreg[16];
    auto loadV = [&](int k0) {
        const float* vp = base + (size_t)(k0 + vs) * D3 + 2 * DD + vdg * 16;
        #pragma unroll
        for (int ii = 0; ii < 4; ii++)
            *(float4*)&vreg[ii * 4] = ((const float4*)vp)[ii];
    };
    issueK(0);
    loadV(0);

    float m2[2] = {-1e30f, -1e30f};
    float l2[2] = {0.0f, 0.0f};
    float oacc[8][4];
    #pragma unroll
    for (int i = 0; i < 8; i++)
        #pragma unroll
        for (int j = 0; j < 4; j++) oacc[i][j] = 0.0f;

    int l7 = l & 7;
    int selA = (l >> 4) & 1, selB = (l >> 3) & 1;
    int rA = w * 16 + (l & 7) + ((l >> 3) & 1) * 8;
    int rB = (l & 7) + ((l >> 4) & 1) * 8;
    int rloc = w * 16 + (l >> 2);

    for (int kt = 0; kt < nk; kt++) {
        int k0 = kt * 64;

        __syncthreads();
        #pragma unroll
        for (int ii = 0; ii < 4; ii++)
            #pragma unroll
            for (int j = 0; j < 4; j++) {
                int d = vdg * 16 + ii * 4 + j;
                int phys = (vs >> 2) ^ (d & 7);
                sm[12288 + d * 64 + phys * 4 + (vs & 3)] = vreg[ii * 4 + j];
            }
        asm volatile("cp.async.wait_group 0;" ::: "memory");
        __syncthreads();

        float sacc[8][4];
        #pragma unroll
        for (int i = 0; i < 8; i++)
            #pragma unroll
            for (int j = 0; j < 4; j++) sacc[i][j] = 0.0f;

        #pragma unroll
        for (int ks = 0; ks < 8; ks++) {
            int pA = (2 * ks + selA) ^ l7;
            int pB = (2 * ks + selB) ^ l7;
            unsigned a0, a1, a2, a3;
            ldsm_x4(a0, a1, a2, a3, uQ + (unsigned)(rA * 256 + pA * 16));
            unsigned bf[4][4];
            #pragma unroll
            for (int np = 0; np < 4; np++)
                ldsm_x4(bf[np][0], bf[np][1], bf[np][2], bf[np][3],
                        uK + (unsigned)((rB + np * 16) * 256 + pB * 16));
            #pragma unroll
            for (int nt = 0; nt < 8; nt++)
                mma_tf32(sacc[nt], a0, a1, a2, a3,
                         bf[nt >> 1][(nt & 1) * 2], bf[nt >> 1][(nt & 1) * 2 + 1]);
        }

        #pragma unroll
        for (int nt = 0; nt < 8; nt++)
            #pragma unroll
            for (int e = 0; e < 4; e++) sacc[nt][e] *= 0.125f;
        if (kt >= nk - 2) {
            #pragma unroll
            for (int nt = 0; nt < 8; nt++)
                #pragma unroll
                for (int e = 0; e < 4; e++) {
                    int r = q0 + rloc + ((e >> 1) << 3);
                    int c = k0 + nt * 8 + 2 * (l & 3) + (e & 1);
                    if (c > r) sacc[nt][e] = -1e30f;
                }
        }

        #pragma unroll
        for (int i = 0; i < 2; i++) {
            float tm = -1e30f;
            #pragma unroll
            for (int nt = 0; nt < 8; nt++)
                tm = fmaxf(tm, fmaxf(sacc[nt][2 * i], sacc[nt][2 * i + 1]));
            tm = fmaxf(tm, __shfl_xor_sync(0xffffffffu, tm, 1));
            tm = fmaxf(tm, __shfl_xor_sync(0xffffffffu, tm, 2));
            float mn = fmaxf(m2[i], tm);
            float alpha = __expf(m2[i] - mn);
            m2[i] = mn;
            float ls = 0.0f;
            #pragma unroll
            for (int nt = 0; nt < 8; nt++) {
                float p0 = __expf(sacc[nt][2 * i] - mn);
                float p1 = __expf(sacc[nt][2 * i + 1] - mn);
                sacc[nt][2 * i] = p0;
                sacc[nt][2 * i + 1] = p1;
                ls += p0 + p1;
            }
            ls += __shfl_xor_sync(0xffffffffu, ls, 1);
            ls += __shfl_xor_sync(0xffffffffu, ls, 2);
            l2[i] = l2[i] * alpha + ls;
            #pragma unroll
            for (int nt = 0; nt < 8; nt++) {
                oacc[nt][2 * i] *= alpha;
                oacc[nt][2 * i + 1] *= alpha;
            }
        }

        {
            int colb = 2 * (l & 3);
            #pragma unroll
            for (int nt = 0; nt < 8; nt++) {
                int phys = (2 * nt + ((l & 3) >> 1)) ^ ((l >> 2) & 7);
                float2 v0 = make_float2(f2tf32(sacc[nt][0]), f2tf32(sacc[nt][1]));
                float2 v1 = make_float2(f2tf32(sacc[nt][2]), f2tf32(sacc[nt][3]));
                *(float2*)&sm[16384 + rloc * 64 + phys * 4 + (colb & 3)] = v0;
                *(float2*)&sm[16384 + (rloc + 8) * 64 + phys * 4 + (colb & 3)] = v1;
            }
        }
        __syncthreads();

        if (kt + 1 < nk) {
            issueK(k0 + 64);
            loadV(k0 + 64);
        }

        #pragma unroll
        for (int ks = 0; ks < 8; ks++) {
            int pA = (2 * ks + selA) ^ l7;
            int pB = (2 * ks + selB) ^ l7;
            unsigned a0, a1, a2, a3;
            ldsm_x4(a0, a1, a2, a3, uP + (unsigned)(rA * 256 + pA * 16));
            unsigned bf[4][4];
            #pragma unroll
            for (int np = 0; np < 4; np++)
                ldsm_x4(bf[np][0], bf[np][1], bf[np][2], bf[np][3],
                        uV + (unsigned)((rB + np * 16) * 256 + pB * 16));
            #pragma unroll
            for (int nt = 0; nt < 8; nt++)
                mma_tf32(oacc[nt], a0, a1, a2, a3,
                         bf[nt >> 1][(nt & 1) * 2], bf[nt >> 1][(nt & 1) * 2 + 1]);
        }
    }

    // epilogue: normalize, fp16 out (feeds fp16 proj GEMM)
    float inv0 = 1.0f / l2[0];
    float inv1 = 1.0f / l2[1];
    int r = q0 + rloc;
    int dcol = h * HSZ + 2 * (l & 3);
    #pragma unroll
    for (int nt = 0; nt < 8; nt++) {
        *(__half2*)&out[(size_t)(b * SS + r) * DD + dcol + nt * 8] =
            __floats2half2_rn(oacc[nt][0] * inv0, oacc[nt][1] * inv0);
        *(__half2*)&out[(size_t)(b * SS + r + 8) * DD + dcol + nt * 8] =
            __floats2half2_rn(oacc[nt][2] * inv1, oacc[nt][3] * inv1);
    }
}

// ---------------- launch ----------------
extern "C" void kernel_launch(void* const* d_in, const int* in_sizes, int n_in,
                              void* d_out, int out_size) {
    const float* x     = (const float*)d_in[0];
    const float* wq    = (const float*)d_in[1];
    const float* wk    = (const float*)d_in[2];
    const float* wv    = (const float*)d_in[3];
    const float* wproj = (const float*)d_in[4];
    const float* bproj = (const float*)d_in[5];
    const float* w1    = (const float*)d_in[6];
    const float* b1    = (const float*)d_in[7];
    const float* w2    = (const float*)d_in[8];
    const float* b2    = (const float*)d_in[9];
    const float* ln1_g = (const float*)d_in[10];
    const float* ln1_b = (const float*)d_in[11];
    const float* ln2_g = (const float*)d_in[12];
    const float* ln2_b = (const float*)d_in[13];
    float* out = (float*)d_out;

    __half *p_xn, *p_attn, *p_hn, *p_ff;
    __half *p_wqkvT, *p_wprojT, *p_w1T, *p_w2T;
    float *p_qkv, *p_h;
    cudaGetSymbolAddress((void**)&p_xn, g_xn);
    cudaGetSymbolAddress((void**)&p_qkv, g_qkv);
    cudaGetSymbolAddress((void**)&p_attn, g_attn);
    cudaGetSymbolAddress((void**)&p_h, g_h);
    cudaGetSymbolAddress((void**)&p_hn, g_hn);
    cudaGetSymbolAddress((void**)&p_ff, g_ff);
    cudaGetSymbolAddress((void**)&p_wqkvT, g_wqkvT);
    cudaGetSymbolAddress((void**)&p_wprojT, g_wprojT);
    cudaGetSymbolAddress((void**)&p_w1T, g_w1T);
    cudaGetSymbolAddress((void**)&p_w2T, g_w2T);

    cudaFuncSetAttribute(gemm_tc<0>, cudaFuncAttributeMaxDynamicSharedMemorySize, GEMM_SMEM);
    cudaFuncSetAttribute(gemm_tc<1>, cudaFuncAttributeMaxDynamicSharedMemorySize, GEMM_SMEM);
    cudaFuncSetAttribute(gemm_tc<3>, cudaFuncAttributeMaxDynamicSharedMemorySize, GEMM_SMEM);
    cudaFuncSetAttribute(attn_tc, cudaFuncAttributeMaxDynamicSharedMemorySize, ATT_SMEM);

    // prep (fp16 weight transposes + LN1); slot 5 = QKV gemm for profiling
    build_wqkvT_kernel<<<dim3(16, 16, 3), 256>>>(wq, wk, wv, p_wqkvT);
    transpose_kernel<<<dim3(DD / 32, DD / 32), dim3(32, 8)>>>(wproj, p_wprojT, DD, DD);
    transpose_kernel<<<dim3(DFF / 32, DD / 32), dim3(32, 8)>>>(w1, p_w1T, DD, DFF);
    transpose_kernel<<<dim3(DD / 32, DFF / 32), dim3(32, 8)>>>(w2, p_w2T, DFF, DD);
    ln_kernel<<<BS, 256>>>(x, ln1_g, ln1_b, p_xn);

    // QKV GEMM (fp16 in, fp32 tf32-rounded out for the tf32 attention)
    gemm_tc<3><<<dim3(D3 / 128, BS / 128), 256, GEMM_SMEM>>>(
        p_xn, p_wqkvT, nullptr, nullptr, p_qkv, BS, D3, DD);

    // tf32 tensor-core flash attention (validated), fp16 out
    attn_tc<<<dim3(SS / 128, BB * HH), 256, ATT_SMEM>>>(p_qkv, p_attn);

    // proj + bias + residual(x) -> h (fp32)
    gemm_tc<0><<<dim3(DD / 128, BS / 128), 256, GEMM_SMEM>>>(
        p_attn, p_wprojT, bproj, x, p_h, BS, DD, DD);

    // LN2 -> fp16 hn
    ln_kernel<<<BS, 256>>>(p_h, ln2_g, ln2_b, p_hn);

    // FF1 + bias + relu -> fp16 ff
    gemm_tc<1><<<dim3(DFF / 128, BS / 128), 256, GEMM_SMEM>>>(
        p_hn, p_w1T, b1, nullptr, p_ff, BS, DFF, DD);

    // FF2 + bias + residual(h) -> out (fp32)
    gemm_tc<0><<<dim3(DD / 128, BS / 128), 256, GEMM_SMEM>>>(
        p_ff, p_w2T, b2, p_h, out, BS, DD, DFF);
}

// round 8
// speedup vs baseline: 1.6893x; 1.1638x over previous
#include <cuda_runtime.h>
#include <cuda_fp16.h>

// Problem constants
#define BB 2
#define SS 2048
#define DD 1024
#define HH 16
#define HSZ 64
#define BS (BB * SS)        // 4096 rows
#define D3 (3 * DD)         // 3072
#define DFF (4 * DD)        // 4096

// ---------------- scratch (static device memory; no allocations) ----------------
__device__ __half g_xn[BS * DD];
__device__ __half g_qkv[BS * D3];
__device__ __half g_attn[BS * DD];
__device__ float  g_h[BS * DD];
__device__ __half g_hn[BS * DD];
__device__ __half g_ff[BS * DFF];
__device__ __half g_wqkvT[D3 * DD];
__device__ __half g_wprojT[DD * DD];
__device__ __half g_w1T[DFF * DD];
__device__ __half g_w2T[DD * DFF];

// ---------------- LayerNorm (fp32 in -> fp16 out) ----------------
__global__ void ln_kernel(const float* __restrict__ in, const float* __restrict__ gamma,
                          const float* __restrict__ beta, __half* __restrict__ out) {
    int row = blockIdx.x;
    int tid = threadIdx.x;
    float4 xv = ((const float4*)(in + (size_t)row * DD))[tid];

    __shared__ float red[256];
    red[tid] = xv.x + xv.y + xv.z + xv.w;
    __syncthreads();
    #pragma unroll
    for (int off = 128; off > 0; off >>= 1) {
        if (tid < off) red[tid] += red[tid + off];
        __syncthreads();
    }
    float mu = red[0] * (1.0f / DD);
    __syncthreads();

    float dx = xv.x - mu, dy = xv.y - mu, dz = xv.z - mu, dw = xv.w - mu;
    red[tid] = dx * dx + dy * dy + dz * dz + dw * dw;
    __syncthreads();
    #pragma unroll
    for (int off = 128; off > 0; off >>= 1) {
        if (tid < off) red[tid] += red[tid + off];
        __syncthreads();
    }
    float rstd = rsqrtf(red[0] * (1.0f / DD) + 1e-5f);

    float4 gv = ((const float4*)gamma)[tid];
    float4 bv = ((const float4*)beta)[tid];
    __half2 h0 = __floats2half2_rn(dx * rstd * gv.x + bv.x, dy * rstd * gv.y + bv.y);
    __half2 h1 = __floats2half2_rn(dz * rstd * gv.z + bv.z, dw * rstd * gv.w + bv.w);
    ((__half2*)(out + (size_t)row * DD))[tid * 2] = h0;
    ((__half2*)(out + (size_t)row * DD))[tid * 2 + 1] = h1;
}

// ---------------- build wqkvT [3072][1024] (fp16) ----------------
__global__ void build_wqkvT_kernel(const float* __restrict__ wq, const float* __restrict__ wk,
                                   const float* __restrict__ wv, __half* __restrict__ out) {
    __shared__ float sm[64][65];
    int dblk = blockIdx.x;
    int h = blockIdx.y;
    int part = blockIdx.z;
    const float* w = (part == 0) ? wq : (part == 1) ? wk : wv;
    int tid = threadIdx.x;
    int d0 = dblk * 64;

    int kk = tid & 63;
    int g4 = tid >> 6;
    #pragma unroll
    for (int i = 0; i < 16; i++) {
        int dl = g4 + i * 4;
        sm[dl][kk] = w[((size_t)(h * DD + d0 + dl)) * HSZ + kk];
    }
    __syncthreads();
    int dc = tid & 63;
    #pragma unroll
    for (int i = 0; i < 16; i++) {
        int kk2 = g4 + i * 4;
        out[(size_t)(part * DD + h * HSZ + kk2) * DD + d0 + dc] = __float2half_rn(sm[dc][kk2]);
    }
}

// ---------------- generic transpose: in[R][C] -> out[C][R] (fp16) ------
__global__ void transpose_kernel(const float* __restrict__ in, __half* __restrict__ out,
                                 int R, int C) {
    __shared__ float t[32][33];
    int x = blockIdx.x * 32 + threadIdx.x;
    int y = blockIdx.y * 32 + threadIdx.y;
    #pragma unroll
    for (int i = 0; i < 32; i += 8)
        t[threadIdx.y + i][threadIdx.x] = in[(size_t)(y + i) * C + x];
    __syncthreads();
    x = blockIdx.y * 32 + threadIdx.x;
    y = blockIdx.x * 32 + threadIdx.y;
    #pragma unroll
    for (int i = 0; i < 32; i += 8)
        out[(size_t)(y + i) * R + x] = __float2half_rn(t[threadIdx.x][threadIdx.y + i]);
}

// ---------------- tensor-core helpers -------------------------------
__device__ __forceinline__ void ldsm_x4(unsigned& r0, unsigned& r1, unsigned& r2, unsigned& r3,
                                        unsigned addr) {
    asm volatile("ldmatrix.sync.aligned.m8n8.x4.shared.b16 {%0,%1,%2,%3}, [%4];"
                 : "=r"(r0), "=r"(r1), "=r"(r2), "=r"(r3) : "r"(addr));
}

__device__ __forceinline__ void mma_f16(float c[4], unsigned a0, unsigned a1, unsigned a2,
                                        unsigned a3, unsigned b0, unsigned b1) {
    asm volatile(
        "mma.sync.aligned.m16n8k16.row.col.f32.f16.f16.f32 "
        "{%0,%1,%2,%3}, {%4,%5,%6,%7}, {%8,%9}, {%0,%1,%2,%3};"
        : "+f"(c[0]), "+f"(c[1]), "+f"(c[2]), "+f"(c[3])
        : "r"(a0), "r"(a1), "r"(a2), "r"(a3), "r"(b0), "r"(b1));
}

#define CPA16(dst, src) \
    asm volatile("cp.async.cg.shared.global [%0], [%1], 16;" :: "r"(dst), "l"(src))

// ---------------- fp16 GEMM: 128x128 tile, BK=64 halves, 256 thr, 2-stage ------
// stage stride = 32768 B (A 16KB + B 16KB). rows = 128B = 8 x 16B chunks,
// swizzle: phys_chunk = chunk ^ (row&7). warp tile 64x32 (2m x 4n warps).
#define GEMM_SMEM (2 * 32768)

// MODE: 0 = fp32 out (+res), 1 = fp16 out + relu, 2 = fp16 out
template <int MODE>
__global__ __launch_bounds__(256, 2)
void gemm_tc(const __half* __restrict__ A, const __half* __restrict__ Bt,
             const float* __restrict__ bias, const float* __restrict__ res,
             void* __restrict__ Cv, int M, int N, int K) {
    extern __shared__ unsigned smem_u[];
    unsigned sbase = (unsigned)__cvta_generic_to_shared(smem_u);

    int tid = threadIdx.x;
    int l = tid & 31;
    int wid = tid >> 5;
    int warp_m = wid >> 2;   // 0..1
    int warp_n = wid & 3;    // 0..3
    int bx = blockIdx.x * 128;
    int by = blockIdx.y * 128;

    float acc[4][4][4];
    #pragma unroll
    for (int i = 0; i < 4; i++)
        #pragma unroll
        for (int j = 0; j < 4; j++)
            #pragma unroll
            for (int k = 0; k < 4; k++) acc[i][j][k] = 0.0f;

    int lm = tid >> 3;                 // row 0..31 (4 passes of 32)
    int kc = tid & 7;                  // 16B chunk
    unsigned physc = (unsigned)(kc ^ (lm & 7));
    const __half* aptr = A + (size_t)(by + lm) * K + kc * 8;
    const __half* bptr = Bt + (size_t)(bx + lm) * K + kc * 8;

    int NT = K / 64;

    int rowfrag = (l & 7) + ((l >> 3) & 1) * 8;
    int sel = (l >> 4) & 1;
    int l7 = l & 7;
    int rA = warp_m * 64 + rowfrag;
    int rB = warp_n * 32 + rowfrag;

    auto issue = [&](int kt) {
        unsigned sA = sbase + (unsigned)(kt & 1) * 32768u;
        unsigned sB = sA + 16384u;
        const __half* ap = aptr + kt * 64;
        const __half* bp = bptr + kt * 64;
        #pragma unroll
        for (int i = 0; i < 4; i++) {
            unsigned off = ((unsigned)(lm + 32 * i) * 8 + physc) * 16;
            CPA16(sA + off, ap + (size_t)(32 * i) * K);
            CPA16(sB + off, bp + (size_t)(32 * i) * K);
        }
        asm volatile("cp.async.commit_group;");
    };

    issue(0);
    if (NT > 1) issue(1);

    for (int kt = 0; kt < NT; kt++) {
        if (kt < NT - 1) {
            asm volatile("cp.async.wait_group 1;" ::: "memory");
        } else {
            asm volatile("cp.async.wait_group 0;" ::: "memory");
        }
        __syncthreads();

        unsigned sA = sbase + (unsigned)(kt & 1) * 32768u;
        unsigned sB = sA + 16384u;

        #pragma unroll
        for (int ks = 0; ks < 4; ks++) {
            unsigned phys = (unsigned)((2 * ks + sel) ^ l7) * 16u;
            unsigned aBase = sA + (unsigned)rA * 128u + phys;
            unsigned bBase = sB + (unsigned)rB * 128u + phys;

            unsigned a[4][4], bf[2][4];
            #pragma unroll
            for (int mt = 0; mt < 4; mt++)
                ldsm_x4(a[mt][0], a[mt][1], a[mt][2], a[mt][3], aBase + mt * 2048u);
            #pragma unroll
            for (int np = 0; np < 2; np++)
                ldsm_x4(bf[np][0], bf[np][1], bf[np][2], bf[np][3], bBase + np * 2048u);

            #pragma unroll
            for (int mt = 0; mt < 4; mt++)
                #pragma unroll
                for (int nt = 0; nt < 4; nt++)
                    mma_f16(acc[mt][nt], a[mt][0], a[mt][1], a[mt][2], a[mt][3],
                            bf[nt >> 1][nt & 1], bf[nt >> 1][(nt & 1) + 2]);
        }
        __syncthreads();
        if (kt + 2 < NT) issue(kt + 2);
    }

    int g = l >> 2, tg = l & 3;
    #pragma unroll
    for (int mt = 0; mt < 4; mt++) {
        int r0 = by + warp_m * 64 + mt * 16 + g;
        #pragma unroll
        for (int nt = 0; nt < 4; nt++) {
            int col = bx + warp_n * 32 + nt * 8 + tg * 2;
            float2 v0 = make_float2(acc[mt][nt][0], acc[mt][nt][1]);
            float2 v1 = make_float2(acc[mt][nt][2], acc[mt][nt][3]);
            if (bias != nullptr) {
                float2 bv = *(const float2*)&bias[col];
                v0.x += bv.x; v0.y += bv.y; v1.x += bv.x; v1.y += bv.y;
            }
            if (MODE == 0) {
                if (res != nullptr) {
                    float2 q0 = *(const float2*)&res[(size_t)r0 * N + col];
                    float2 q1 = *(const float2*)&res[(size_t)(r0 + 8) * N + col];
                    v0.x += q0.x; v0.y += q0.y; v1.x += q1.x; v1.y += q1.y;
                }
                float* C = (float*)Cv;
                *(float2*)&C[(size_t)r0 * N + col] = v0;
                *(float2*)&C[(size_t)(r0 + 8) * N + col] = v1;
            } else {
                if (MODE == 1) {
                    v0.x = fmaxf(v0.x, 0.0f); v0.y = fmaxf(v0.y, 0.0f);
                    v1.x = fmaxf(v1.x, 0.0f); v1.y = fmaxf(v1.y, 0.0f);
                }
                __half* C = (__half*)Cv;
                *(__half2*)&C[(size_t)r0 * N + col] = __floats2half2_rn(v0.x, v0.y);
                *(__half2*)&C[(size_t)(r0 + 8) * N + col] = __floats2half2_rn(v1.x, v1.y);
            }
        }
    }
}

// ---------------- fp16 tensor-core flash attention ----------------------------
// 128-query tile, 8 warps x 16 rows; 64-key tiles. R5 loop structure; all
// fragment paths use the GEMM-validated non-trans ldsm wiring.
// smem bytes: Q[128][128B] @0 (16KB), K[64][128B] @16384 (8KB),
//             VT[64][128B] @24576 (8KB), P[128][128B] @32768 (16KB). total 48KB.
// swizzle everywhere: phys_chunk = chunk ^ (row&7), 8 chunks x 16B per 128B row.
#define ATT_SMEM 49152

__global__ __launch_bounds__(256, 2)
void attn_tc(const __half* __restrict__ qkv, __half* __restrict__ out) {
    extern __shared__ char smc[];
    unsigned ub = (unsigned)__cvta_generic_to_shared(smc);
    unsigned uQ = ub, uK = ub + 16384u, uVT = ub + 24576u, uP = ub + 32768u;

    int tid = threadIdx.x;
    int l = tid & 31, w = tid >> 5;
    int b = blockIdx.y >> 4, h = blockIdx.y & 15;
    int q0 = ((int)gridDim.x - 1 - (int)blockIdx.x) * 128;
    int nk = q0 / 64 + 2;

    const __half* base = qkv + (size_t)b * SS * D3 + h * HSZ;

    // gmem->smem mapping (identical to GEMM): lr = row 0..31, lc = 16B chunk
    int lr = tid >> 3, lc = tid & 7;
    unsigned lphys = (unsigned)(lc ^ (lr & 7)) * 16u;

    // Q: 128 rows, 4 passes
    #pragma unroll
    for (int p = 0; p < 4; p++) {
        int row = lr + 32 * p;
        CPA16(uQ + (unsigned)row * 128u + lphys, base + (size_t)(q0 + row) * D3 + lc * 8);
    }
    auto issueK = [&](int k0) {
        #pragma unroll
        for (int p = 0; p < 2; p++) {
            int row = lr + 32 * p;
            CPA16(uK + (unsigned)row * 128u + lphys,
                  base + (size_t)(k0 + row) * D3 + DD + lc * 8);
        }
        asm volatile("cp.async.commit_group;");
    };

    // V: regs. thread handles s = vs2, vs2+1 and d = vdg*8 .. +7 (8 halves each row)
    int vs2 = (tid & 31) * 2, vdg = tid >> 5;
    uint4 vr0, vr1;
    auto loadV = [&](int k0) {
        const __half* vp = base + (size_t)(k0 + vs2) * D3 + 2 * DD + vdg * 8;
        vr0 = *(const uint4*)vp;
        vr1 = *(const uint4*)(vp + D3);
    };
    issueK(0);
    loadV(0);

    float m2[2] = {-1e30f, -1e30f};
    float l2[2] = {0.0f, 0.0f};
    float oacc[8][4];
    #pragma unroll
    for (int i = 0; i < 8; i++)
        #pragma unroll
        for (int j = 0; j < 4; j++) oacc[i][j] = 0.0f;

    int l7 = l & 7;
    int rowfrag = (l & 7) + ((l >> 3) & 1) * 8;
    int sel = (l >> 4) & 1;
    int rA = w * 16 + rowfrag;
    int rloc = w * 16 + (l >> 2);

    for (int kt = 0; kt < nk; kt++) {
        int k0 = kt * 64;

        __syncthreads();   // prior PV reads of VT/P done
        // store V transposed: VT[d][s], conflict-free half2 stores
        {
            const __half* h0 = (const __half*)&vr0;
            const __half* h1 = (const __half*)&vr1;
            unsigned srow = (unsigned)(vs2 >> 3);      // chunk index from s
            unsigned scol = (unsigned)(vs2 & 7) * 2u;  // byte within chunk
            #pragma unroll
            for (int j = 0; j < 8; j++) {
                int d = vdg * 8 + j;
                unsigned phys = (srow ^ (unsigned)(d & 7)) * 16u;
                *(__half2*)(smc + 24576u + (unsigned)d * 128u + phys + scol) =
                    __halves2half2(h0[j], h1[j]);
            }
        }
        asm volatile("cp.async.wait_group 0;" ::: "memory");
        __syncthreads();   // K + VT visible

        // ---- S = Q K^T ----
        float sacc[8][4];
        #pragma unroll
        for (int i = 0; i < 8; i++)
            #pragma unroll
            for (int j = 0; j < 4; j++) sacc[i][j] = 0.0f;

        #pragma unroll
        for (int ks = 0; ks < 4; ks++) {
            unsigned phys = (unsigned)((2 * ks + sel) ^ l7) * 16u;
            unsigned a0, a1, a2, a3;
            ldsm_x4(a0, a1, a2, a3, uQ + (unsigned)rA * 128u + phys);
            unsigned bf[4][4];
            #pragma unroll
            for (int np = 0; np < 4; np++)
                ldsm_x4(bf[np][0], bf[np][1], bf[np][2], bf[np][3],
                        uK + (unsigned)(np * 16 + rowfrag) * 128u + phys);
            #pragma unroll
            for (int nt = 0; nt < 8; nt++)
                mma_f16(sacc[nt], a0, a1, a2, a3,
                        bf[nt >> 1][nt & 1], bf[nt >> 1][(nt & 1) + 2]);
        }

        // scale + causal mask
        #pragma unroll
        for (int nt = 0; nt < 8; nt++)
            #pragma unroll
            for (int e = 0; e < 4; e++) sacc[nt][e] *= 0.125f;
        if (kt >= nk - 2) {
            #pragma unroll
            for (int nt = 0; nt < 8; nt++)
                #pragma unroll
                for (int e = 0; e < 4; e++) {
                    int r = q0 + rloc + ((e >> 1) << 3);
                    int c = k0 + nt * 8 + 2 * (l & 3) + (e & 1);
                    if (c > r) sacc[nt][e] = -1e30f;
                }
        }

        // online softmax (2 rows per thread)
        #pragma unroll
        for (int i = 0; i < 2; i++) {
            float tm = -1e30f;
            #pragma unroll
            for (int nt = 0; nt < 8; nt++)
                tm = fmaxf(tm, fmaxf(sacc[nt][2 * i], sacc[nt][2 * i + 1]));
            tm = fmaxf(tm, __shfl_xor_sync(0xffffffffu, tm, 1));
            tm = fmaxf(tm, __shfl_xor_sync(0xffffffffu, tm, 2));
            float mn = fmaxf(m2[i], tm);
            float alpha = __expf(m2[i] - mn);
            m2[i] = mn;
            float ls = 0.0f;
            #pragma unroll
            for (int nt = 0; nt < 8; nt++) {
                float p0 = __expf(sacc[nt][2 * i] - mn);
                float p1 = __expf(sacc[nt][2 * i + 1] - mn);
                sacc[nt][2 * i] = p0;
                sacc[nt][2 * i + 1] = p1;
                ls += p0 + p1;
            }
            ls += __shfl_xor_sync(0xffffffffu, ls, 1);
            ls += __shfl_xor_sync(0xffffffffu, ls, 2);
            l2[i] = l2[i] * alpha + ls;
            #pragma unroll
            for (int nt = 0; nt < 8; nt++) {
                oacc[nt][2 * i] *= alpha;
                oacc[nt][2 * i + 1] *= alpha;
            }
        }

        // store P (fp16): rows rloc / rloc+8, cols nt*8 + 2(l&3)
        // byte-in-row = nt*16 + (l&3)*4 -> chunk = nt, phys = nt ^ (rloc&7)
        {
            unsigned pc = (unsigned)(rloc & 7);
            unsigned prow = 32768u + (unsigned)rloc * 128u + (unsigned)((l & 3) * 4);
            #pragma unroll
            for (int nt = 0; nt < 8; nt++) {
                unsigned boff = prow + ((unsigned)nt ^ pc) * 16u;
                *(__half2*)(smc + boff) = __floats2half2_rn(sacc[nt][0], sacc[nt][1]);
                *(__half2*)(smc + boff + 1024u) = __floats2half2_rn(sacc[nt][2], sacc[nt][3]);
            }
        }
        __syncthreads();   // P visible; all warps done reading K

        if (kt + 1 < nk) {
            issueK(k0 + 64);
            loadV(k0 + 64);
        }

        // ---- O += P @ VT^T  (B operand = VT[d][s], GEMM wiring) ----
        #pragma unroll
        for (int ks = 0; ks < 4; ks++) {
            unsigned phys = (unsigned)((2 * ks + sel) ^ l7) * 16u;
            unsigned a0, a1, a2, a3;
            ldsm_x4(a0, a1, a2, a3, uP + (unsigned)rA * 128u + phys);
            unsigned bf[4][4];
            #pragma unroll
            for (int np = 0; np < 4; np++)
                ldsm_x4(bf[np][0], bf[np][1], bf[np][2], bf[np][3],
                        uVT + (unsigned)(np * 16 + rowfrag) * 128u + phys);
            #pragma unroll
            for (int nt = 0; nt < 8; nt++)
                mma_f16(oacc[nt], a0, a1, a2, a3,
                        bf[nt >> 1][nt & 1], bf[nt >> 1][(nt & 1) + 2]);
        }
    }

    // epilogue: normalize, fp16 out (feeds fp16 proj GEMM)
    float inv0 = 1.0f / l2[0];
    float inv1 = 1.0f / l2[1];
    int r = q0 + rloc;
    int dcol = h * HSZ + 2 * (l & 3);
    #pragma unroll
    for (int nt = 0; nt < 8; nt++) {
        *(__half2*)&out[(size_t)(b * SS + r) * DD + dcol + nt * 8] =
            __floats2half2_rn(oacc[nt][0] * inv0, oacc[nt][1] * inv0);
        *(__half2*)&out[(size_t)(b * SS + r + 8) * DD + dcol + nt * 8] =
            __floats2half2_rn(oacc[nt][2] * inv1, oacc[nt][3] * inv1);
    }
}

// ---------------- launch ----------------
extern "C" void kernel_launch(void* const* d_in, const int* in_sizes, int n_in,
                              void* d_out, int out_size) {
    const float* x     = (const float*)d_in[0];
    const float* wq    = (const float*)d_in[1];
    const float* wk    = (const float*)d_in[2];
    const float* wv    = (const float*)d_in[3];
    const float* wproj = (const float*)d_in[4];
    const float* bproj = (const float*)d_in[5];
    const float* w1    = (const float*)d_in[6];
    const float* b1    = (const float*)d_in[7];
    const float* w2    = (const float*)d_in[8];
    const float* b2    = (const float*)d_in[9];
    const float* ln1_g = (const float*)d_in[10];
    const float* ln1_b = (const float*)d_in[11];
    const float* ln2_g = (const float*)d_in[12];
    const float* ln2_b = (const float*)d_in[13];
    float* out = (float*)d_out;

    __half *p_xn, *p_qkv, *p_attn, *p_hn, *p_ff;
    __half *p_wqkvT, *p_wprojT, *p_w1T, *p_w2T;
    float *p_h;
    cudaGetSymbolAddress((void**)&p_xn, g_xn);
    cudaGetSymbolAddress((void**)&p_qkv, g_qkv);
    cudaGetSymbolAddress((void**)&p_attn, g_attn);
    cudaGetSymbolAddress((void**)&p_h, g_h);
    cudaGetSymbolAddress((void**)&p_hn, g_hn);
    cudaGetSymbolAddress((void**)&p_ff, g_ff);
    cudaGetSymbolAddress((void**)&p_wqkvT, g_wqkvT);
    cudaGetSymbolAddress((void**)&p_wprojT, g_wprojT);
    cudaGetSymbolAddress((void**)&p_w1T, g_w1T);
    cudaGetSymbolAddress((void**)&p_w2T, g_w2T);

    cudaFuncSetAttribute(gemm_tc<0>, cudaFuncAttributeMaxDynamicSharedMemorySize, GEMM_SMEM);
    cudaFuncSetAttribute(gemm_tc<1>, cudaFuncAttributeMaxDynamicSharedMemorySize, GEMM_SMEM);
    cudaFuncSetAttribute(gemm_tc<2>, cudaFuncAttributeMaxDynamicSharedMemorySize, GEMM_SMEM);
    cudaFuncSetAttribute(attn_tc, cudaFuncAttributeMaxDynamicSharedMemorySize, ATT_SMEM);

    // prep (fp16 weight transposes + LN1); slot 5 = QKV gemm for profiling
    build_wqkvT_kernel<<<dim3(16, 16, 3), 256>>>(wq, wk, wv, p_wqkvT);
    transpose_kernel<<<dim3(DD / 32, DD / 32), dim3(32, 8)>>>(wproj, p_wprojT, DD, DD);
    transpose_kernel<<<dim3(DFF / 32, DD / 32), dim3(32, 8)>>>(w1, p_w1T, DD, DFF);
    transpose_kernel<<<dim3(DD / 32, DFF / 32), dim3(32, 8)>>>(w2, p_w2T, DFF, DD);
    ln_kernel<<<BS, 256>>>(x, ln1_g, ln1_b, p_xn);

    // QKV GEMM -> fp16 qkv
    gemm_tc<2><<<dim3(D3 / 128, BS / 128), 256, GEMM_SMEM>>>(
        p_xn, p_wqkvT, nullptr, nullptr, p_qkv, BS, D3, DD);

    // fp16 tensor-core flash attention
    attn_tc<<<dim3(SS / 128, BB * HH), 256, ATT_SMEM>>>(p_qkv, p_attn);

    // proj + bias + residual(x) -> h (fp32)
    gemm_tc<0><<<dim3(DD / 128, BS / 128), 256, GEMM_SMEM>>>(
        p_attn, p_wprojT, bproj, x, p_h, BS, DD, DD);

    // LN2 -> fp16 hn
    ln_kernel<<<BS, 256>>>(p_h, ln2_g, ln2_b, p_hn);

    // FF1 + bias + relu -> fp16 ff
    gemm_tc<1><<<dim3(DFF / 128, BS / 128), 256, GEMM_SMEM>>>(
        p_hn, p_w1T, b1, nullptr, p_ff, BS, DFF, DD);

    // FF2 + bias + residual(h) -> out (fp32)
    gemm_tc<0><<<dim3(DD / 128, BS / 128), 256, GEMM_SMEM>>>(
        p_ff, p_w2T, b2, p_h, out, BS, DD, DFF);
}

// round 10
// speedup vs baseline: 1.7126x; 1.0138x over previous
#include <cuda_runtime.h>
#include <cuda_fp16.h>
#include <cstdint>

// Problem constants
#define BB 2
#define SS 2048
#define DD 1024
#define HH 16
#define HSZ 64
#define BS (BB * SS)        // 4096 rows
#define D3 (3 * DD)         // 3072
#define DFF (4 * DD)        // 4096

// ---------------- scratch (static device memory; no allocations) ----------------
__device__ __half g_xn[BS * DD];
__device__ __half g_qkv[BS * D3];
__device__ __half g_attn[BS * DD];
__device__ float  g_h[BS * DD];
__device__ __half g_hn[BS * DD];
__device__ __half g_ff[BS * DFF];
__device__ __half g_wqkvT[D3 * DD];
__device__ __half g_wprojT[DD * DD];
__device__ __half g_w1T[DFF * DD];
__device__ __half g_w2T[DD * DFF];

// ---------------- LayerNorm (fp32 in -> fp16 out) ----------------
__global__ void ln_kernel(const float* __restrict__ in, const float* __restrict__ gamma,
                          const float* __restrict__ beta, __half* __restrict__ out) {
    int row = blockIdx.x;
    int tid = threadIdx.x;
    float4 xv = ((const float4*)(in + (size_t)row * DD))[tid];

    __shared__ float red[256];
    red[tid] = xv.x + xv.y + xv.z + xv.w;
    __syncthreads();
    #pragma unroll
    for (int off = 128; off > 0; off >>= 1) {
        if (tid < off) red[tid] += red[tid + off];
        __syncthreads();
    }
    float mu = red[0] * (1.0f / DD);
    __syncthreads();

    float dx = xv.x - mu, dy = xv.y - mu, dz = xv.z - mu, dw = xv.w - mu;
    red[tid] = dx * dx + dy * dy + dz * dz + dw * dw;
    __syncthreads();
    #pragma unroll
    for (int off = 128; off > 0; off >>= 1) {
        if (tid < off) red[tid] += red[tid + off];
        __syncthreads();
    }
    float rstd = rsqrtf(red[0] * (1.0f / DD) + 1e-5f);

    float4 gv = ((const float4*)gamma)[tid];
    float4 bv = ((const float4*)beta)[tid];
    __half2 h0 = __floats2half2_rn(dx * rstd * gv.x + bv.x, dy * rstd * gv.y + bv.y);
    __half2 h1 = __floats2half2_rn(dz * rstd * gv.z + bv.z, dw * rstd * gv.w + bv.w);
    ((__half2*)(out + (size_t)row * DD))[tid * 2] = h0;
    ((__half2*)(out + (size_t)row * DD))[tid * 2 + 1] = h1;
}

// ---------------- build wqkvT [3072][1024] (fp16) ----------------
__global__ void build_wqkvT_kernel(const float* __restrict__ wq, const float* __restrict__ wk,
                                   const float* __restrict__ wv, __half* __restrict__ out) {
    __shared__ float sm[64][65];
    int dblk = blockIdx.x;
    int h = blockIdx.y;
    int part = blockIdx.z;
    const float* w = (part == 0) ? wq : (part == 1) ? wk : wv;
    int tid = threadIdx.x;
    int d0 = dblk * 64;

    int kk = tid & 63;
    int g4 = tid >> 6;
    #pragma unroll
    for (int i = 0; i < 16; i++) {
        int dl = g4 + i * 4;
        sm[dl][kk] = w[((size_t)(h * DD + d0 + dl)) * HSZ + kk];
    }
    __syncthreads();
    int dc = tid & 63;
    #pragma unroll
    for (int i = 0; i < 16; i++) {
        int kk2 = g4 + i * 4;
        out[(size_t)(part * DD + h * HSZ + kk2) * DD + d0 + dc] = __float2half_rn(sm[dc][kk2]);
    }
}

// ---------------- generic transpose: in[R][C] -> out[C][R] (fp16) ------
__global__ void transpose_kernel(const float* __restrict__ in, __half* __restrict__ out,
                                 int R, int C) {
    __shared__ float t[32][33];
    int x = blockIdx.x * 32 + threadIdx.x;
    int y = blockIdx.y * 32 + threadIdx.y;
    #pragma unroll
    for (int i = 0; i < 32; i += 8)
        t[threadIdx.y + i][threadIdx.x] = in[(size_t)(y + i) * C + x];
    __syncthreads();
    x = blockIdx.y * 32 + threadIdx.x;
    y = blockIdx.x * 32 + threadIdx.y;
    #pragma unroll
    for (int i = 0; i < 32; i += 8)
        out[(size_t)(y + i) * R + x] = __float2half_rn(t[threadIdx.x][threadIdx.y + i]);
}

// ---------------- tensor-core helpers -------------------------------
__device__ __forceinline__ void ldsm_x4(unsigned& r0, unsigned& r1, unsigned& r2, unsigned& r3,
                                        unsigned addr) {
    asm volatile("ldmatrix.sync.aligned.m8n8.x4.shared.b16 {%0,%1,%2,%3}, [%4];"
                 : "=r"(r0), "=r"(r1), "=r"(r2), "=r"(r3) : "r"(addr));
}

__device__ __forceinline__ void mma_f16(float c[4], unsigned a0, unsigned a1, unsigned a2,
                                        unsigned a3, unsigned b0, unsigned b1) {
    asm volatile(
        "mma.sync.aligned.m16n8k16.row.col.f32.f16.f16.f32 "
        "{%0,%1,%2,%3}, {%4,%5,%6,%7}, {%8,%9}, {%0,%1,%2,%3};"
        : "+f"(c[0]), "+f"(c[1]), "+f"(c[2]), "+f"(c[3])
        : "r"(a0), "r"(a1), "r"(a2), "r"(a3), "r"(b0), "r"(b1));
}

#define CPA16(dst, src) \
    asm volatile("cp.async.cg.shared.global [%0], [%1], 16;" :: "r"(dst), "l"(src))

// ---------------- fp16 GEMM: 128x128 tile, BK=64 halves, 256 thr, 3-stage ------
// stage stride = 32768 B (A 16KB + B 16KB). rows = 128B = 8 x 16B chunks,
// swizzle: phys_chunk = chunk ^ (row&7). warp tile 64x32 (2m x 4n warps).
// Single __syncthreads per chunk: with 3 buffers, write target (kt+2)%3 ==
// (kt-1)%3 whose readers all arrived at this chunk's barrier already.
#define GEMM_SMEM (3 * 32768)

// MODE: 0 = fp32 out (+res), 1 = fp16 out + relu, 2 = fp16 out
template <int MODE>
__global__ __launch_bounds__(256, 2)
void gemm_tc(const __half* __restrict__ A, const __half* __restrict__ Bt,
             const float* __restrict__ bias, const float* __restrict__ res,
             void* __restrict__ Cv, int M, int N, int K) {
    extern __shared__ unsigned smem_u[];
    unsigned sbase = (unsigned)__cvta_generic_to_shared(smem_u);

    int tid = threadIdx.x;
    int l = tid & 31;
    int wid = tid >> 5;
    int warp_m = wid >> 2;   // 0..1
    int warp_n = wid & 3;    // 0..3
    int bx = blockIdx.x * 128;
    int by = blockIdx.y * 128;

    float acc[4][4][4];
    #pragma unroll
    for (int i = 0; i < 4; i++)
        #pragma unroll
        for (int j = 0; j < 4; j++)
            #pragma unroll
            for (int k = 0; k < 4; k++) acc[i][j][k] = 0.0f;

    int lm = tid >> 3;                 // row 0..31 (4 passes of 32)
    int kc = tid & 7;                  // 16B chunk
    unsigned physc = (unsigned)(kc ^ (lm & 7));
    const __half* aptr = A + (size_t)(by + lm) * K + kc * 8;
    const __half* bptr = Bt + (size_t)(bx + lm) * K + kc * 8;

    int NT = K / 64;

    int rowfrag = (l & 7) + ((l >> 3) & 1) * 8;
    int sel = (l >> 4) & 1;
    int l7 = l & 7;
    int rA = warp_m * 64 + rowfrag;
    int rB = warp_n * 32 + rowfrag;

    auto issue = [&](int kt) {
        unsigned sA = sbase + (unsigned)(kt % 3) * 32768u;
        unsigned sB = sA + 16384u;
        const __half* ap = aptr + kt * 64;
        const __half* bp = bptr + kt * 64;
        #pragma unroll
        for (int i = 0; i < 4; i++) {
            unsigned off = ((unsigned)(lm + 32 * i) * 8 + physc) * 16;
            CPA16(sA + off, ap + (size_t)(32 * i) * K);
            CPA16(sB + off, bp + (size_t)(32 * i) * K);
        }
        asm volatile("cp.async.commit_group;");
    };

    issue(0);
    issue(1);

    #pragma unroll 1
    for (int kt = 0; kt < NT; kt++) {
        if (kt < NT - 1) {
            asm volatile("cp.async.wait_group 1;" ::: "memory");
        } else {
            asm volatile("cp.async.wait_group 0;" ::: "memory");
        }
        __syncthreads();   // stage kt visible; all warps done reading stage kt-1

        if (kt + 2 < NT) issue(kt + 2);   // buffer (kt+2)%3 == (kt-1)%3, free

        unsigned sA = sbase + (unsigned)(kt % 3) * 32768u;
        unsigned sB = sA + 16384u;

        #pragma unroll
        for (int ks = 0; ks < 4; ks++) {
            unsigned phys = (unsigned)((2 * ks + sel) ^ l7) * 16u;
            unsigned aBase = sA + (unsigned)rA * 128u + phys;
            unsigned bBase = sB + (unsigned)rB * 128u + phys;

            unsigned a[4][4], bf[2][4];
            #pragma unroll
            for (int mt = 0; mt < 4; mt++)
                ldsm_x4(a[mt][0], a[mt][1], a[mt][2], a[mt][3], aBase + mt * 2048u);
            #pragma unroll
            for (int np = 0; np < 2; np++)
                ldsm_x4(bf[np][0], bf[np][1], bf[np][2], bf[np][3], bBase + np * 2048u);

            #pragma unroll
            for (int mt = 0; mt < 4; mt++)
                #pragma unroll
                for (int nt = 0; nt < 4; nt++)
                    mma_f16(acc[mt][nt], a[mt][0], a[mt][1], a[mt][2], a[mt][3],
                            bf[nt >> 1][nt & 1], bf[nt >> 1][(nt & 1) + 2]);
        }
    }

    int g = l >> 2, tg = l & 3;
    #pragma unroll
    for (int mt = 0; mt < 4; mt++) {
        int r0 = by + warp_m * 64 + mt * 16 + g;
        #pragma unroll
        for (int nt = 0; nt < 4; nt++) {
            int col = bx + warp_n * 32 + nt * 8 + tg * 2;
            float2 v0 = make_float2(acc[mt][nt][0], acc[mt][nt][1]);
            float2 v1 = make_float2(acc[mt][nt][2], acc[mt][nt][3]);
            if (bias != nullptr) {
                float2 bv = *(const float2*)&bias[col];
                v0.x += bv.x; v0.y += bv.y; v1.x += bv.x; v1.y += bv.y;
            }
            if (MODE == 0) {
                if (res != nullptr) {
                    float2 q0 = *(const float2*)&res[(size_t)r0 * N + col];
                    float2 q1 = *(const float2*)&res[(size_t)(r0 + 8) * N + col];
                    v0.x += q0.x; v0.y += q0.y; v1.x += q1.x; v1.y += q1.y;
                }
                float* C = (float*)Cv;
                *(float2*)&C[(size_t)r0 * N + col] = v0;
                *(float2*)&C[(size_t)(r0 + 8) * N + col] = v1;
            } else {
                if (MODE == 1) {
                    v0.x = fmaxf(v0.x, 0.0f); v0.y = fmaxf(v0.y, 0.0f);
                    v1.x = fmaxf(v1.x, 0.0f); v1.y = fmaxf(v1.y, 0.0f);
                }
                __half* C = (__half*)Cv;
                *(__half2*)&C[(size_t)r0 * N + col] = __floats2half2_rn(v0.x, v0.y);
                *(__half2*)&C[(size_t)(r0 + 8) * N + col] = __floats2half2_rn(v1.x, v1.y);
            }
        }
    }
}

// ---------------- fp16 flash attention: 2 barriers/tile, Q-frags hoisted -------
// 128-query tile, 8 warps x 16 rows; 64-key tiles.
// smem: Q[128][128B] @0 (16KB), K[64][128B] @16384 (8KB),
//       VT[2][64][128B] @24576/@32768 (8KB each),
//       P[2][128][128B] @40960/@57344 (16KB each). total 72KB.
// Double-buffered VT/P remove the iteration-start barrier: buffer kt&1 was
// last read at tile kt-2, and all warps passed tile kt-1's first barrier.
#define ATT_SMEM 73728

__global__ __launch_bounds__(256, 2)
void attn_tc(const __half* __restrict__ qkv, __half* __restrict__ out) {
    extern __shared__ char smc[];
    unsigned ub = (unsigned)__cvta_generic_to_shared(smc);
    unsigned uQ = ub, uK = ub + 16384u;

    int tid = threadIdx.x;
    int l = tid & 31, w = tid >> 5;
    int b = blockIdx.y >> 4, h = blockIdx.y & 15;
    int q0 = ((int)gridDim.x - 1 - (int)blockIdx.x) * 128;
    int nk = q0 / 64 + 2;

    const __half* base = qkv + (size_t)b * SS * D3 + h * HSZ;

    int lr = tid >> 3, lc = tid & 7;
    unsigned lphys = (unsigned)(lc ^ (lr & 7)) * 16u;

    #pragma unroll
    for (int p = 0; p < 4; p++) {
        int row = lr + 32 * p;
        CPA16(uQ + (unsigned)row * 128u + lphys, base + (size_t)(q0 + row) * D3 + lc * 8);
    }
    auto issueK = [&](int k0) {
        #pragma unroll
        for (int p = 0; p < 2; p++) {
            int row = lr + 32 * p;
            CPA16(uK + (unsigned)row * 128u + lphys,
                  base + (size_t)(k0 + row) * D3 + DD + lc * 8);
        }
        asm volatile("cp.async.commit_group;");
    };

    int vs2 = (tid & 31) * 2, vdg = tid >> 5;
    uint4 vr0, vr1;
    auto loadV = [&](int k0) {
        const __half* vp = base + (size_t)(k0 + vs2) * D3 + 2 * DD + vdg * 8;
        vr0 = *(const uint4*)vp;
        vr1 = *(const uint4*)(vp + D3);
    };
    issueK(0);   // group 0: Q + K(0)
    loadV(0);

    float m2[2] = {-1e30f, -1e30f};
    float l2[2] = {0.0f, 0.0f};
    float oacc[8][4];
    #pragma unroll
    for (int i = 0; i < 8; i++)
        #pragma unroll
        for (int j = 0; j < 4; j++) oacc[i][j] = 0.0f;

    int l7 = l & 7;
    int rowfrag = (l & 7) + ((l >> 3) & 1) * 8;
    int sel = (l >> 4) & 1;
    int rA = w * 16 + rowfrag;
    int rloc = w * 16 + (l >> 2);

    // ---- hoist Q fragments (Q smem dead afterwards) ----
    unsigned aq[4][4];
    asm volatile("cp.async.wait_group 0;" ::: "memory");
    __syncthreads();
    #pragma unroll
    for (int ks = 0; ks < 4; ks++) {
        unsigned phys = (unsigned)((2 * ks + sel) ^ l7) * 16u;
        ldsm_x4(aq[ks][0], aq[ks][1], aq[ks][2], aq[ks][3], uQ + (unsigned)rA * 128u + phys);
    }

    for (int kt = 0; kt < nk; kt++) {
        int k0 = kt * 64;
        unsigned uVT = ub + 24576u + (unsigned)(kt & 1) * 8192u;
        unsigned uP  = ub + 40960u + (unsigned)(kt & 1) * 16384u;

        // store V transposed into VT[kt&1] (free: last read at tile kt-2)
        {
            const __half* h0 = (const __half*)&vr0;
            const __half* h1 = (const __half*)&vr1;
            unsigned srow = (unsigned)(vs2 >> 3);
            unsigned scol = (unsigned)(vs2 & 7) * 2u;
            unsigned vtb = 24576u + (unsigned)(kt & 1) * 8192u;
            #pragma unroll
            for (int j = 0; j < 8; j++) {
                int d = vdg * 8 + j;
                unsigned phys = (srow ^ (unsigned)(d & 7)) * 16u;
                *(__half2*)(smc + vtb + (unsigned)d * 128u + phys + scol) =
                    __halves2half2(h0[j], h1[j]);
            }
        }
        asm volatile("cp.async.wait_group 0;" ::: "memory");
        __syncthreads();   // barrier 1: K(kt) + VT(kt) visible

        // ---- S = Q K^T ----
        float sacc[8][4];
        #pragma unroll
        for (int i = 0; i < 8; i++)
            #pragma unroll
            for (int j = 0; j < 4; j++) sacc[i][j] = 0.0f;

        #pragma unroll
        for (int ks = 0; ks < 4; ks++) {
            unsigned phys = (unsigned)((2 * ks + sel) ^ l7) * 16u;
            unsigned bf[4][4];
            #pragma unroll
            for (int np = 0; np < 4; np++)
                ldsm_x4(bf[np][0], bf[np][1], bf[np][2], bf[np][3],
                        uK + (unsigned)(np * 16 + rowfrag) * 128u + phys);
            #pragma unroll
            for (int nt = 0; nt < 8; nt++)
                mma_f16(sacc[nt], aq[ks][0], aq[ks][1], aq[ks][2], aq[ks][3],
                        bf[nt >> 1][nt & 1], bf[nt >> 1][(nt & 1) + 2]);
        }

        #pragma unroll
        for (int nt = 0; nt < 8; nt++)
            #pragma unroll
            for (int e = 0; e < 4; e++) sacc[nt][e] *= 0.125f;
        if (kt >= nk - 2) {
            #pragma unroll
            for (int nt = 0; nt < 8; nt++)
                #pragma unroll
                for (int e = 0; e < 4; e++) {
                    int r = q0 + rloc + ((e >> 1) << 3);
                    int c = k0 + nt * 8 + 2 * (l & 3) + (e & 1);
                    if (c > r) sacc[nt][e] = -1e30f;
                }
        }

        // online softmax (2 rows per thread)
        #pragma unroll
        for (int i = 0; i < 2; i++) {
            float tm = -1e30f;
            #pragma unroll
            for (int nt = 0; nt < 8; nt++)
                tm = fmaxf(tm, fmaxf(sacc[nt][2 * i], sacc[nt][2 * i + 1]));
            tm = fmaxf(tm, __shfl_xor_sync(0xffffffffu, tm, 1));
            tm = fmaxf(tm, __shfl_xor_sync(0xffffffffu, tm, 2));
            float mn = fmaxf(m2[i], tm);
            float alpha = __expf(m2[i] - mn);
            m2[i] = mn;
            float ls = 0.0f;
            #pragma unroll
            for (int nt = 0; nt < 8; nt++) {
                float p0 = __expf(sacc[nt][2 * i] - mn);
                float p1 = __expf(sacc[nt][2 * i + 1] - mn);
                sacc[nt][2 * i] = p0;
                sacc[nt][2 * i + 1] = p1;
                ls += p0 + p1;
            }
            ls += __shfl_xor_sync(0xffffffffu, ls, 1);
            ls += __shfl_xor_sync(0xffffffffu, ls, 2);
            l2[i] = l2[i] * alpha + ls;
            #pragma unroll
            for (int nt = 0; nt < 8; nt++) {
                oacc[nt][2 * i] *= alpha;
                oacc[nt][2 * i + 1] *= alpha;
            }
        }

        // store P (fp16) into P[kt&1]
        {
            unsigned pc = (unsigned)(rloc & 7);
            unsigned prow = 40960u + (unsigned)(kt & 1) * 16384u +
                            (unsigned)rloc * 128u + (unsigned)((l & 3) * 4);
            #pragma unroll
            for (int nt = 0; nt < 8; nt++) {
                unsigned boff = prow + ((unsigned)nt ^ pc) * 16u;
                *(__half2*)(smc + boff) = __floats2half2_rn(sacc[nt][0], sacc[nt][1]);
                *(__half2*)(smc + boff + 1024u) = __floats2half2_rn(sacc[nt][2], sacc[nt][3]);
            }
        }
        __syncthreads();   // barrier 2: P visible; all warps done reading K(kt)

        if (kt + 1 < nk) {
            issueK(k0 + 64);
            loadV(k0 + 64);
        }

        // ---- O += P @ VT^T ----
        #pragma unroll
        for (int ks = 0; ks < 4; ks++) {
            unsigned phys = (unsigned)((2 * ks + sel) ^ l7) * 16u;
            unsigned a0, a1, a2, a3;
            ldsm_x4(a0, a1, a2, a3, uP + (unsigned)rA * 128u + phys);
            unsigned bf[4][4];
            #pragma unroll
            for (int np = 0; np < 4; np++)
                ldsm_x4(bf[np][0], bf[np][1], bf[np][2], bf[np][3],
                        uVT + (unsigned)(np * 16 + rowfrag) * 128u + phys);
            #pragma unroll
            for (int nt = 0; nt < 8; nt++)
                mma_f16(oacc[nt], a0, a1, a2, a3,
                        bf[nt >> 1][nt & 1], bf[nt >> 1][(nt & 1) + 2]);
        }
    }

    float inv0 = 1.0f / l2[0];
    float inv1 = 1.0f / l2[1];
    int r = q0 + rloc;
    int dcol = h * HSZ + 2 * (l & 3);
    #pragma unroll
    for (int nt = 0; nt < 8; nt++) {
        *(__half2*)&out[(size_t)(b * SS + r) * DD + dcol + nt * 8] =
            __floats2half2_rn(oacc[nt][0] * inv0, oacc[nt][1] * inv0);
        *(__half2*)&out[(size_t)(b * SS + r + 8) * DD + dcol + nt * 8] =
            __floats2half2_rn(oacc[nt][2] * inv1, oacc[nt][3] * inv1);
    }
}

// ---------------- launch ----------------
extern "C" void kernel_launch(void* const* d_in, const int* in_sizes, int n_in,
                              void* d_out, int out_size) {
    const float* x     = (const float*)d_in[0];
    const float* wq    = (const float*)d_in[1];
    const float* wk    = (const float*)d_in[2];
    const float* wv    = (const float*)d_in[3];
    const float* wproj = (const float*)d_in[4];
    const float* bproj = (const float*)d_in[5];
    const float* w1    = (const float*)d_in[6];
    const float* b1    = (const float*)d_in[7];
    const float* w2    = (const float*)d_in[8];
    const float* b2    = (const float*)d_in[9];
    const float* ln1_g = (const float*)d_in[10];
    const float* ln1_b = (const float*)d_in[11];
    const float* ln2_g = (const float*)d_in[12];
    const float* ln2_b = (const float*)d_in[13];
    float* out = (float*)d_out;

    __half *p_xn, *p_qkv, *p_attn, *p_hn, *p_ff;
    __half *p_wqkvT, *p_wprojT, *p_w1T, *p_w2T;
    float *p_h;
    cudaGetSymbolAddress((void**)&p_xn, g_xn);
    cudaGetSymbolAddress((void**)&p_qkv, g_qkv);
    cudaGetSymbolAddress((void**)&p_attn, g_attn);
    cudaGetSymbolAddress((void**)&p_h, g_h);
    cudaGetSymbolAddress((void**)&p_hn, g_hn);
    cudaGetSymbolAddress((void**)&p_ff, g_ff);
    cudaGetSymbolAddress((void**)&p_wqkvT, g_wqkvT);
    cudaGetSymbolAddress((void**)&p_wprojT, g_wprojT);
    cudaGetSymbolAddress((void**)&p_w1T, g_w1T);
    cudaGetSymbolAddress((void**)&p_w2T, g_w2T);

    cudaFuncSetAttribute(gemm_tc<0>, cudaFuncAttributeMaxDynamicSharedMemorySize, GEMM_SMEM);
    cudaFuncSetAttribute(gemm_tc<1>, cudaFuncAttributeMaxDynamicSharedMemorySize, GEMM_SMEM);
    cudaFuncSetAttribute(gemm_tc<2>, cudaFuncAttributeMaxDynamicSharedMemorySize, GEMM_SMEM);
    cudaFuncSetAttribute(attn_tc, cudaFuncAttributeMaxDynamicSharedMemorySize, ATT_SMEM);

    // prep (fp16 weight transposes + LN1)
    build_wqkvT_kernel<<<dim3(16, 16, 3), 256>>>(wq, wk, wv, p_wqkvT);
    transpose_kernel<<<dim3(DD / 32, DD / 32), dim3(32, 8)>>>(wproj, p_wprojT, DD, DD);
    transpose_kernel<<<dim3(DFF / 32, DD / 32), dim3(32, 8)>>>(w1, p_w1T, DD, DFF);
    transpose_kernel<<<dim3(DD / 32, DFF / 32), dim3(32, 8)>>>(w2, p_w2T, DFF, DD);
    ln_kernel<<<BS, 256>>>(x, ln1_g, ln1_b, p_xn);

    // QKV GEMM -> fp16 qkv
    gemm_tc<2><<<dim3(D3 / 128, BS / 128), 256, GEMM_SMEM>>>(
        p_xn, p_wqkvT, nullptr, nullptr, p_qkv, BS, D3, DD);

    // fp16 flash attention
    attn_tc<<<dim3(SS / 128, BB * HH), 256, ATT_SMEM>>>(p_qkv, p_attn);

    // proj + bias + residual(x) -> h (fp32)
    gemm_tc<0><<<dim3(DD / 128, BS / 128), 256, GEMM_SMEM>>>(
        p_attn, p_wprojT, bproj, x, p_h, BS, DD, DD);

    // LN2 -> fp16 hn
    ln_kernel<<<BS, 256>>>(p_h, ln2_g, ln2_b, p_hn);

    // FF1 + bias + relu -> fp16 ff
    gemm_tc<1><<<dim3(DFF / 128, BS / 128), 256, GEMM_SMEM>>>(
        p_hn, p_w1T, b1, nullptr, p_ff, BS, DFF, DD);

    // FF2 + bias + residual(h) -> out (fp32)
    gemm_tc<0><<<dim3(DD / 128, BS / 128), 256, GEMM_SMEM>>>(
        p_ff, p_w2T, b2, p_h, out, BS, DD, DFF);
}

// round 12
// speedup vs baseline: 1.7685x; 1.0327x over previous
#include <cuda_runtime.h>
#include <cuda_fp16.h>
#include <cstdint>

// Problem constants
#define BB 2
#define SS 2048
#define DD 1024
#define HH 16
#define HSZ 64
#define BS (BB * SS)        // 4096 rows
#define D3 (3 * DD)         // 3072
#define DFF (4 * DD)        // 4096

// ---------------- scratch (static device memory; no allocations) ----------------
__device__ __half g_xn[BS * DD];
__device__ __half g_qkv[BS * D3];
__device__ __half g_attn[BS * DD];
__device__ float  g_h[BS * DD];
__device__ __half g_hn[BS * DD];
__device__ __half g_ff[BS * DFF];
__device__ __half g_wqkvT[D3 * DD];
__device__ __half g_wprojT[DD * DD];
__device__ __half g_w1T[DFF * DD];
__device__ __half g_w2T[DD * DFF];

// pack two fp32 into one f16x2 register (rn rounding, == __floats2half2_rn)
__device__ __forceinline__ unsigned pack_h2(float lo, float hi) {
    unsigned r;
    asm("cvt.rn.f16x2.f32 %0, %1, %2;" : "=r"(r) : "f"(hi), "f"(lo));
    return r;
}

// ---------------- LayerNorm (fp32 in -> fp16 out) ----------------
__global__ void ln_kernel(const float* __restrict__ in, const float* __restrict__ gamma,
                          const float* __restrict__ beta, __half* __restrict__ out) {
    int row = blockIdx.x;
    int tid = threadIdx.x;
    float4 xv = ((const float4*)(in + (size_t)row * DD))[tid];

    __shared__ float red[256];
    red[tid] = xv.x + xv.y + xv.z + xv.w;
    __syncthreads();
    #pragma unroll
    for (int off = 128; off > 0; off >>= 1) {
        if (tid < off) red[tid] += red[tid + off];
        __syncthreads();
    }
    float mu = red[0] * (1.0f / DD);
    __syncthreads();

    float dx = xv.x - mu, dy = xv.y - mu, dz = xv.z - mu, dw = xv.w - mu;
    red[tid] = dx * dx + dy * dy + dz * dz + dw * dw;
    __syncthreads();
    #pragma unroll
    for (int off = 128; off > 0; off >>= 1) {
        if (tid < off) red[tid] += red[tid + off];
        __syncthreads();
    }
    float rstd = rsqrtf(red[0] * (1.0f / DD) + 1e-5f);

    float4 gv = ((const float4*)gamma)[tid];
    float4 bv = ((const float4*)beta)[tid];
    __half2 h0 = __floats2half2_rn(dx * rstd * gv.x + bv.x, dy * rstd * gv.y + bv.y);
    __half2 h1 = __floats2half2_rn(dz * rstd * gv.z + bv.z, dw * rstd * gv.w + bv.w);
    ((__half2*)(out + (size_t)row * DD))[tid * 2] = h0;
    ((__half2*)(out + (size_t)row * DD))[tid * 2 + 1] = h1;
}

// ---------------- build wqkvT [3072][1024] (fp16) ----------------
__global__ void build_wqkvT_kernel(const float* __restrict__ wq, const float* __restrict__ wk,
                                   const float* __restrict__ wv, __half* __restrict__ out) {
    __shared__ float sm[64][65];
    int dblk = blockIdx.x;
    int h = blockIdx.y;
    int part = blockIdx.z;
    const float* w = (part == 0) ? wq : (part == 1) ? wk : wv;
    int tid = threadIdx.x;
    int d0 = dblk * 64;

    int kk = tid & 63;
    int g4 = tid >> 6;
    #pragma unroll
    for (int i = 0; i < 16; i++) {
        int dl = g4 + i * 4;
        sm[dl][kk] = w[((size_t)(h * DD + d0 + dl)) * HSZ + kk];
    }
    __syncthreads();
    int dc = tid & 63;
    #pragma unroll
    for (int i = 0; i < 16; i++) {
        int kk2 = g4 + i * 4;
        out[(size_t)(part * DD + h * HSZ + kk2) * DD + d0 + dc] = __float2half_rn(sm[dc][kk2]);
    }
}

// ---------------- generic transpose: in[R][C] -> out[C][R] (fp16) ------
__global__ void transpose_kernel(const float* __restrict__ in, __half* __restrict__ out,
                                 int R, int C) {
    __shared__ float t[32][33];
    int x = blockIdx.x * 32 + threadIdx.x;
    int y = blockIdx.y * 32 + threadIdx.y;
    #pragma unroll
    for (int i = 0; i < 32; i += 8)
        t[threadIdx.y + i][threadIdx.x] = in[(size_t)(y + i) * C + x];
    __syncthreads();
    x = blockIdx.y * 32 + threadIdx.x;
    y = blockIdx.x * 32 + threadIdx.y;
    #pragma unroll
    for (int i = 0; i < 32; i += 8)
        out[(size_t)(y + i) * R + x] = __float2half_rn(t[threadIdx.x][threadIdx.y + i]);
}

// ---------------- tensor-core helpers -------------------------------
__device__ __forceinline__ void ldsm_x4(unsigned& r0, unsigned& r1, unsigned& r2, unsigned& r3,
                                        unsigned addr) {
    asm volatile("ldmatrix.sync.aligned.m8n8.x4.shared.b16 {%0,%1,%2,%3}, [%4];"
                 : "=r"(r0), "=r"(r1), "=r"(r2), "=r"(r3) : "r"(addr));
}

__device__ __forceinline__ void mma_f16(float c[4], unsigned a0, unsigned a1, unsigned a2,
                                        unsigned a3, unsigned b0, unsigned b1) {
    asm volatile(
        "mma.sync.aligned.m16n8k16.row.col.f32.f16.f16.f32 "
        "{%0,%1,%2,%3}, {%4,%5,%6,%7}, {%8,%9}, {%0,%1,%2,%3};"
        : "+f"(c[0]), "+f"(c[1]), "+f"(c[2]), "+f"(c[3])
        : "r"(a0), "r"(a1), "r"(a2), "r"(a3), "r"(b0), "r"(b1));
}

#define CPA16(dst, src) \
    asm volatile("cp.async.cg.shared.global [%0], [%1], 16;" :: "r"(dst), "l"(src))

// ---------------- fp16 GEMM: 128x128 tile, BK=64 halves, 256 thr, 3-stage ------
#define GEMM_SMEM (3 * 32768)

// MODE: 0 = fp32 out (+res), 1 = fp16 out + relu, 2 = fp16 out
template <int MODE>
__global__ __launch_bounds__(256, 2)
void gemm_tc(const __half* __restrict__ A, const __half* __restrict__ Bt,
             const float* __restrict__ bias, const float* __restrict__ res,
             void* __restrict__ Cv, int M, int N, int K) {
    extern __shared__ unsigned smem_u[];
    unsigned sbase = (unsigned)__cvta_generic_to_shared(smem_u);

    int tid = threadIdx.x;
    int l = tid & 31;
    int wid = tid >> 5;
    int warp_m = wid >> 2;   // 0..1
    int warp_n = wid & 3;    // 0..3
    int bx = blockIdx.x * 128;
    int by = blockIdx.y * 128;

    float acc[4][4][4];
    #pragma unroll
    for (int i = 0; i < 4; i++)
        #pragma unroll
        for (int j = 0; j < 4; j++)
            #pragma unroll
            for (int k = 0; k < 4; k++) acc[i][j][k] = 0.0f;

    int lm = tid >> 3;
    int kc = tid & 7;
    unsigned physc = (unsigned)(kc ^ (lm & 7));
    const __half* aptr = A + (size_t)(by + lm) * K + kc * 8;
    const __half* bptr = Bt + (size_t)(bx + lm) * K + kc * 8;

    int NT = K / 64;

    int rowfrag = (l & 7) + ((l >> 3) & 1) * 8;
    int sel = (l >> 4) & 1;
    int l7 = l & 7;
    int rA = warp_m * 64 + rowfrag;
    int rB = warp_n * 32 + rowfrag;

    auto issue = [&](int kt) {
        unsigned sA = sbase + (unsigned)(kt % 3) * 32768u;
        unsigned sB = sA + 16384u;
        const __half* ap = aptr + kt * 64;
        const __half* bp = bptr + kt * 64;
        #pragma unroll
        for (int i = 0; i < 4; i++) {
            unsigned off = ((unsigned)(lm + 32 * i) * 8 + physc) * 16;
            CPA16(sA + off, ap + (size_t)(32 * i) * K);
            CPA16(sB + off, bp + (size_t)(32 * i) * K);
        }
        asm volatile("cp.async.commit_group;");
    };

    issue(0);
    issue(1);

    #pragma unroll 1
    for (int kt = 0; kt < NT; kt++) {
        if (kt < NT - 1) {
            asm volatile("cp.async.wait_group 1;" ::: "memory");
        } else {
            asm volatile("cp.async.wait_group 0;" ::: "memory");
        }
        __syncthreads();

        if (kt + 2 < NT) issue(kt + 2);

        unsigned sA = sbase + (unsigned)(kt % 3) * 32768u;
        unsigned sB = sA + 16384u;

        #pragma unroll
        for (int ks = 0; ks < 4; ks++) {
            unsigned phys = (unsigned)((2 * ks + sel) ^ l7) * 16u;
            unsigned aBase = sA + (unsigned)rA * 128u + phys;
            unsigned bBase = sB + (unsigned)rB * 128u + phys;

            unsigned a[4][4], bf[2][4];
            #pragma unroll
            for (int mt = 0; mt < 4; mt++)
                ldsm_x4(a[mt][0], a[mt][1], a[mt][2], a[mt][3], aBase + mt * 2048u);
            #pragma unroll
            for (int np = 0; np < 2; np++)
                ldsm_x4(bf[np][0], bf[np][1], bf[np][2], bf[np][3], bBase + np * 2048u);

            #pragma unroll
            for (int mt = 0; mt < 4; mt++)
                #pragma unroll
                for (int nt = 0; nt < 4; nt++)
                    mma_f16(acc[mt][nt], a[mt][0], a[mt][1], a[mt][2], a[mt][3],
                            bf[nt >> 1][nt & 1], bf[nt >> 1][(nt & 1) + 2]);
        }
    }

    int g = l >> 2, tg = l & 3;
    #pragma unroll
    for (int mt = 0; mt < 4; mt++) {
        int r0 = by + warp_m * 64 + mt * 16 + g;
        #pragma unroll
        for (int nt = 0; nt < 4; nt++) {
            int col = bx + warp_n * 32 + nt * 8 + tg * 2;
            float2 v0 = make_float2(acc[mt][nt][0], acc[mt][nt][1]);
            float2 v1 = make_float2(acc[mt][nt][2], acc[mt][nt][3]);
            if (bias != nullptr) {
                float2 bv = *(const float2*)&bias[col];
                v0.x += bv.x; v0.y += bv.y; v1.x += bv.x; v1.y += bv.y;
            }
            if (MODE == 0) {
                if (res != nullptr) {
                    float2 q0 = *(const float2*)&res[(size_t)r0 * N + col];
                    float2 q1 = *(const float2*)&res[(size_t)(r0 + 8) * N + col];
                    v0.x += q0.x; v0.y += q0.y; v1.x += q1.x; v1.y += q1.y;
                }
                float* C = (float*)Cv;
                *(float2*)&C[(size_t)r0 * N + col] = v0;
                *(float2*)&C[(size_t)(r0 + 8) * N + col] = v1;
            } else {
                if (MODE == 1) {
                    v0.x = fmaxf(v0.x, 0.0f); v0.y = fmaxf(v0.y, 0.0f);
                    v1.x = fmaxf(v1.x, 0.0f); v1.y = fmaxf(v1.y, 0.0f);
                }
                __half* C = (__half*)Cv;
                *(__half2*)&C[(size_t)r0 * N + col] = __floats2half2_rn(v0.x, v0.y);
                *(__half2*)&C[(size_t)(r0 + 8) * N + col] = __floats2half2_rn(v1.x, v1.y);
            }
        }
    }
}

// ---------------- fp16 flash attention, register-resident P (FA2 style) --------
// 128-query tile, 8 warps x 16 rows; 64-key tiles; ONE barrier per tile.
// P never touches smem: S C-fragments are converted to fp16 in registers and
// reused directly as the A operand of the PV mma (C-layout == A-layout match).
// smem: Q[128][128B] @0 (16KB), K[2][64][128B] @16384 (8KB each),
//       VT[2][64][128B] @32768 (8KB each). total 48KB -> 2 CTAs/SM.
// Buffer recycling: buffer kt&1 of K/VT was last read in tile kt-2 (K by S-mma,
// VT by PV-mma), and every warp passed barrier kt-1 after those reads.
#define ATT_SMEM 49152

__global__ __launch_bounds__(256, 2)
void attn_tc(const __half* __restrict__ qkv, __half* __restrict__ out) {
    extern __shared__ char smc[];
    unsigned ub = (unsigned)__cvta_generic_to_shared(smc);
    unsigned uQ = ub;

    int tid = threadIdx.x;
    int l = tid & 31, w = tid >> 5;
    int b = blockIdx.y >> 4, h = blockIdx.y & 15;
    int q0 = ((int)gridDim.x - 1 - (int)blockIdx.x) * 128;
    int nk = q0 / 64 + 2;

    const __half* base = qkv + (size_t)b * SS * D3 + h * HSZ;

    int lr = tid >> 3, lc = tid & 7;
    unsigned lphys = (unsigned)(lc ^ (lr & 7)) * 16u;

    #pragma unroll
    for (int p = 0; p < 4; p++) {
        int row = lr + 32 * p;
        CPA16(uQ + (unsigned)row * 128u + lphys, base + (size_t)(q0 + row) * D3 + lc * 8);
    }
    auto issueK = [&](int kt) {
        unsigned uK = ub + 16384u + (unsigned)(kt & 1) * 8192u;
        int k0 = kt * 64;
        #pragma unroll
        for (int p = 0; p < 2; p++) {
            int row = lr + 32 * p;
            CPA16(uK + (unsigned)row * 128u + lphys,
                  base + (size_t)(k0 + row) * D3 + DD + lc * 8);
        }
        asm volatile("cp.async.commit_group;");
    };

    int vs2 = (tid & 31) * 2, vdg = tid >> 5;
    uint4 vr0, vr1;
    auto loadV = [&](int k0) {
        const __half* vp = base + (size_t)(k0 + vs2) * D3 + 2 * DD + vdg * 8;
        vr0 = *(const uint4*)vp;
        vr1 = *(const uint4*)(vp + D3);
    };
    issueK(0);   // group 0: Q + K(0)
    loadV(0);

    float m2[2] = {-1e30f, -1e30f};
    float l2[2] = {0.0f, 0.0f};
    float oacc[8][4];
    #pragma unroll
    for (int i = 0; i < 8; i++)
        #pragma unroll
        for (int j = 0; j < 4; j++) oacc[i][j] = 0.0f;

    int l7 = l & 7;
    int rowfrag = (l & 7) + ((l >> 3) & 1) * 8;
    int sel = (l >> 4) & 1;
    int rA = w * 16 + rowfrag;
    int rloc = w * 16 + (l >> 2);

    // ---- hoist Q fragments (Q smem dead afterwards) ----
    unsigned aq[4][4];
    asm volatile("cp.async.wait_group 0;" ::: "memory");
    __syncthreads();
    #pragma unroll
    for (int ks = 0; ks < 4; ks++) {
        unsigned phys = (unsigned)((2 * ks + sel) ^ l7) * 16u;
        ldsm_x4(aq[ks][0], aq[ks][1], aq[ks][2], aq[ks][3], uQ + (unsigned)rA * 128u + phys);
    }

    for (int kt = 0; kt < nk; kt++) {
        int k0 = kt * 64;
        unsigned uK  = ub + 16384u + (unsigned)(kt & 1) * 8192u;
        unsigned uVT = ub + 32768u + (unsigned)(kt & 1) * 8192u;

        // store V transposed into VT[kt&1] (buffer free: see header comment)
        {
            const __half* h0 = (const __half*)&vr0;
            const __half* h1 = (const __half*)&vr1;
            unsigned srow = (unsigned)(vs2 >> 3);
            unsigned scol = (unsigned)(vs2 & 7) * 2u;
            unsigned vtb = 32768u + (unsigned)(kt & 1) * 8192u;
            #pragma unroll
            for (int j = 0; j < 8; j++) {
                int d = vdg * 8 + j;
                unsigned phys = (srow ^ (unsigned)(d & 7)) * 16u;
                *(__half2*)(smc + vtb + (unsigned)d * 128u + phys + scol) =
                    __halves2half2(h0[j], h1[j]);
            }
        }
        asm volatile("cp.async.wait_group 0;" ::: "memory");
        __syncthreads();   // THE barrier: K(kt)+VT(kt) visible; prior-tile reads drained

        // prefetch next tile (K buffer (kt+1)&1 last read tile kt-1: drained)
        if (kt + 1 < nk) {
            issueK(kt + 1);
            loadV(k0 + 64);
        }

        // ---- S = Q K^T ----
        float sacc[8][4];
        #pragma unroll
        for (int i = 0; i < 8; i++)
            #pragma unroll
            for (int j = 0; j < 4; j++) sacc[i][j] = 0.0f;

        #pragma unroll
        for (int ks = 0; ks < 4; ks++) {
            unsigned phys = (unsigned)((2 * ks + sel) ^ l7) * 16u;
            unsigned bf[4][4];
            #pragma unroll
            for (int np = 0; np < 4; np++)
                ldsm_x4(bf[np][0], bf[np][1], bf[np][2], bf[np][3],
                        uK + (unsigned)(np * 16 + rowfrag) * 128u + phys);
            #pragma unroll
            for (int nt = 0; nt < 8; nt++)
                mma_f16(sacc[nt], aq[ks][0], aq[ks][1], aq[ks][2], aq[ks][3],
                        bf[nt >> 1][nt & 1], bf[nt >> 1][(nt & 1) + 2]);
        }

        #pragma unroll
        for (int nt = 0; nt < 8; nt++)
            #pragma unroll
            for (int e = 0; e < 4; e++) sacc[nt][e] *= 0.125f;
        if (kt >= nk - 2) {
            #pragma unroll
            for (int nt = 0; nt < 8; nt++)
                #pragma unroll
                for (int e = 0; e < 4; e++) {
                    int r = q0 + rloc + ((e >> 1) << 3);
                    int c = k0 + nt * 8 + 2 * (l & 3) + (e & 1);
                    if (c > r) sacc[nt][e] = -1e30f;
                }
        }

        // online softmax (2 rows per thread)
        #pragma unroll
        for (int i = 0; i < 2; i++) {
            float tm = -1e30f;
            #pragma unroll
            for (int nt = 0; nt < 8; nt++)
                tm = fmaxf(tm, fmaxf(sacc[nt][2 * i], sacc[nt][2 * i + 1]));
            tm = fmaxf(tm, __shfl_xor_sync(0xffffffffu, tm, 1));
            tm = fmaxf(tm, __shfl_xor_sync(0xffffffffu, tm, 2));
            float mn = fmaxf(m2[i], tm);
            float alpha = __expf(m2[i] - mn);
            m2[i] = mn;
            float ls = 0.0f;
            #pragma unroll
            for (int nt = 0; nt < 8; nt++) {
                float p0 = __expf(sacc[nt][2 * i] - mn);
                float p1 = __expf(sacc[nt][2 * i + 1] - mn);
                sacc[nt][2 * i] = p0;
                sacc[nt][2 * i + 1] = p1;
                ls += p0 + p1;
            }
            ls += __shfl_xor_sync(0xffffffffu, ls, 1);
            ls += __shfl_xor_sync(0xffffffffu, ls, 2);
            l2[i] = l2[i] * alpha + ls;
            #pragma unroll
            for (int nt = 0; nt < 8; nt++) {
                oacc[nt][2 * i] *= alpha;
                oacc[nt][2 * i + 1] *= alpha;
            }
        }

        // ---- convert P to fp16 A-fragments (in registers) ----
        // A-frag for k16-chunk ks: a0 = row r  k-lo  = sacc[2ks][0..1]
        //                          a1 = row r+8 k-lo = sacc[2ks][2..3]
        //                          a2 = row r  k-hi  = sacc[2ks+1][0..1]
        //                          a3 = row r+8 k-hi = sacc[2ks+1][2..3]
        unsigned pa[4][4];
        #pragma unroll
        for (int ks = 0; ks < 4; ks++) {
            pa[ks][0] = pack_h2(sacc[2 * ks][0], sacc[2 * ks][1]);
            pa[ks][1] = pack_h2(sacc[2 * ks][2], sacc[2 * ks][3]);
            pa[ks][2] = pack_h2(sacc[2 * ks + 1][0], sacc[2 * ks + 1][1]);
            pa[ks][3] = pack_h2(sacc[2 * ks + 1][2], sacc[2 * ks + 1][3]);
        }

        // ---- O += P @ VT^T  (A from registers, B = VT[d][s]) ----
        #pragma unroll
        for (int ks = 0; ks < 4; ks++) {
            unsigned phys = (unsigned)((2 * ks + sel) ^ l7) * 16u;
            unsigned bf[4][4];
            #pragma unroll
            for (int np = 0; np < 4; np++)
                ldsm_x4(bf[np][0], bf[np][1], bf[np][2], bf[np][3],
                        uVT + (unsigned)(np * 16 + rowfrag) * 128u + phys);
            #pragma unroll
            for (int nt = 0; nt < 8; nt++)
                mma_f16(oacc[nt], pa[ks][0], pa[ks][1], pa[ks][2], pa[ks][3],
                        bf[nt >> 1][nt & 1], bf[nt >> 1][(nt & 1) + 2]);
        }
    }

    float inv0 = 1.0f / l2[0];
    float inv1 = 1.0f / l2[1];
    int r = q0 + rloc;
    int dcol = h * HSZ + 2 * (l & 3);
    #pragma unroll
    for (int nt = 0; nt < 8; nt++) {
        *(__half2*)&out[(size_t)(b * SS + r) * DD + dcol + nt * 8] =
            __floats2half2_rn(oacc[nt][0] * inv0, oacc[nt][1] * inv0);
        *(__half2*)&out[(size_t)(b * SS + r + 8) * DD + dcol + nt * 8] =
            __floats2half2_rn(oacc[nt][2] * inv1, oacc[nt][3] * inv1);
    }
}

// ---------------- launch ----------------
extern "C" void kernel_launch(void* const* d_in, const int* in_sizes, int n_in,
                              void* d_out, int out_size) {
    const float* x     = (const float*)d_in[0];
    const float* wq    = (const float*)d_in[1];
    const float* wk    = (const float*)d_in[2];
    const float* wv    = (const float*)d_in[3];
    const float* wproj = (const float*)d_in[4];
    const float* bproj = (const float*)d_in[5];
    const float* w1    = (const float*)d_in[6];
    const float* b1    = (const float*)d_in[7];
    const float* w2    = (const float*)d_in[8];
    const float* b2    = (const float*)d_in[9];
    const float* ln1_g = (const float*)d_in[10];
    const float* ln1_b = (const float*)d_in[11];
    const float* ln2_g = (const float*)d_in[12];
    const float* ln2_b = (const float*)d_in[13];
    float* out = (float*)d_out;

    __half *p_xn, *p_qkv, *p_attn, *p_hn, *p_ff;
    __half *p_wqkvT, *p_wprojT, *p_w1T, *p_w2T;
    float *p_h;
    cudaGetSymbolAddress((void**)&p_xn, g_xn);
    cudaGetSymbolAddress((void**)&p_qkv, g_qkv);
    cudaGetSymbolAddress((void**)&p_attn, g_attn);
    cudaGetSymbolAddress((void**)&p_h, g_h);
    cudaGetSymbolAddress((void**)&p_hn, g_hn);
    cudaGetSymbolAddress((void**)&p_ff, g_ff);
    cudaGetSymbolAddress((void**)&p_wqkvT, g_wqkvT);
    cudaGetSymbolAddress((void**)&p_wprojT, g_wprojT);
    cudaGetSymbolAddress((void**)&p_w1T, g_w1T);
    cudaGetSymbolAddress((void**)&p_w2T, g_w2T);

    cudaFuncSetAttribute(gemm_tc<0>, cudaFuncAttributeMaxDynamicSharedMemorySize, GEMM_SMEM);
    cudaFuncSetAttribute(gemm_tc<1>, cudaFuncAttributeMaxDynamicSharedMemorySize, GEMM_SMEM);
    cudaFuncSetAttribute(gemm_tc<2>, cudaFuncAttributeMaxDynamicSharedMemorySize, GEMM_SMEM);
    cudaFuncSetAttribute(attn_tc, cudaFuncAttributeMaxDynamicSharedMemorySize, ATT_SMEM);

    // prep (fp16 weight transposes + LN1)
    build_wqkvT_kernel<<<dim3(16, 16, 3), 256>>>(wq, wk, wv, p_wqkvT);
    transpose_kernel<<<dim3(DD / 32, DD / 32), dim3(32, 8)>>>(wproj, p_wprojT, DD, DD);
    transpose_kernel<<<dim3(DFF / 32, DD / 32), dim3(32, 8)>>>(w1, p_w1T, DD, DFF);
    transpose_kernel<<<dim3(DD / 32, DFF / 32), dim3(32, 8)>>>(w2, p_w2T, DFF, DD);
    ln_kernel<<<BS, 256>>>(x, ln1_g, ln1_b, p_xn);

    // QKV GEMM -> fp16 qkv
    gemm_tc<2><<<dim3(D3 / 128, BS / 128), 256, GEMM_SMEM>>>(
        p_xn, p_wqkvT, nullptr, nullptr, p_qkv, BS, D3, DD);

    // fp16 flash attention (register-resident P)
    attn_tc<<<dim3(SS / 128, BB * HH), 256, ATT_SMEM>>>(p_qkv, p_attn);

    // proj + bias + residual(x) -> h (fp32)
    gemm_tc<0><<<dim3(DD / 128, BS / 128), 256, GEMM_SMEM>>>(
        p_attn, p_wprojT, bproj, x, p_h, BS, DD, DD);

    // LN2 -> fp16 hn
    ln_kernel<<<BS, 256>>>(p_h, ln2_g, ln2_b, p_hn);

    // FF1 + bias + relu -> fp16 ff
    gemm_tc<1><<<dim3(DFF / 128, BS / 128), 256, GEMM_SMEM>>>(
        p_hn, p_w1T, b1, nullptr, p_ff, BS, DFF, DD);

    // FF2 + bias + residual(h) -> out (fp32)
    gemm_tc<0><<<dim3(DD / 128, BS / 128), 256, GEMM_SMEM>>>(
        p_ff, p_w2T, b2, p_h, out, BS, DD, DFF);
}

// round 13
// speedup vs baseline: 1.7973x; 1.0163x over previous
#include <cuda_runtime.h>
#include <cuda_fp16.h>
#include <cstdint>

// Problem constants
#define BB 2
#define SS 2048
#define DD 1024
#define HH 16
#define HSZ 64
#define BS (BB * SS)        // 4096 rows
#define D3 (3 * DD)         // 3072
#define DFF (4 * DD)        // 4096

// ---------------- scratch (static device memory; no allocations) ----------------
__device__ __half g_xn[BS * DD];
__device__ __half g_qkv[BS * D3];
__device__ __half g_attn[BS * DD];
__device__ float  g_h[BS * DD];
__device__ __half g_hn[BS * DD];
__device__ __half g_ff[BS * DFF];
__device__ __half g_wqkvT[D3 * DD];
__device__ __half g_wprojT[DD * DD];
__device__ __half g_w1T[DFF * DD];
__device__ __half g_w2T[DD * DFF];

// pack two fp32 into one f16x2 register (rn rounding)
__device__ __forceinline__ unsigned pack_h2(float lo, float hi) {
    unsigned r;
    asm("cvt.rn.f16x2.f32 %0, %1, %2;" : "=r"(r) : "f"(hi), "f"(lo));
    return r;
}

// bare exp2 (single MUFU.EX2)
__device__ __forceinline__ float ex2(float x) {
    float r;
    asm("ex2.approx.f32 %0, %1;" : "=f"(r) : "f"(x));
    return r;
}

// ---------------- LayerNorm (fp32 in -> fp16 out), single-pass, 2 barriers -----
__global__ void ln_kernel(const float* __restrict__ in, const float* __restrict__ gamma,
                          const float* __restrict__ beta, __half* __restrict__ out) {
    int row = blockIdx.x;
    int tid = threadIdx.x;
    int lane = tid & 31, wid = tid >> 5;
    float4 xv = ((const float4*)(in + (size_t)row * DD))[tid];

    float s = xv.x + xv.y + xv.z + xv.w;
    float s2 = xv.x * xv.x + xv.y * xv.y + xv.z * xv.z + xv.w * xv.w;
    #pragma unroll
    for (int o = 16; o; o >>= 1) {
        s += __shfl_xor_sync(0xffffffffu, s, o);
        s2 += __shfl_xor_sync(0xffffffffu, s2, o);
    }

    __shared__ float red[16];
    __shared__ float stat[2];
    if (lane == 0) { red[wid] = s; red[8 + wid] = s2; }
    __syncthreads();
    if (tid < 32) {
        float a = (lane < 8) ? red[lane] : 0.0f;
        float b = (lane < 8) ? red[8 + lane] : 0.0f;
        #pragma unroll
        for (int o = 4; o; o >>= 1) {
            a += __shfl_xor_sync(0xffffffffu, a, o);
            b += __shfl_xor_sync(0xffffffffu, b, o);
        }
        if (lane == 0) {
            float mu = a * (1.0f / DD);
            float var = b * (1.0f / DD) - mu * mu;
            stat[0] = mu;
            stat[1] = rsqrtf(var + 1e-5f);
        }
    }
    __syncthreads();
    float mu = stat[0], rstd = stat[1];

    float4 gv = ((const float4*)gamma)[tid];
    float4 bv = ((const float4*)beta)[tid];
    __half2 h0 = __floats2half2_rn((xv.x - mu) * rstd * gv.x + bv.x,
                                   (xv.y - mu) * rstd * gv.y + bv.y);
    __half2 h1 = __floats2half2_rn((xv.z - mu) * rstd * gv.z + bv.z,
                                   (xv.w - mu) * rstd * gv.w + bv.w);
    ((__half2*)(out + (size_t)row * DD))[tid * 2] = h0;
    ((__half2*)(out + (size_t)row * DD))[tid * 2 + 1] = h1;
}

// ---------------- build wqkvT [3072][1024] (fp16) ----------------
__global__ void build_wqkvT_kernel(const float* __restrict__ wq, const float* __restrict__ wk,
                                   const float* __restrict__ wv, __half* __restrict__ out) {
    __shared__ float sm[64][65];
    int dblk = blockIdx.x;
    int h = blockIdx.y;
    int part = blockIdx.z;
    const float* w = (part == 0) ? wq : (part == 1) ? wk : wv;
    int tid = threadIdx.x;
    int d0 = dblk * 64;

    int kk = tid & 63;
    int g4 = tid >> 6;
    #pragma unroll
    for (int i = 0; i < 16; i++) {
        int dl = g4 + i * 4;
        sm[dl][kk] = w[((size_t)(h * DD + d0 + dl)) * HSZ + kk];
    }
    __syncthreads();
    int dc = tid & 63;
    #pragma unroll
    for (int i = 0; i < 16; i++) {
        int kk2 = g4 + i * 4;
        out[(size_t)(part * DD + h * HSZ + kk2) * DD + d0 + dc] = __float2half_rn(sm[dc][kk2]);
    }
}

// ---------------- generic transpose: in[R][C] -> out[C][R] (fp16) ------
__global__ void transpose_kernel(const float* __restrict__ in, __half* __restrict__ out,
                                 int R, int C) {
    __shared__ float t[32][33];
    int x = blockIdx.x * 32 + threadIdx.x;
    int y = blockIdx.y * 32 + threadIdx.y;
    #pragma unroll
    for (int i = 0; i < 32; i += 8)
        t[threadIdx.y + i][threadIdx.x] = in[(size_t)(y + i) * C + x];
    __syncthreads();
    x = blockIdx.y * 32 + threadIdx.x;
    y = blockIdx.x * 32 + threadIdx.y;
    #pragma unroll
    for (int i = 0; i < 32; i += 8)
        out[(size_t)(y + i) * R + x] = __float2half_rn(t[threadIdx.x][threadIdx.y + i]);
}

// ---------------- tensor-core helpers -------------------------------
__device__ __forceinline__ void ldsm_x4(unsigned& r0, unsigned& r1, unsigned& r2, unsigned& r3,
                                        unsigned addr) {
    asm volatile("ldmatrix.sync.aligned.m8n8.x4.shared.b16 {%0,%1,%2,%3}, [%4];"
                 : "=r"(r0), "=r"(r1), "=r"(r2), "=r"(r3) : "r"(addr));
}

__device__ __forceinline__ void mma_f16(float c[4], unsigned a0, unsigned a1, unsigned a2,
                                        unsigned a3, unsigned b0, unsigned b1) {
    asm volatile(
        "mma.sync.aligned.m16n8k16.row.col.f32.f16.f16.f32 "
        "{%0,%1,%2,%3}, {%4,%5,%6,%7}, {%8,%9}, {%0,%1,%2,%3};"
        : "+f"(c[0]), "+f"(c[1]), "+f"(c[2]), "+f"(c[3])
        : "r"(a0), "r"(a1), "r"(a2), "r"(a3), "r"(b0), "r"(b1));
}

#define CPA16(dst, src) \
    asm volatile("cp.async.cg.shared.global [%0], [%1], 16;" :: "r"(dst), "l"(src))

// ---------------- fp16 GEMM: 128x128 tile, BK=64 halves, 256 thr, 3-stage ------
#define GEMM_SMEM (3 * 32768)

// MODE: 0 = fp32 out (+res), 1 = fp16 out + relu, 2 = fp16 out
template <int MODE>
__global__ __launch_bounds__(256, 2)
void gemm_tc(const __half* __restrict__ A, const __half* __restrict__ Bt,
             const float* __restrict__ bias, const float* __restrict__ res,
             void* __restrict__ Cv, int M, int N, int K) {
    extern __shared__ unsigned smem_u[];
    unsigned sbase = (unsigned)__cvta_generic_to_shared(smem_u);

    int tid = threadIdx.x;
    int l = tid & 31;
    int wid = tid >> 5;
    int warp_m = wid >> 2;   // 0..1
    int warp_n = wid & 3;    // 0..3
    int bx = blockIdx.x * 128;
    int by = blockIdx.y * 128;

    float acc[4][4][4];
    #pragma unroll
    for (int i = 0; i < 4; i++)
        #pragma unroll
        for (int j = 0; j < 4; j++)
            #pragma unroll
            for (int k = 0; k < 4; k++) acc[i][j][k] = 0.0f;

    int lm = tid >> 3;
    int kc = tid & 7;
    unsigned physc = (unsigned)(kc ^ (lm & 7));
    const __half* aptr = A + (size_t)(by + lm) * K + kc * 8;
    const __half* bptr = Bt + (size_t)(bx + lm) * K + kc * 8;

    int NT = K / 64;

    int rowfrag = (l & 7) + ((l >> 3) & 1) * 8;
    int sel = (l >> 4) & 1;
    int l7 = l & 7;
    int rA = warp_m * 64 + rowfrag;
    int rB = warp_n * 32 + rowfrag;

    auto issue = [&](int kt) {
        unsigned sA = sbase + (unsigned)(kt % 3) * 32768u;
        unsigned sB = sA + 16384u;
        const __half* ap = aptr + kt * 64;
        const __half* bp = bptr + kt * 64;
        #pragma unroll
        for (int i = 0; i < 4; i++) {
            unsigned off = ((unsigned)(lm + 32 * i) * 8 + physc) * 16;
            CPA16(sA + off, ap + (size_t)(32 * i) * K);
            CPA16(sB + off, bp + (size_t)(32 * i) * K);
        }
        asm volatile("cp.async.commit_group;");
    };

    issue(0);
    issue(1);

    #pragma unroll 1
    for (int kt = 0; kt < NT; kt++) {
        if (kt < NT - 1) {
            asm volatile("cp.async.wait_group 1;" ::: "memory");
        } else {
            asm volatile("cp.async.wait_group 0;" ::: "memory");
        }
        __syncthreads();

        if (kt + 2 < NT) issue(kt + 2);

        unsigned sA = sbase + (unsigned)(kt % 3) * 32768u;
        unsigned sB = sA + 16384u;

        #pragma unroll
        for (int ks = 0; ks < 4; ks++) {
            unsigned phys = (unsigned)((2 * ks + sel) ^ l7) * 16u;
            unsigned aBase = sA + (unsigned)rA * 128u + phys;
            unsigned bBase = sB + (unsigned)rB * 128u + phys;

            unsigned a[4][4], bf[2][4];
            #pragma unroll
            for (int mt = 0; mt < 4; mt++)
                ldsm_x4(a[mt][0], a[mt][1], a[mt][2], a[mt][3], aBase + mt * 2048u);
            #pragma unroll
            for (int np = 0; np < 2; np++)
                ldsm_x4(bf[np][0], bf[np][1], bf[np][2], bf[np][3], bBase + np * 2048u);

            #pragma unroll
            for (int mt = 0; mt < 4; mt++)
                #pragma unroll
                for (int nt = 0; nt < 4; nt++)
                    mma_f16(acc[mt][nt], a[mt][0], a[mt][1], a[mt][2], a[mt][3],
                            bf[nt >> 1][nt & 1], bf[nt >> 1][(nt & 1) + 2]);
        }
    }

    int g = l >> 2, tg = l & 3;
    #pragma unroll
    for (int mt = 0; mt < 4; mt++) {
        int r0 = by + warp_m * 64 + mt * 16 + g;
        #pragma unroll
        for (int nt = 0; nt < 4; nt++) {
            int col = bx + warp_n * 32 + nt * 8 + tg * 2;
            float2 v0 = make_float2(acc[mt][nt][0], acc[mt][nt][1]);
            float2 v1 = make_float2(acc[mt][nt][2], acc[mt][nt][3]);
            if (bias != nullptr) {
                float2 bv = *(const float2*)&bias[col];
                v0.x += bv.x; v0.y += bv.y; v1.x += bv.x; v1.y += bv.y;
            }
            if (MODE == 0) {
                if (res != nullptr) {
                    float2 q0 = *(const float2*)&res[(size_t)r0 * N + col];
                    float2 q1 = *(const float2*)&res[(size_t)(r0 + 8) * N + col];
                    v0.x += q0.x; v0.y += q0.y; v1.x += q1.x; v1.y += q1.y;
                }
                float* C = (float*)Cv;
                *(float2*)&C[(size_t)r0 * N + col] = v0;
                *(float2*)&C[(size_t)(r0 + 8) * N + col] = v1;
            } else {
                if (MODE == 1) {
                    v0.x = fmaxf(v0.x, 0.0f); v0.y = fmaxf(v0.y, 0.0f);
                    v1.x = fmaxf(v1.x, 0.0f); v1.y = fmaxf(v1.y, 0.0f);
                }
                __half* C = (__half*)Cv;
                *(__half2*)&C[(size_t)r0 * N + col] = __floats2half2_rn(v0.x, v0.y);
                *(__half2*)&C[(size_t)(r0 + 8) * N + col] = __floats2half2_rn(v1.x, v1.y);
            }
        }
    }
}

// ---------------- fp16 flash attention, register P, exp2 softmax ---------------
// 128-query tile, 8 warps x 16 rows; 64-key tiles; ONE barrier per tile.
// smem: Q[128][128B] @0 (16KB), K[2][64][128B] @16384 (8KB each),
//       VT[2][64][128B] @32768 (8KB each). total 48KB -> 2 CTAs/SM.
#define ATT_SMEM 49152

__global__ __launch_bounds__(256, 2)
void attn_tc(const __half* __restrict__ qkv, __half* __restrict__ out) {
    extern __shared__ char smc[];
    unsigned ub = (unsigned)__cvta_generic_to_shared(smc);
    unsigned uQ = ub;

    int tid = threadIdx.x;
    int l = tid & 31, w = tid >> 5;
    int b = blockIdx.y >> 4, h = blockIdx.y & 15;
    int q0 = ((int)gridDim.x - 1 - (int)blockIdx.x) * 128;
    int nk = q0 / 64 + 2;

    const __half* base = qkv + (size_t)b * SS * D3 + h * HSZ;

    int lr = tid >> 3, lc = tid & 7;
    unsigned lphys = (unsigned)(lc ^ (lr & 7)) * 16u;

    #pragma unroll
    for (int p = 0; p < 4; p++) {
        int row = lr + 32 * p;
        CPA16(uQ + (unsigned)row * 128u + lphys, base + (size_t)(q0 + row) * D3 + lc * 8);
    }
    auto issueK = [&](int kt) {
        unsigned uK = ub + 16384u + (unsigned)(kt & 1) * 8192u;
        int k0 = kt * 64;
        #pragma unroll
        for (int p = 0; p < 2; p++) {
            int row = lr + 32 * p;
            CPA16(uK + (unsigned)row * 128u + lphys,
                  base + (size_t)(k0 + row) * D3 + DD + lc * 8);
        }
        asm volatile("cp.async.commit_group;");
    };

    int vs2 = (tid & 31) * 2, vdg = tid >> 5;
    uint4 vr0, vr1;
    auto loadV = [&](int k0) {
        const __half* vp = base + (size_t)(k0 + vs2) * D3 + 2 * DD + vdg * 8;
        vr0 = *(const uint4*)vp;
        vr1 = *(const uint4*)(vp + D3);
    };
    issueK(0);   // group 0: Q + K(0)
    loadV(0);

    float m2[2] = {-1e30f, -1e30f};
    float l2[2] = {0.0f, 0.0f};
    float oacc[8][4];
    #pragma unroll
    for (int i = 0; i < 8; i++)
        #pragma unroll
        for (int j = 0; j < 4; j++) oacc[i][j] = 0.0f;

    int l7 = l & 7;
    int rowfrag = (l & 7) + ((l >> 3) & 1) * 8;
    int sel = (l >> 4) & 1;
    int rA = w * 16 + rowfrag;
    int rloc = w * 16 + (l >> 2);

    // scale folded with log2e: softmax computed in exp2 domain
    const float sc2 = 0.125f * 1.4426950408889634f;

    // ---- hoist Q fragments (Q smem dead afterwards) ----
    unsigned aq[4][4];
    asm volatile("cp.async.wait_group 0;" ::: "memory");
    __syncthreads();
    #pragma unroll
    for (int ks = 0; ks < 4; ks++) {
        unsigned phys = (unsigned)((2 * ks + sel) ^ l7) * 16u;
        ldsm_x4(aq[ks][0], aq[ks][1], aq[ks][2], aq[ks][3], uQ + (unsigned)rA * 128u + phys);
    }

    for (int kt = 0; kt < nk; kt++) {
        int k0 = kt * 64;
        unsigned uK  = ub + 16384u + (unsigned)(kt & 1) * 8192u;
        unsigned uVT = ub + 32768u + (unsigned)(kt & 1) * 8192u;

        // store V transposed into VT[kt&1]
        {
            const __half* h0 = (const __half*)&vr0;
            const __half* h1 = (const __half*)&vr1;
            unsigned srow = (unsigned)(vs2 >> 3);
            unsigned scol = (unsigned)(vs2 & 7) * 2u;
            unsigned vtb = 32768u + (unsigned)(kt & 1) * 8192u;
            #pragma unroll
            for (int j = 0; j < 8; j++) {
                int d = vdg * 8 + j;
                unsigned phys = (srow ^ (unsigned)(d & 7)) * 16u;
                *(__half2*)(smc + vtb + (unsigned)d * 128u + phys + scol) =
                    __halves2half2(h0[j], h1[j]);
            }
        }
        asm volatile("cp.async.wait_group 0;" ::: "memory");
        __syncthreads();   // K(kt)+VT(kt) visible; prior-tile reads drained

        if (kt + 1 < nk) {
            issueK(kt + 1);
            loadV(k0 + 64);
        }

        // ---- S = Q K^T ----
        float sacc[8][4];
        #pragma unroll
        for (int i = 0; i < 8; i++)
            #pragma unroll
            for (int j = 0; j < 4; j++) sacc[i][j] = 0.0f;

        #pragma unroll
        for (int ks = 0; ks < 4; ks++) {
            unsigned phys = (unsigned)((2 * ks + sel) ^ l7) * 16u;
            unsigned bf[4][4];
            #pragma unroll
            for (int np = 0; np < 4; np++)
                ldsm_x4(bf[np][0], bf[np][1], bf[np][2], bf[np][3],
                        uK + (unsigned)(np * 16 + rowfrag) * 128u + phys);
            #pragma unroll
            for (int nt = 0; nt < 8; nt++)
                mma_f16(sacc[nt], aq[ks][0], aq[ks][1], aq[ks][2], aq[ks][3],
                        bf[nt >> 1][nt & 1], bf[nt >> 1][(nt & 1) + 2]);
        }

        #pragma unroll
        for (int nt = 0; nt < 8; nt++)
            #pragma unroll
            for (int e = 0; e < 4; e++) sacc[nt][e] *= sc2;
        if (kt >= nk - 2) {
            #pragma unroll
            for (int nt = 0; nt < 8; nt++)
                #pragma unroll
                for (int e = 0; e < 4; e++) {
                    int r = q0 + rloc + ((e >> 1) << 3);
                    int c = k0 + nt * 8 + 2 * (l & 3) + (e & 1);
                    if (c > r) sacc[nt][e] = -1e30f;
                }
        }

        // online softmax (exp2 domain; 2 rows per thread)
        #pragma unroll
        for (int i = 0; i < 2; i++) {
            float tm = -1e30f;
            #pragma unroll
            for (int nt = 0; nt < 8; nt++)
                tm = fmaxf(tm, fmaxf(sacc[nt][2 * i], sacc[nt][2 * i + 1]));
            tm = fmaxf(tm, __shfl_xor_sync(0xffffffffu, tm, 1));
            tm = fmaxf(tm, __shfl_xor_sync(0xffffffffu, tm, 2));
            float mn = fmaxf(m2[i], tm);
            float alpha = ex2(m2[i] - mn);
            m2[i] = mn;
            float ls = 0.0f;
            #pragma unroll
            for (int nt = 0; nt < 8; nt++) {
                float p0 = ex2(sacc[nt][2 * i] - mn);
                float p1 = ex2(sacc[nt][2 * i + 1] - mn);
                sacc[nt][2 * i] = p0;
                sacc[nt][2 * i + 1] = p1;
                ls += p0 + p1;
            }
            ls += __shfl_xor_sync(0xffffffffu, ls, 1);
            ls += __shfl_xor_sync(0xffffffffu, ls, 2);
            l2[i] = l2[i] * alpha + ls;
            #pragma unroll
            for (int nt = 0; nt < 8; nt++) {
                oacc[nt][2 * i] *= alpha;
                oacc[nt][2 * i + 1] *= alpha;
            }
        }

        // ---- convert P to fp16 A-fragments (in registers) ----
        unsigned pa[4][4];
        #pragma unroll
        for (int ks = 0; ks < 4; ks++) {
            pa[ks][0] = pack_h2(sacc[2 * ks][0], sacc[2 * ks][1]);
            pa[ks][1] = pack_h2(sacc[2 * ks][2], sacc[2 * ks][3]);
            pa[ks][2] = pack_h2(sacc[2 * ks + 1][0], sacc[2 * ks + 1][1]);
            pa[ks][3] = pack_h2(sacc[2 * ks + 1][2], sacc[2 * ks + 1][3]);
        }

        // ---- O += P @ VT^T ----
        #pragma unroll
        for (int ks = 0; ks < 4; ks++) {
            unsigned phys = (unsigned)((2 * ks + sel) ^ l7) * 16u;
            unsigned bf[4][4];
            #pragma unroll
            for (int np = 0; np < 4; np++)
                ldsm_x4(bf[np][0], bf[np][1], bf[np][2], bf[np][3],
                        uVT + (unsigned)(np * 16 + rowfrag) * 128u + phys);
            #pragma unroll
            for (int nt = 0; nt < 8; nt++)
                mma_f16(oacc[nt], pa[ks][0], pa[ks][1], pa[ks][2], pa[ks][3],
                        bf[nt >> 1][nt & 1], bf[nt >> 1][(nt & 1) + 2]);
        }
    }

    float inv0 = 1.0f / l2[0];
    float inv1 = 1.0f / l2[1];
    int r = q0 + rloc;
    int dcol = h * HSZ + 2 * (l & 3);
    #pragma unroll
    for (int nt = 0; nt < 8; nt++) {
        *(__half2*)&out[(size_t)(b * SS + r) * DD + dcol + nt * 8] =
            __floats2half2_rn(oacc[nt][0] * inv0, oacc[nt][1] * inv0);
        *(__half2*)&out[(size_t)(b * SS + r + 8) * DD + dcol + nt * 8] =
            __floats2half2_rn(oacc[nt][2] * inv1, oacc[nt][3] * inv1);
    }
}

// ---------------- launch ----------------
extern "C" void kernel_launch(void* const* d_in, const int* in_sizes, int n_in,
                              void* d_out, int out_size) {
    const float* x     = (const float*)d_in[0];
    const float* wq    = (const float*)d_in[1];
    const float* wk    = (const float*)d_in[2];
    const float* wv    = (const float*)d_in[3];
    const float* wproj = (const float*)d_in[4];
    const float* bproj = (const float*)d_in[5];
    const float* w1    = (const float*)d_in[6];
    const float* b1    = (const float*)d_in[7];
    const float* w2    = (const float*)d_in[8];
    const float* b2    = (const float*)d_in[9];
    const float* ln1_g = (const float*)d_in[10];
    const float* ln1_b = (const float*)d_in[11];
    const float* ln2_g = (const float*)d_in[12];
    const float* ln2_b = (const float*)d_in[13];
    float* out = (float*)d_out;

    __half *p_xn, *p_qkv, *p_attn, *p_hn, *p_ff;
    __half *p_wqkvT, *p_wprojT, *p_w1T, *p_w2T;
    float *p_h;
    cudaGetSymbolAddress((void**)&p_xn, g_xn);
    cudaGetSymbolAddress((void**)&p_qkv, g_qkv);
    cudaGetSymbolAddress((void**)&p_attn, g_attn);
    cudaGetSymbolAddress((void**)&p_h, g_h);
    cudaGetSymbolAddress((void**)&p_hn, g_hn);
    cudaGetSymbolAddress((void**)&p_ff, g_ff);
    cudaGetSymbolAddress((void**)&p_wqkvT, g_wqkvT);
    cudaGetSymbolAddress((void**)&p_wprojT, g_wprojT);
    cudaGetSymbolAddress((void**)&p_w1T, g_w1T);
    cudaGetSymbolAddress((void**)&p_w2T, g_w2T);

    cudaFuncSetAttribute(gemm_tc<0>, cudaFuncAttributeMaxDynamicSharedMemorySize, GEMM_SMEM);
    cudaFuncSetAttribute(gemm_tc<1>, cudaFuncAttributeMaxDynamicSharedMemorySize, GEMM_SMEM);
    cudaFuncSetAttribute(gemm_tc<2>, cudaFuncAttributeMaxDynamicSharedMemorySize, GEMM_SMEM);
    cudaFuncSetAttribute(attn_tc, cudaFuncAttributeMaxDynamicSharedMemorySize, ATT_SMEM);

    // prep (fp16 weight transposes + LN1)
    build_wqkvT_kernel<<<dim3(16, 16, 3), 256>>>(wq, wk, wv, p_wqkvT);
    transpose_kernel<<<dim3(DD / 32, DD / 32), dim3(32, 8)>>>(wproj, p_wprojT, DD, DD);
    transpose_kernel<<<dim3(DFF / 32, DD / 32), dim3(32, 8)>>>(w1, p_w1T, DD, DFF);
    transpose_kernel<<<dim3(DD / 32, DFF / 32), dim3(32, 8)>>>(w2, p_w2T, DFF, DD);
    ln_kernel<<<BS, 256>>>(x, ln1_g, ln1_b, p_xn);

    // QKV GEMM -> fp16 qkv
    gemm_tc<2><<<dim3(D3 / 128, BS / 128), 256, GEMM_SMEM>>>(
        p_xn, p_wqkvT, nullptr, nullptr, p_qkv, BS, D3, DD);

    // fp16 flash attention (register-resident P)
    attn_tc<<<dim3(SS / 128, BB * HH), 256, ATT_SMEM>>>(p_qkv, p_attn);

    // proj + bias + residual(x) -> h (fp32)
    gemm_tc<0><<<dim3(DD / 128, BS / 128), 256, GEMM_SMEM>>>(
        p_attn, p_wprojT, bproj, x, p_h, BS, DD, DD);

    // LN2 -> fp16 hn
    ln_kernel<<<BS, 256>>>(p_h, ln2_g, ln2_b, p_hn);

    // FF1 + bias + relu -> fp16 ff
    gemm_tc<1><<<dim3(DFF / 128, BS / 128), 256, GEMM_SMEM>>>(
        p_hn, p_w1T, b1, nullptr, p_ff, BS, DFF, DD);

    // FF2 + bias + residual(h) -> out (fp32)
    gemm_tc<0><<<dim3(DD / 128, BS / 128), 256, GEMM_SMEM>>>(
        p_ff, p_w2T, b2, p_h, out, BS, DD, DFF);
}

// round 14
// speedup vs baseline: 1.8248x; 1.0153x over previous
#include <cuda_runtime.h>
#include <cuda_fp16.h>
#include <cstdint>

// Problem constants
#define BB 2
#define SS 2048
#define DD 1024
#define HH 16
#define HSZ 64
#define BS (BB * SS)        // 4096 rows
#define D3 (3 * DD)         // 3072
#define DFF (4 * DD)        // 4096

// softmax scale folded with log2e, applied to q in the QKV GEMM epilogue
#define QSCALE 0.1803368801111721f   // 0.125 * log2(e)

// ---------------- scratch (static device memory; no allocations) ----------------
__device__ __half g_xn[BS * DD];
__device__ __half g_qkv[BS * D3];
__device__ __half g_attn[BS * DD];
__device__ float  g_h[BS * DD];
__device__ __half g_hn[BS * DD];
__device__ __half g_ff[BS * DFF];
__device__ __half g_wqkvT[D3 * DD];
__device__ __half g_wprojT[DD * DD];
__device__ __half g_w1T[DFF * DD];
__device__ __half g_w2T[DD * DFF];

// pack two fp32 into one f16x2 register (rn rounding)
__device__ __forceinline__ unsigned pack_h2(float lo, float hi) {
    unsigned r;
    asm("cvt.rn.f16x2.f32 %0, %1, %2;" : "=r"(r) : "f"(hi), "f"(lo));
    return r;
}

// bare exp2 (single MUFU.EX2)
__device__ __forceinline__ float ex2(float x) {
    float r;
    asm("ex2.approx.f32 %0, %1;" : "=f"(r) : "f"(x));
    return r;
}

// ---------------- LayerNorm (fp32 in -> fp16 out), single-pass, 2 barriers -----
__global__ void ln_kernel(const float* __restrict__ in, const float* __restrict__ gamma,
                          const float* __restrict__ beta, __half* __restrict__ out) {
    int row = blockIdx.x;
    int tid = threadIdx.x;
    int lane = tid & 31, wid = tid >> 5;
    float4 xv = ((const float4*)(in + (size_t)row * DD))[tid];

    float s = xv.x + xv.y + xv.z + xv.w;
    float s2 = xv.x * xv.x + xv.y * xv.y + xv.z * xv.z + xv.w * xv.w;
    #pragma unroll
    for (int o = 16; o; o >>= 1) {
        s += __shfl_xor_sync(0xffffffffu, s, o);
        s2 += __shfl_xor_sync(0xffffffffu, s2, o);
    }

    __shared__ float red[16];
    __shared__ float stat[2];
    if (lane == 0) { red[wid] = s; red[8 + wid] = s2; }
    __syncthreads();
    if (tid < 32) {
        float a = (lane < 8) ? red[lane] : 0.0f;
        float b = (lane < 8) ? red[8 + lane] : 0.0f;
        #pragma unroll
        for (int o = 4; o; o >>= 1) {
            a += __shfl_xor_sync(0xffffffffu, a, o);
            b += __shfl_xor_sync(0xffffffffu, b, o);
        }
        if (lane == 0) {
            float mu = a * (1.0f / DD);
            float var = b * (1.0f / DD) - mu * mu;
            stat[0] = mu;
            stat[1] = rsqrtf(var + 1e-5f);
        }
    }
    __syncthreads();
    float mu = stat[0], rstd = stat[1];

    float4 gv = ((const float4*)gamma)[tid];
    float4 bv = ((const float4*)beta)[tid];
    __half2 h0 = __floats2half2_rn((xv.x - mu) * rstd * gv.x + bv.x,
                                   (xv.y - mu) * rstd * gv.y + bv.y);
    __half2 h1 = __floats2half2_rn((xv.z - mu) * rstd * gv.z + bv.z,
                                   (xv.w - mu) * rstd * gv.w + bv.w);
    ((__half2*)(out + (size_t)row * DD))[tid * 2] = h0;
    ((__half2*)(out + (size_t)row * DD))[tid * 2 + 1] = h1;
}

// ---------------- build wqkvT [3072][1024] (fp16) ----------------
__global__ void build_wqkvT_kernel(const float* __restrict__ wq, const float* __restrict__ wk,
                                   const float* __restrict__ wv, __half* __restrict__ out) {
    __shared__ float sm[64][65];
    int dblk = blockIdx.x;
    int h = blockIdx.y;
    int part = blockIdx.z;
    const float* w = (part == 0) ? wq : (part == 1) ? wk : wv;
    int tid = threadIdx.x;
    int d0 = dblk * 64;

    int kk = tid & 63;
    int g4 = tid >> 6;
    #pragma unroll
    for (int i = 0; i < 16; i++) {
        int dl = g4 + i * 4;
        sm[dl][kk] = w[((size_t)(h * DD + d0 + dl)) * HSZ + kk];
    }
    __syncthreads();
    int dc = tid & 63;
    #pragma unroll
    for (int i = 0; i < 16; i++) {
        int kk2 = g4 + i * 4;
        out[(size_t)(part * DD + h * HSZ + kk2) * DD + d0 + dc] = __float2half_rn(sm[dc][kk2]);
    }
}

// ---------------- fused transpose of wproj/w1/w2 (fp32 -> fp16, out[C][R]) -----
// linear tile id: [0,1024) wproj (32x32), [1024,5120) w1 (128x32),
//                 [5120,9216) w2 (32x128)
__global__ void transpose3_kernel(const float* __restrict__ wproj, __half* __restrict__ wprojT,
                                  const float* __restrict__ w1, __half* __restrict__ w1T,
                                  const float* __restrict__ w2, __half* __restrict__ w2T) {
    __shared__ float t[32][33];
    int id = blockIdx.x;
    const float* in;
    __half* out;
    int bx, by, R, C;
    if (id < 1024) {
        in = wproj; out = wprojT; R = DD; C = DD;
        bx = id & 31; by = id >> 5;
    } else if (id < 5120) {
        int tgt = id - 1024;
        in = w1; out = w1T; R = DD; C = DFF;
        bx = tgt & 127; by = tgt >> 7;
    } else {
        int tgt = id - 5120;
        in = w2; out = w2T; R = DFF; C = DD;
        bx = tgt & 31; by = tgt >> 5;
    }

    int x = bx * 32 + threadIdx.x;
    int y = by * 32 + threadIdx.y;
    #pragma unroll
    for (int i = 0; i < 32; i += 8)
        t[threadIdx.y + i][threadIdx.x] = in[(size_t)(y + i) * C + x];
    __syncthreads();
    x = by * 32 + threadIdx.x;
    y = bx * 32 + threadIdx.y;
    #pragma unroll
    for (int i = 0; i < 32; i += 8)
        out[(size_t)(y + i) * R + x] = __float2half_rn(t[threadIdx.x][threadIdx.y + i]);
}

// ---------------- tensor-core helpers -------------------------------
__device__ __forceinline__ void ldsm_x4(unsigned& r0, unsigned& r1, unsigned& r2, unsigned& r3,
                                        unsigned addr) {
    asm volatile("ldmatrix.sync.aligned.m8n8.x4.shared.b16 {%0,%1,%2,%3}, [%4];"
                 : "=r"(r0), "=r"(r1), "=r"(r2), "=r"(r3) : "r"(addr));
}

__device__ __forceinline__ void mma_f16(float c[4], unsigned a0, unsigned a1, unsigned a2,
                                        unsigned a3, unsigned b0, unsigned b1) {
    asm volatile(
        "mma.sync.aligned.m16n8k16.row.col.f32.f16.f16.f32 "
        "{%0,%1,%2,%3}, {%4,%5,%6,%7}, {%8,%9}, {%0,%1,%2,%3};"
        : "+f"(c[0]), "+f"(c[1]), "+f"(c[2]), "+f"(c[3])
        : "r"(a0), "r"(a1), "r"(a2), "r"(a3), "r"(b0), "r"(b1));
}

#define CPA16(dst, src) \
    asm volatile("cp.async.cg.shared.global [%0], [%1], 16;" :: "r"(dst), "l"(src))

// ---------------- fp16 GEMM: 128x128 tile, BK=64 halves, 256 thr, 3-stage ------
#define GEMM_SMEM (3 * 32768)

// MODE: 0 = fp32 out (+res), 1 = fp16 out + relu,
//       2 = fp16 out with QSCALE applied to cols < DD (QKV gemm: scales q)
template <int MODE>
__global__ __launch_bounds__(256, 2)
void gemm_tc(const __half* __restrict__ A, const __half* __restrict__ Bt,
             const float* __restrict__ bias, const float* __restrict__ res,
             void* __restrict__ Cv, int M, int N, int K) {
    extern __shared__ unsigned smem_u[];
    unsigned sbase = (unsigned)__cvta_generic_to_shared(smem_u);

    int tid = threadIdx.x;
    int l = tid & 31;
    int wid = tid >> 5;
    int warp_m = wid >> 2;   // 0..1
    int warp_n = wid & 3;    // 0..3
    int bx = blockIdx.x * 128;
    int by = blockIdx.y * 128;

    float acc[4][4][4];
    #pragma unroll
    for (int i = 0; i < 4; i++)
        #pragma unroll
        for (int j = 0; j < 4; j++)
            #pragma unroll
            for (int k = 0; k < 4; k++) acc[i][j][k] = 0.0f;

    int lm = tid >> 3;
    int kc = tid & 7;
    unsigned physc = (unsigned)(kc ^ (lm & 7));
    const __half* aptr = A + (size_t)(by + lm) * K + kc * 8;
    const __half* bptr = Bt + (size_t)(bx + lm) * K + kc * 8;

    int NT = K / 64;

    int rowfrag = (l & 7) + ((l >> 3) & 1) * 8;
    int sel = (l >> 4) & 1;
    int l7 = l & 7;
    int rA = warp_m * 64 + rowfrag;
    int rB = warp_n * 32 + rowfrag;

    auto issue = [&](int kt) {
        unsigned sA = sbase + (unsigned)(kt % 3) * 32768u;
        unsigned sB = sA + 16384u;
        const __half* ap = aptr + kt * 64;
        const __half* bp = bptr + kt * 64;
        #pragma unroll
        for (int i = 0; i < 4; i++) {
            unsigned off = ((unsigned)(lm + 32 * i) * 8 + physc) * 16;
            CPA16(sA + off, ap + (size_t)(32 * i) * K);
            CPA16(sB + off, bp + (size_t)(32 * i) * K);
        }
        asm volatile("cp.async.commit_group;");
    };

    issue(0);
    issue(1);

    #pragma unroll 1
    for (int kt = 0; kt < NT; kt++) {
        if (kt < NT - 1) {
            asm volatile("cp.async.wait_group 1;" ::: "memory");
        } else {
            asm volatile("cp.async.wait_group 0;" ::: "memory");
        }
        __syncthreads();

        if (kt + 2 < NT) issue(kt + 2);

        unsigned sA = sbase + (unsigned)(kt % 3) * 32768u;
        unsigned sB = sA + 16384u;

        #pragma unroll
        for (int ks = 0; ks < 4; ks++) {
            unsigned phys = (unsigned)((2 * ks + sel) ^ l7) * 16u;
            unsigned aBase = sA + (unsigned)rA * 128u + phys;
            unsigned bBase = sB + (unsigned)rB * 128u + phys;

            unsigned a[4][4], bf[2][4];
            #pragma unroll
            for (int mt = 0; mt < 4; mt++)
                ldsm_x4(a[mt][0], a[mt][1], a[mt][2], a[mt][3], aBase + mt * 2048u);
            #pragma unroll
            for (int np = 0; np < 2; np++)
                ldsm_x4(bf[np][0], bf[np][1], bf[np][2], bf[np][3], bBase + np * 2048u);

            #pragma unroll
            for (int mt = 0; mt < 4; mt++)
                #pragma unroll
                for (int nt = 0; nt < 4; nt++)
                    mma_f16(acc[mt][nt], a[mt][0], a[mt][1], a[mt][2], a[mt][3],
                            bf[nt >> 1][nt & 1], bf[nt >> 1][(nt & 1) + 2]);
        }
    }

    int g = l >> 2, tg = l & 3;
    #pragma unroll
    for (int mt = 0; mt < 4; mt++) {
        int r0 = by + warp_m * 64 + mt * 16 + g;
        #pragma unroll
        for (int nt = 0; nt < 4; nt++) {
            int col = bx + warp_n * 32 + nt * 8 + tg * 2;
            float2 v0 = make_float2(acc[mt][nt][0], acc[mt][nt][1]);
            float2 v1 = make_float2(acc[mt][nt][2], acc[mt][nt][3]);
            if (bias != nullptr) {
                float2 bv = *(const float2*)&bias[col];
                v0.x += bv.x; v0.y += bv.y; v1.x += bv.x; v1.y += bv.y;
            }
            if (MODE == 0) {
                if (res != nullptr) {
                    float2 q0 = *(const float2*)&res[(size_t)r0 * N + col];
                    float2 q1 = *(const float2*)&res[(size_t)(r0 + 8) * N + col];
                    v0.x += q0.x; v0.y += q0.y; v1.x += q1.x; v1.y += q1.y;
                }
                float* C = (float*)Cv;
                *(float2*)&C[(size_t)r0 * N + col] = v0;
                *(float2*)&C[(size_t)(r0 + 8) * N + col] = v1;
            } else {
                if (MODE == 1) {
                    v0.x = fmaxf(v0.x, 0.0f); v0.y = fmaxf(v0.y, 0.0f);
                    v1.x = fmaxf(v1.x, 0.0f); v1.y = fmaxf(v1.y, 0.0f);
                }
                if (MODE == 2 && col < DD) {   // q columns: fold softmax scale
                    v0.x *= QSCALE; v0.y *= QSCALE;
                    v1.x *= QSCALE; v1.y *= QSCALE;
                }
                __half* C = (__half*)Cv;
                *(__half2*)&C[(size_t)r0 * N + col] = __floats2half2_rn(v0.x, v0.y);
                *(__half2*)&C[(size_t)(r0 + 8) * N + col] = __floats2half2_rn(v1.x, v1.y);
            }
        }
    }
}

// ---------------- fp16 flash attention, register P, exp2 softmax ---------------
// q pre-scaled by QSCALE at the QKV GEMM -> S lands in log2 domain directly.
// 128-query tile, 8 warps x 16 rows; 64-key tiles; ONE barrier per tile.
// smem: Q[128][128B] @0 (16KB), K[2][64][128B] @16384 (8KB each),
//       VT[2][64][128B] @32768 (8KB each). total 48KB -> 2 CTAs/SM.
#define ATT_SMEM 49152

__global__ __launch_bounds__(256, 2)
void attn_tc(const __half* __restrict__ qkv, __half* __restrict__ out) {
    extern __shared__ char smc[];
    unsigned ub = (unsigned)__cvta_generic_to_shared(smc);
    unsigned uQ = ub;

    int tid = threadIdx.x;
    int l = tid & 31, w = tid >> 5;
    int b = blockIdx.y >> 4, h = blockIdx.y & 15;
    int q0 = ((int)gridDim.x - 1 - (int)blockIdx.x) * 128;
    int nk = q0 / 64 + 2;

    const __half* base = qkv + (size_t)b * SS * D3 + h * HSZ;

    int lr = tid >> 3, lc = tid & 7;
    unsigned lphys = (unsigned)(lc ^ (lr & 7)) * 16u;

    #pragma unroll
    for (int p = 0; p < 4; p++) {
        int row = lr + 32 * p;
        CPA16(uQ + (unsigned)row * 128u + lphys, base + (size_t)(q0 + row) * D3 + lc * 8);
    }
    auto issueK = [&](int kt) {
        unsigned uK = ub + 16384u + (unsigned)(kt & 1) * 8192u;
        int k0 = kt * 64;
        #pragma unroll
        for (int p = 0; p < 2; p++) {
            int row = lr + 32 * p;
            CPA16(uK + (unsigned)row * 128u + lphys,
                  base + (size_t)(k0 + row) * D3 + DD + lc * 8);
        }
        asm volatile("cp.async.commit_group;");
    };

    int vs2 = (tid & 31) * 2, vdg = tid >> 5;
    uint4 vr0, vr1;
    auto loadV = [&](int k0) {
        const __half* vp = base + (size_t)(k0 + vs2) * D3 + 2 * DD + vdg * 8;
        vr0 = *(const uint4*)vp;
        vr1 = *(const uint4*)(vp + D3);
    };
    issueK(0);   // group 0: Q + K(0)
    loadV(0);

    float m2[2] = {-1e30f, -1e30f};
    float l2[2] = {0.0f, 0.0f};
    float oacc[8][4];
    #pragma unroll
    for (int i = 0; i < 8; i++)
        #pragma unroll
        for (int j = 0; j < 4; j++) oacc[i][j] = 0.0f;

    int l7 = l & 7;
    int rowfrag = (l & 7) + ((l >> 3) & 1) * 8;
    int sel = (l >> 4) & 1;
    int rA = w * 16 + rowfrag;
    int rloc = w * 16 + (l >> 2);

    // ---- hoist Q fragments (Q smem dead afterwards) ----
    unsigned aq[4][4];
    asm volatile("cp.async.wait_group 0;" ::: "memory");
    __syncthreads();
    #pragma unroll
    for (int ks = 0; ks < 4; ks++) {
        unsigned phys = (unsigned)((2 * ks + sel) ^ l7) * 16u;
        ldsm_x4(aq[ks][0], aq[ks][1], aq[ks][2], aq[ks][3], uQ + (unsigned)rA * 128u + phys);
    }

    for (int kt = 0; kt < nk; kt++) {
        int k0 = kt * 64;
        unsigned uK  = ub + 16384u + (unsigned)(kt & 1) * 8192u;
        unsigned uVT = ub + 32768u + (unsigned)(kt & 1) * 8192u;

        // store V transposed into VT[kt&1]
        {
            const __half* h0 = (const __half*)&vr0;
            const __half* h1 = (const __half*)&vr1;
            unsigned srow = (unsigned)(vs2 >> 3);
            unsigned scol = (unsigned)(vs2 & 7) * 2u;
            unsigned vtb = 32768u + (unsigned)(kt & 1) * 8192u;
            #pragma unroll
            for (int j = 0; j < 8; j++) {
                int d = vdg * 8 + j;
                unsigned phys = (srow ^ (unsigned)(d & 7)) * 16u;
                *(__half2*)(smc + vtb + (unsigned)d * 128u + phys + scol) =
                    __halves2half2(h0[j], h1[j]);
            }
        }
        asm volatile("cp.async.wait_group 0;" ::: "memory");
        __syncthreads();   // K(kt)+VT(kt) visible; prior-tile reads drained

        if (kt + 1 < nk) {
            issueK(kt + 1);
            loadV(k0 + 64);
        }

        // ---- S = Q K^T (already in log2 domain; q pre-scaled) ----
        float sacc[8][4];
        #pragma unroll
        for (int i = 0; i < 8; i++)
            #pragma unroll
            for (int j = 0; j < 4; j++) sacc[i][j] = 0.0f;

        #pragma unroll
        for (int ks = 0; ks < 4; ks++) {
            unsigned phys = (unsigned)((2 * ks + sel) ^ l7) * 16u;
            unsigned bf[4][4];
            #pragma unroll
            for (int np = 0; np < 4; np++)
                ldsm_x4(bf[np][0], bf[np][1], bf[np][2], bf[np][3],
                        uK + (unsigned)(np * 16 + rowfrag) * 128u + phys);
            #pragma unroll
            for (int nt = 0; nt < 8; nt++)
                mma_f16(sacc[nt], aq[ks][0], aq[ks][1], aq[ks][2], aq[ks][3],
                        bf[nt >> 1][nt & 1], bf[nt >> 1][(nt & 1) + 2]);
        }

        if (kt >= nk - 2) {
            #pragma unroll
            for (int nt = 0; nt < 8; nt++)
                #pragma unroll
                for (int e = 0; e < 4; e++) {
                    int r = q0 + rloc + ((e >> 1) << 3);
                    int c = k0 + nt * 8 + 2 * (l & 3) + (e & 1);
                    if (c > r) sacc[nt][e] = -1e30f;
                }
        }

        // online softmax (exp2 domain; 2 rows per thread)
        #pragma unroll
        for (int i = 0; i < 2; i++) {
            float tm = -1e30f;
            #pragma unroll
            for (int nt = 0; nt < 8; nt++)
                tm = fmaxf(tm, fmaxf(sacc[nt][2 * i], sacc[nt][2 * i + 1]));
            tm = fmaxf(tm, __shfl_xor_sync(0xffffffffu, tm, 1));
            tm = fmaxf(tm, __shfl_xor_sync(0xffffffffu, tm, 2));
            float mn = fmaxf(m2[i], tm);
            float alpha = ex2(m2[i] - mn);
            m2[i] = mn;
            float ls = 0.0f;
            #pragma unroll
            for (int nt = 0; nt < 8; nt++) {
                float p0 = ex2(sacc[nt][2 * i] - mn);
                float p1 = ex2(sacc[nt][2 * i + 1] - mn);
                sacc[nt][2 * i] = p0;
                sacc[nt][2 * i + 1] = p1;
                ls += p0 + p1;
            }
            ls += __shfl_xor_sync(0xffffffffu, ls, 1);
            ls += __shfl_xor_sync(0xffffffffu, ls, 2);
            l2[i] = l2[i] * alpha + ls;
            #pragma unroll
            for (int nt = 0; nt < 8; nt++) {
                oacc[nt][2 * i] *= alpha;
                oacc[nt][2 * i + 1] *= alpha;
            }
        }

        // ---- convert P to fp16 A-fragments (in registers) ----
        unsigned pa[4][4];
        #pragma unroll
        for (int ks = 0; ks < 4; ks++) {
            pa[ks][0] = pack_h2(sacc[2 * ks][0], sacc[2 * ks][1]);
            pa[ks][1] = pack_h2(sacc[2 * ks][2], sacc[2 * ks][3]);
            pa[ks][2] = pack_h2(sacc[2 * ks + 1][0], sacc[2 * ks + 1][1]);
            pa[ks][3] = pack_h2(sacc[2 * ks + 1][2], sacc[2 * ks + 1][3]);
        }

        // ---- O += P @ VT^T ----
        #pragma unroll
        for (int ks = 0; ks < 4; ks++) {
            unsigned phys = (unsigned)((2 * ks + sel) ^ l7) * 16u;
            unsigned bf[4][4];
            #pragma unroll
            for (int np = 0; np < 4; np++)
                ldsm_x4(bf[np][0], bf[np][1], bf[np][2], bf[np][3],
                        uVT + (unsigned)(np * 16 + rowfrag) * 128u + phys);
            #pragma unroll
            for (int nt = 0; nt < 8; nt++)
                mma_f16(oacc[nt], pa[ks][0], pa[ks][1], pa[ks][2], pa[ks][3],
                        bf[nt >> 1][nt & 1], bf[nt >> 1][(nt & 1) + 2]);
        }
    }

    float inv0 = 1.0f / l2[0];
    float inv1 = 1.0f / l2[1];
    int r = q0 + rloc;
    int dcol = h * HSZ + 2 * (l & 3);
    #pragma unroll
    for (int nt = 0; nt < 8; nt++) {
        *(__half2*)&out[(size_t)(b * SS + r) * DD + dcol + nt * 8] =
            __floats2half2_rn(oacc[nt][0] * inv0, oacc[nt][1] * inv0);
        *(__half2*)&out[(size_t)(b * SS + r + 8) * DD + dcol + nt * 8] =
            __floats2half2_rn(oacc[nt][2] * inv1, oacc[nt][3] * inv1);
    }
}

// ---------------- launch ----------------
extern "C" void kernel_launch(void* const* d_in, const int* in_sizes, int n_in,
                              void* d_out, int out_size) {
    const float* x     = (const float*)d_in[0];
    const float* wq    = (const float*)d_in[1];
    const float* wk    = (const float*)d_in[2];
    const float* wv    = (const float*)d_in[3];
    const float* wproj = (const float*)d_in[4];
    const float* bproj = (const float*)d_in[5];
    const float* w1    = (const float*)d_in[6];
    const float* b1    = (const float*)d_in[7];
    const float* w2    = (const float*)d_in[8];
    const float* b2    = (const float*)d_in[9];
    const float* ln1_g = (const float*)d_in[10];
    const float* ln1_b = (const float*)d_in[11];
    const float* ln2_g = (const float*)d_in[12];
    const float* ln2_b = (const float*)d_in[13];
    float* out = (float*)d_out;

    __half *p_xn, *p_qkv, *p_attn, *p_hn, *p_ff;
    __half *p_wqkvT, *p_wprojT, *p_w1T, *p_w2T;
    float *p_h;
    cudaGetSymbolAddress((void**)&p_xn, g_xn);
    cudaGetSymbolAddress((void**)&p_qkv, g_qkv);
    cudaGetSymbolAddress((void**)&p_attn, g_attn);
    cudaGetSymbolAddress((void**)&p_h, g_h);
    cudaGetSymbolAddress((void**)&p_hn, g_hn);
    cudaGetSymbolAddress((void**)&p_ff, g_ff);
    cudaGetSymbolAddress((void**)&p_wqkvT, g_wqkvT);
    cudaGetSymbolAddress((void**)&p_wprojT, g_wprojT);
    cudaGetSymbolAddress((void**)&p_w1T, g_w1T);
    cudaGetSymbolAddress((void**)&p_w2T, g_w2T);

    cudaFuncSetAttribute(gemm_tc<0>, cudaFuncAttributeMaxDynamicSharedMemorySize, GEMM_SMEM);
    cudaFuncSetAttribute(gemm_tc<1>, cudaFuncAttributeMaxDynamicSharedMemorySize, GEMM_SMEM);
    cudaFuncSetAttribute(gemm_tc<2>, cudaFuncAttributeMaxDynamicSharedMemorySize, GEMM_SMEM);
    cudaFuncSetAttribute(attn_tc, cudaFuncAttributeMaxDynamicSharedMemorySize, ATT_SMEM);

    // prep (fp16 weight transposes + LN1)
    build_wqkvT_kernel<<<dim3(16, 16, 3), 256>>>(wq, wk, wv, p_wqkvT);
    transpose3_kernel<<<9216, dim3(32, 8)>>>(wproj, p_wprojT, w1, p_w1T, w2, p_w2T);
    ln_kernel<<<BS, 256>>>(x, ln1_g, ln1_b, p_xn);

    // QKV GEMM -> fp16 qkv (q pre-scaled by QSCALE)
    gemm_tc<2><<<dim3(D3 / 128, BS / 128), 256, GEMM_SMEM>>>(
        p_xn, p_wqkvT, nullptr, nullptr, p_qkv, BS, D3, DD);

    // fp16 flash attention (register-resident P, log2-domain S)
    attn_tc<<<dim3(SS / 128, BB * HH), 256, ATT_SMEM>>>(p_qkv, p_attn);

    // proj + bias + residual(x) -> h (fp32)
    gemm_tc<0><<<dim3(DD / 128, BS / 128), 256, GEMM_SMEM>>>(
        p_attn, p_wprojT, bproj, x, p_h, BS, DD, DD);

    // LN2 -> fp16 hn
    ln_kernel<<<BS, 256>>>(p_h, ln2_g, ln2_b, p_hn);

    // FF1 + bias + relu -> fp16 ff
    gemm_tc<1><<<dim3(DFF / 128, BS / 128), 256, GEMM_SMEM>>>(
        p_hn, p_w1T, b1, nullptr, p_ff, BS, DFF, DD);

    // FF2 + bias + residual(h) -> out (fp32)
    gemm_tc<0><<<dim3(DD / 128, BS / 128), 256, GEMM_SMEM>>>(
        p_ff, p_w2T, b2, p_h, out, BS, DD, DFF);
}

// round 15
// speedup vs baseline: 1.8453x; 1.0112x over previous
#include <cuda_runtime.h>
#include <cuda_fp16.h>
#include <cstdint>

// Problem constants
#define BB 2
#define SS 2048
#define DD 1024
#define HH 16
#define HSZ 64
#define BS (BB * SS)        // 4096 rows
#define D3 (3 * DD)         // 3072
#define DFF (4 * DD)        // 4096

// softmax scale folded with log2e, applied to q in the QKV GEMM epilogue
#define QSCALE 0.1803368801111721f   // 0.125 * log2(e)

// ---------------- scratch (static device memory; no allocations) ----------------
__device__ __half g_xn[BS * DD];
__device__ __half g_qkv[BS * D3];
__device__ __half g_attn[BS * DD];
__device__ float  g_h[BS * DD];
__device__ __half g_hn[BS * DD];
__device__ __half g_ff[BS * DFF];
__device__ __half g_wqkvT[D3 * DD];
__device__ __half g_wprojT[DD * DD];
__device__ __half g_w1T[DFF * DD];
__device__ __half g_w2T[DD * DFF];

// pack two fp32 into one f16x2 register (rn rounding)
__device__ __forceinline__ unsigned pack_h2(float lo, float hi) {
    unsigned r;
    asm("cvt.rn.f16x2.f32 %0, %1, %2;" : "=r"(r) : "f"(hi), "f"(lo));
    return r;
}

// bare exp2 (single MUFU.EX2)
__device__ __forceinline__ float ex2(float x) {
    float r;
    asm("ex2.approx.f32 %0, %1;" : "=f"(r) : "f"(x));
    return r;
}

// ---------------- LayerNorm (fp32 in -> fp16 out), single-pass, 2 barriers -----
__global__ void ln_kernel(const float* __restrict__ in, const float* __restrict__ gamma,
                          const float* __restrict__ beta, __half* __restrict__ out) {
    int row = blockIdx.x;
    int tid = threadIdx.x;
    int lane = tid & 31, wid = tid >> 5;
    float4 xv = ((const float4*)(in + (size_t)row * DD))[tid];

    float s = xv.x + xv.y + xv.z + xv.w;
    float s2 = xv.x * xv.x + xv.y * xv.y + xv.z * xv.z + xv.w * xv.w;
    #pragma unroll
    for (int o = 16; o; o >>= 1) {
        s += __shfl_xor_sync(0xffffffffu, s, o);
        s2 += __shfl_xor_sync(0xffffffffu, s2, o);
    }

    __shared__ float red[16];
    __shared__ float stat[2];
    if (lane == 0) { red[wid] = s; red[8 + wid] = s2; }
    __syncthreads();
    if (tid < 32) {
        float a = (lane < 8) ? red[lane] : 0.0f;
        float b = (lane < 8) ? red[8 + lane] : 0.0f;
        #pragma unroll
        for (int o = 4; o; o >>= 1) {
            a += __shfl_xor_sync(0xffffffffu, a, o);
            b += __shfl_xor_sync(0xffffffffu, b, o);
        }
        if (lane == 0) {
            float mu = a * (1.0f / DD);
            float var = b * (1.0f / DD) - mu * mu;
            stat[0] = mu;
            stat[1] = rsqrtf(var + 1e-5f);
        }
    }
    __syncthreads();
    float mu = stat[0], rstd = stat[1];

    float4 gv = ((const float4*)gamma)[tid];
    float4 bv = ((const float4*)beta)[tid];
    __half2 h0 = __floats2half2_rn((xv.x - mu) * rstd * gv.x + bv.x,
                                   (xv.y - mu) * rstd * gv.y + bv.y);
    __half2 h1 = __floats2half2_rn((xv.z - mu) * rstd * gv.z + bv.z,
                                   (xv.w - mu) * rstd * gv.w + bv.w);
    ((__half2*)(out + (size_t)row * DD))[tid * 2] = h0;
    ((__half2*)(out + (size_t)row * DD))[tid * 2 + 1] = h1;
}

// ---------------- fused weight prep: wqkvT + transposes (fp32 -> fp16) ---------
// blocks [0,1024): wproj 32x32 tiles; [1024,5120): w1; [5120,9216): w2;
// [9216,9984): build wqkvT (768 blocks = 16 dblk x 16 h x 3 part)
__global__ void prep_weights_kernel(
    const float* __restrict__ wq, const float* __restrict__ wk,
    const float* __restrict__ wv, __half* __restrict__ wqkvT,
    const float* __restrict__ wproj, __half* __restrict__ wprojT,
    const float* __restrict__ w1, __half* __restrict__ w1T,
    const float* __restrict__ w2, __half* __restrict__ w2T) {
    int id = blockIdx.x;
    int tid = threadIdx.x;

    if (id >= 9216) {
        // build wqkvT: wqkvT[part*1024 + h*64 + kk][d] = w_part[(h*1024+d)*64 + kk]
        __shared__ float sm[64][65];
        int t = id - 9216;
        int dblk = t & 15;
        int h = (t >> 4) & 15;
        int part = t >> 8;
        const float* w = (part == 0) ? wq : (part == 1) ? wk : wv;
        int d0 = dblk * 64;

        int kk = tid & 63;
        int g4 = tid >> 6;
        #pragma unroll
        for (int i = 0; i < 16; i++) {
            int dl = g4 + i * 4;
            sm[dl][kk] = w[((size_t)(h * DD + d0 + dl)) * HSZ + kk];
        }
        __syncthreads();
        int dc = tid & 63;
        #pragma unroll
        for (int i = 0; i < 16; i++) {
            int kk2 = g4 + i * 4;
            wqkvT[(size_t)(part * DD + h * HSZ + kk2) * DD + d0 + dc] =
                __float2half_rn(sm[dc][kk2]);
        }
        return;
    }

    // transpose path: in[R][C] -> out[C][R]
    __shared__ float t[32][33];
    int tx = tid & 31, ty = tid >> 5;   // 32 x 8
    const float* in;
    __half* out;
    int bx, by, R, C;
    if (id < 1024) {
        in = wproj; out = wprojT; R = DD; C = DD;
        bx = id & 31; by = id >> 5;
    } else if (id < 5120) {
        int tgt = id - 1024;
        in = w1; out = w1T; R = DD; C = DFF;
        bx = tgt & 127; by = tgt >> 7;
    } else {
        int tgt = id - 5120;
        in = w2; out = w2T; R = DFF; C = DD;
        bx = tgt & 31; by = tgt >> 5;
    }

    int x = bx * 32 + tx;
    int y = by * 32 + ty;
    #pragma unroll
    for (int i = 0; i < 32; i += 8)
        t[ty + i][tx] = in[(size_t)(y + i) * C + x];
    __syncthreads();
    x = by * 32 + tx;
    y = bx * 32 + ty;
    #pragma unroll
    for (int i = 0; i < 32; i += 8)
        out[(size_t)(y + i) * R + x] = __float2half_rn(t[tx][ty + i]);
}

// ---------------- tensor-core helpers -------------------------------
__device__ __forceinline__ void ldsm_x4(unsigned& r0, unsigned& r1, unsigned& r2, unsigned& r3,
                                        unsigned addr) {
    asm volatile("ldmatrix.sync.aligned.m8n8.x4.shared.b16 {%0,%1,%2,%3}, [%4];"
                 : "=r"(r0), "=r"(r1), "=r"(r2), "=r"(r3) : "r"(addr));
}

__device__ __forceinline__ void mma_f16(float c[4], unsigned a0, unsigned a1, unsigned a2,
                                        unsigned a3, unsigned b0, unsigned b1) {
    asm volatile(
        "mma.sync.aligned.m16n8k16.row.col.f32.f16.f16.f32 "
        "{%0,%1,%2,%3}, {%4,%5,%6,%7}, {%8,%9}, {%0,%1,%2,%3};"
        : "+f"(c[0]), "+f"(c[1]), "+f"(c[2]), "+f"(c[3])
        : "r"(a0), "r"(a1), "r"(a2), "r"(a3), "r"(b0), "r"(b1));
}

#define CPA16(dst, src) \
    asm volatile("cp.async.cg.shared.global [%0], [%1], 16;" :: "r"(dst), "l"(src))

// ---------------- fp16 GEMM: 128x128 tile, BK=64 halves, 256 thr, 3-stage ------
// stage offsets rotated in registers (no %3); ks=0 fragment loads peeled ahead
// of the next prefetch so the ldsm->mma critical chain starts immediately.
#define GEMM_SMEM (3 * 32768)

// MODE: 0 = fp32 out (+res), 1 = fp16 out + relu,
//       2 = fp16 out with QSCALE applied to cols < DD (QKV gemm: scales q)
template <int MODE>
__global__ __launch_bounds__(256, 2)
void gemm_tc(const __half* __restrict__ A, const __half* __restrict__ Bt,
             const float* __restrict__ bias, const float* __restrict__ res,
             void* __restrict__ Cv, int M, int N, int K) {
    extern __shared__ unsigned smem_u[];
    unsigned sbase = (unsigned)__cvta_generic_to_shared(smem_u);

    int tid = threadIdx.x;
    int l = tid & 31;
    int wid = tid >> 5;
    int warp_m = wid >> 2;   // 0..1
    int warp_n = wid & 3;    // 0..3
    int bx = blockIdx.x * 128;
    int by = blockIdx.y * 128;

    float acc[4][4][4];
    #pragma unroll
    for (int i = 0; i < 4; i++)
        #pragma unroll
        for (int j = 0; j < 4; j++)
            #pragma unroll
            for (int k = 0; k < 4; k++) acc[i][j][k] = 0.0f;

    int lm = tid >> 3;
    int kc = tid & 7;
    unsigned physc = (unsigned)(kc ^ (lm & 7));
    const __half* aptr = A + (size_t)(by + lm) * K + kc * 8;
    const __half* bptr = Bt + (size_t)(bx + lm) * K + kc * 8;

    int NT = K / 64;

    int rowfrag = (l & 7) + ((l >> 3) & 1) * 8;
    int sel = (l >> 4) & 1;
    int l7 = l & 7;
    int rA = warp_m * 64 + rowfrag;
    int rB = warp_n * 32 + rowfrag;

    auto issue = [&](int kt, unsigned soff) {
        unsigned sA = sbase + soff;
        unsigned sB = sA + 16384u;
        const __half* ap = aptr + kt * 64;
        const __half* bp = bptr + kt * 64;
        #pragma unroll
        for (int i = 0; i < 4; i++) {
            unsigned off = ((unsigned)(lm + 32 * i) * 8 + physc) * 16;
            CPA16(sA + off, ap + (size_t)(32 * i) * K);
            CPA16(sB + off, bp + (size_t)(32 * i) * K);
        }
        asm volatile("cp.async.commit_group;");
    };

    issue(0, 0u);
    issue(1, 32768u);

    unsigned stComp = 0u;        // stage offset for compute chunk kt
    unsigned stIss = 65536u;     // stage offset for prefetch chunk kt+2

    #pragma unroll 1
    for (int kt = 0; kt < NT; kt++) {
        if (kt < NT - 1) {
            asm volatile("cp.async.wait_group 1;" ::: "memory");
        } else {
            asm volatile("cp.async.wait_group 0;" ::: "memory");
        }
        __syncthreads();

        unsigned sA = sbase + stComp;
        unsigned sB = sA + 16384u;
        stComp = (stComp == 65536u) ? 0u : stComp + 32768u;

        unsigned a[4][4], bf[2][4];
        // ---- peel ks=0 fragment loads (critical chain starts now) ----
        {
            unsigned phys = (unsigned)(sel ^ l7) * 16u;
            unsigned aBase = sA + (unsigned)rA * 128u + phys;
            unsigned bBase = sB + (unsigned)rB * 128u + phys;
            #pragma unroll
            for (int mt = 0; mt < 4; mt++)
                ldsm_x4(a[mt][0], a[mt][1], a[mt][2], a[mt][3], aBase + mt * 2048u);
            #pragma unroll
            for (int np = 0; np < 2; np++)
                ldsm_x4(bf[np][0], bf[np][1], bf[np][2], bf[np][3], bBase + np * 2048u);
        }

        // prefetch kt+2 in the shadow of ks=0 mma
        if (kt + 2 < NT) {
            issue(kt + 2, stIss);
            stIss = (stIss == 65536u) ? 0u : stIss + 32768u;
        }

        // ks=0 mma
        #pragma unroll
        for (int mt = 0; mt < 4; mt++)
            #pragma unroll
            for (int nt = 0; nt < 4; nt++)
                mma_f16(acc[mt][nt], a[mt][0], a[mt][1], a[mt][2], a[mt][3],
                        bf[nt >> 1][nt & 1], bf[nt >> 1][(nt & 1) + 2]);

        // ks = 1..3
        #pragma unroll
        for (int ks = 1; ks < 4; ks++) {
            unsigned phys = (unsigned)((2 * ks + sel) ^ l7) * 16u;
            unsigned aBase = sA + (unsigned)rA * 128u + phys;
            unsigned bBase = sB + (unsigned)rB * 128u + phys;
            #pragma unroll
            for (int mt = 0; mt < 4; mt++)
                ldsm_x4(a[mt][0], a[mt][1], a[mt][2], a[mt][3], aBase + mt * 2048u);
            #pragma unroll
            for (int np = 0; np < 2; np++)
                ldsm_x4(bf[np][0], bf[np][1], bf[np][2], bf[np][3], bBase + np * 2048u);
            #pragma unroll
            for (int mt = 0; mt < 4; mt++)
                #pragma unroll
                for (int nt = 0; nt < 4; nt++)
                    mma_f16(acc[mt][nt], a[mt][0], a[mt][1], a[mt][2], a[mt][3],
                            bf[nt >> 1][nt & 1], bf[nt >> 1][(nt & 1) + 2]);
        }
    }

    int g = l >> 2, tg = l & 3;
    #pragma unroll
    for (int mt = 0; mt < 4; mt++) {
        int r0 = by + warp_m * 64 + mt * 16 + g;
        #pragma unroll
        for (int nt = 0; nt < 4; nt++) {
            int col = bx + warp_n * 32 + nt * 8 + tg * 2;
            float2 v0 = make_float2(acc[mt][nt][0], acc[mt][nt][1]);
            float2 v1 = make_float2(acc[mt][nt][2], acc[mt][nt][3]);
            if (bias != nullptr) {
                float2 bv = *(const float2*)&bias[col];
                v0.x += bv.x; v0.y += bv.y; v1.x += bv.x; v1.y += bv.y;
            }
            if (MODE == 0) {
                if (res != nullptr) {
                    float2 q0 = *(const float2*)&res[(size_t)r0 * N + col];
                    float2 q1 = *(const float2*)&res[(size_t)(r0 + 8) * N + col];
                    v0.x += q0.x; v0.y += q0.y; v1.x += q1.x; v1.y += q1.y;
                }
                float* C = (float*)Cv;
                *(float2*)&C[(size_t)r0 * N + col] = v0;
                *(float2*)&C[(size_t)(r0 + 8) * N + col] = v1;
            } else {
                if (MODE == 1) {
                    v0.x = fmaxf(v0.x, 0.0f); v0.y = fmaxf(v0.y, 0.0f);
                    v1.x = fmaxf(v1.x, 0.0f); v1.y = fmaxf(v1.y, 0.0f);
                }
                if (MODE == 2 && col < DD) {   // q columns: fold softmax scale
                    v0.x *= QSCALE; v0.y *= QSCALE;
                    v1.x *= QSCALE; v1.y *= QSCALE;
                }
                __half* C = (__half*)Cv;
                *(__half2*)&C[(size_t)r0 * N + col] = __floats2half2_rn(v0.x, v0.y);
                *(__half2*)&C[(size_t)(r0 + 8) * N + col] = __floats2half2_rn(v1.x, v1.y);
            }
        }
    }
}

// ---------------- fp16 flash attention, register P, exp2 softmax ---------------
// q pre-scaled by QSCALE at the QKV GEMM -> S lands in log2 domain directly.
// 128-query tile, 8 warps x 16 rows; 64-key tiles; ONE barrier per tile.
// smem: Q[128][128B] @0 (16KB), K[2][64][128B] @16384 (8KB each),
//       VT[2][64][128B] @32768 (8KB each). total 48KB -> 2 CTAs/SM.
#define ATT_SMEM 49152

__global__ __launch_bounds__(256, 2)
void attn_tc(const __half* __restrict__ qkv, __half* __restrict__ out) {
    extern __shared__ char smc[];
    unsigned ub = (unsigned)__cvta_generic_to_shared(smc);
    unsigned uQ = ub;

    int tid = threadIdx.x;
    int l = tid & 31, w = tid >> 5;
    int b = blockIdx.y >> 4, h = blockIdx.y & 15;
    int q0 = ((int)gridDim.x - 1 - (int)blockIdx.x) * 128;
    int nk = q0 / 64 + 2;

    const __half* base = qkv + (size_t)b * SS * D3 + h * HSZ;

    int lr = tid >> 3, lc = tid & 7;
    unsigned lphys = (unsigned)(lc ^ (lr & 7)) * 16u;

    #pragma unroll
    for (int p = 0; p < 4; p++) {
        int row = lr + 32 * p;
        CPA16(uQ + (unsigned)row * 128u + lphys, base + (size_t)(q0 + row) * D3 + lc * 8);
    }
    auto issueK = [&](int kt) {
        unsigned uK = ub + 16384u + (unsigned)(kt & 1) * 8192u;
        int k0 = kt * 64;
        #pragma unroll
        for (int p = 0; p < 2; p++) {
            int row = lr + 32 * p;
            CPA16(uK + (unsigned)row * 128u + lphys,
                  base + (size_t)(k0 + row) * D3 + DD + lc * 8);
        }
        asm volatile("cp.async.commit_group;");
    };

    int vs2 = (tid & 31) * 2, vdg = tid >> 5;
    uint4 vr0, vr1;
    auto loadV = [&](int k0) {
        const __half* vp = base + (size_t)(k0 + vs2) * D3 + 2 * DD + vdg * 8;
        vr0 = *(const uint4*)vp;
        vr1 = *(const uint4*)(vp + D3);
    };
    issueK(0);   // group 0: Q + K(0)
    loadV(0);

    float m2[2] = {-1e30f, -1e30f};
    float l2[2] = {0.0f, 0.0f};
    float oacc[8][4];
    #pragma unroll
    for (int i = 0; i < 8; i++)
        #pragma unroll
        for (int j = 0; j < 4; j++) oacc[i][j] = 0.0f;

    int l7 = l & 7;
    int rowfrag = (l & 7) + ((l >> 3) & 1) * 8;
    int sel = (l >> 4) & 1;
    int rA = w * 16 + rowfrag;
    int rloc = w * 16 + (l >> 2);

    // ---- hoist Q fragments (Q smem dead afterwards) ----
    unsigned aq[4][4];
    asm volatile("cp.async.wait_group 0;" ::: "memory");
    __syncthreads();
    #pragma unroll
    for (int ks = 0; ks < 4; ks++) {
        unsigned phys = (unsigned)((2 * ks + sel) ^ l7) * 16u;
        ldsm_x4(aq[ks][0], aq[ks][1], aq[ks][2], aq[ks][3], uQ + (unsigned)rA * 128u + phys);
    }

    for (int kt = 0; kt < nk; kt++) {
        int k0 = kt * 64;
        unsigned uK  = ub + 16384u + (unsigned)(kt & 1) * 8192u;
        unsigned uVT = ub + 32768u + (unsigned)(kt & 1) * 8192u;

        // store V transposed into VT[kt&1]
        {
            const __half* h0 = (const __half*)&vr0;
            const __half* h1 = (const __half*)&vr1;
            unsigned srow = (unsigned)(vs2 >> 3);
            unsigned scol = (unsigned)(vs2 & 7) * 2u;
            unsigned vtb = 32768u + (unsigned)(kt & 1) * 8192u;
            #pragma unroll
            for (int j = 0; j < 8; j++) {
                int d = vdg * 8 + j;
                unsigned phys = (srow ^ (unsigned)(d & 7)) * 16u;
                *(__half2*)(smc + vtb + (unsigned)d * 128u + phys + scol) =
                    __halves2half2(h0[j], h1[j]);
            }
        }
        asm volatile("cp.async.wait_group 0;" ::: "memory");
        __syncthreads();   // K(kt)+VT(kt) visible; prior-tile reads drained

        if (kt + 1 < nk) {
            issueK(kt + 1);
            loadV(k0 + 64);
        }

        // ---- S = Q K^T (already in log2 domain; q pre-scaled) ----
        float sacc[8][4];
        #pragma unroll
        for (int i = 0; i < 8; i++)
            #pragma unroll
            for (int j = 0; j < 4; j++) sacc[i][j] = 0.0f;

        #pragma unroll
        for (int ks = 0; ks < 4; ks++) {
            unsigned phys = (unsigned)((2 * ks + sel) ^ l7) * 16u;
            unsigned bf[4][4];
            #pragma unroll
            for (int np = 0; np < 4; np++)
                ldsm_x4(bf[np][0], bf[np][1], bf[np][2], bf[np][3],
                        uK + (unsigned)(np * 16 + rowfrag) * 128u + phys);
            #pragma unroll
            for (int nt = 0; nt < 8; nt++)
                mma_f16(sacc[nt], aq[ks][0], aq[ks][1], aq[ks][2], aq[ks][3],
                        bf[nt >> 1][nt & 1], bf[nt >> 1][(nt & 1) + 2]);
        }

        if (kt >= nk - 2) {
            #pragma unroll
            for (int nt = 0; nt < 8; nt++)
                #pragma unroll
                for (int e = 0; e < 4; e++) {
                    int r = q0 + rloc + ((e >> 1) << 3);
                    int c = k0 + nt * 8 + 2 * (l & 3) + (e & 1);
                    if (c > r) sacc[nt][e] = -1e30f;
                }
        }

        // online softmax (exp2 domain; 2 rows per thread)
        #pragma unroll
        for (int i = 0; i < 2; i++) {
            float tm = -1e30f;
            #pragma unroll
            for (int nt = 0; nt < 8; nt++)
                tm = fmaxf(tm, fmaxf(sacc[nt][2 * i], sacc[nt][2 * i + 1]));
            tm = fmaxf(tm, __shfl_xor_sync(0xffffffffu, tm, 1));
            tm = fmaxf(tm, __shfl_xor_sync(0xffffffffu, tm, 2));
            float mn = fmaxf(m2[i], tm);
            float alpha = ex2(m2[i] - mn);
            m2[i] = mn;
            float ls = 0.0f;
            #pragma unroll
            for (int nt = 0; nt < 8; nt++) {
                float p0 = ex2(sacc[nt][2 * i] - mn);
                float p1 = ex2(sacc[nt][2 * i + 1] - mn);
                sacc[nt][2 * i] = p0;
                sacc[nt][2 * i + 1] = p1;
                ls += p0 + p1;
            }
            ls += __shfl_xor_sync(0xffffffffu, ls, 1);
            ls += __shfl_xor_sync(0xffffffffu, ls, 2);
            l2[i] = l2[i] * alpha + ls;
            #pragma unroll
            for (int nt = 0; nt < 8; nt++) {
                oacc[nt][2 * i] *= alpha;
                oacc[nt][2 * i + 1] *= alpha;
            }
        }

        // ---- convert P to fp16 A-fragments (in registers) ----
        unsigned pa[4][4];
        #pragma unroll
        for (int ks = 0; ks < 4; ks++) {
            pa[ks][0] = pack_h2(sacc[2 * ks][0], sacc[2 * ks][1]);
            pa[ks][1] = pack_h2(sacc[2 * ks][2], sacc[2 * ks][3]);
            pa[ks][2] = pack_h2(sacc[2 * ks + 1][0], sacc[2 * ks + 1][1]);
            pa[ks][3] = pack_h2(sacc[2 * ks + 1][2], sacc[2 * ks + 1][3]);
        }

        // ---- O += P @ VT^T ----
        #pragma unroll
        for (int ks = 0; ks < 4; ks++) {
            unsigned phys = (unsigned)((2 * ks + sel) ^ l7) * 16u;
            unsigned bf[4][4];
            #pragma unroll
            for (int np = 0; np < 4; np++)
                ldsm_x4(bf[np][0], bf[np][1], bf[np][2], bf[np][3],
                        uVT + (unsigned)(np * 16 + rowfrag) * 128u + phys);
            #pragma unroll
            for (int nt = 0; nt < 8; nt++)
                mma_f16(oacc[nt], pa[ks][0], pa[ks][1], pa[ks][2], pa[ks][3],
                        bf[nt >> 1][nt & 1], bf[nt >> 1][(nt & 1) + 2]);
        }
    }

    float inv0 = 1.0f / l2[0];
    float inv1 = 1.0f / l2[1];
    int r = q0 + rloc;
    int dcol = h * HSZ + 2 * (l & 3);
    #pragma unroll
    for (int nt = 0; nt < 8; nt++) {
        *(__half2*)&out[(size_t)(b * SS + r) * DD + dcol + nt * 8] =
            __floats2half2_rn(oacc[nt][0] * inv0, oacc[nt][1] * inv0);
        *(__half2*)&out[(size_t)(b * SS + r + 8) * DD + dcol + nt * 8] =
            __floats2half2_rn(oacc[nt][2] * inv1, oacc[nt][3] * inv1);
    }
}

// ---------------- launch ----------------
extern "C" void kernel_launch(void* const* d_in, const int* in_sizes, int n_in,
                              void* d_out, int out_size) {
    const float* x     = (const float*)d_in[0];
    const float* wq    = (const float*)d_in[1];
    const float* wk    = (const float*)d_in[2];
    const float* wv    = (const float*)d_in[3];
    const float* wproj = (const float*)d_in[4];
    const float* bproj = (const float*)d_in[5];
    const float* w1    = (const float*)d_in[6];
    const float* b1    = (const float*)d_in[7];
    const float* w2    = (const float*)d_in[8];
    const float* b2    = (const float*)d_in[9];
    const float* ln1_g = (const float*)d_in[10];
    const float* ln1_b = (const float*)d_in[11];
    const float* ln2_g = (const float*)d_in[12];
    const float* ln2_b = (const float*)d_in[13];
    float* out = (float*)d_out;

    __half *p_xn, *p_qkv, *p_attn, *p_hn, *p_ff;
    __half *p_wqkvT, *p_wprojT, *p_w1T, *p_w2T;
    float *p_h;
    cudaGetSymbolAddress((void**)&p_xn, g_xn);
    cudaGetSymbolAddress((void**)&p_qkv, g_qkv);
    cudaGetSymbolAddress((void**)&p_attn, g_attn);
    cudaGetSymbolAddress((void**)&p_h, g_h);
    cudaGetSymbolAddress((void**)&p_hn, g_hn);
    cudaGetSymbolAddress((void**)&p_ff, g_ff);
    cudaGetSymbolAddress((void**)&p_wqkvT, g_wqkvT);
    cudaGetSymbolAddress((void**)&p_wprojT, g_wprojT);
    cudaGetSymbolAddress((void**)&p_w1T, g_w1T);
    cudaGetSymbolAddress((void**)&p_w2T, g_w2T);

    cudaFuncSetAttribute(gemm_tc<0>, cudaFuncAttributeMaxDynamicSharedMemorySize, GEMM_SMEM);
    cudaFuncSetAttribute(gemm_tc<1>, cudaFuncAttributeMaxDynamicSharedMemorySize, GEMM_SMEM);
    cudaFuncSetAttribute(gemm_tc<2>, cudaFuncAttributeMaxDynamicSharedMemorySize, GEMM_SMEM);
    cudaFuncSetAttribute(attn_tc, cudaFuncAttributeMaxDynamicSharedMemorySize, ATT_SMEM);

    // prep: fused weight transposes + LN1
    prep_weights_kernel<<<9984, 256>>>(wq, wk, wv, p_wqkvT, wproj, p_wprojT,
                                       w1, p_w1T, w2, p_w2T);
    ln_kernel<<<BS, 256>>>(x, ln1_g, ln1_b, p_xn);

    // QKV GEMM -> fp16 qkv (q pre-scaled by QSCALE)
    gemm_tc<2><<<dim3(D3 / 128, BS / 128), 256, GEMM_SMEM>>>(
        p_xn, p_wqkvT, nullptr, nullptr, p_qkv, BS, D3, DD);

    // fp16 flash attention (register-resident P, log2-domain S)
    attn_tc<<<dim3(SS / 128, BB * HH), 256, ATT_SMEM>>>(p_qkv, p_attn);

    // proj + bias + residual(x) -> h (fp32)
    gemm_tc<0><<<dim3(DD / 128, BS / 128), 256, GEMM_SMEM>>>(
        p_attn, p_wprojT, bproj, x, p_h, BS, DD, DD);

    // LN2 -> fp16 hn
    ln_kernel<<<BS, 256>>>(p_h, ln2_g, ln2_b, p_hn);

    // FF1 + bias + relu -> fp16 ff
    gemm_tc<1><<<dim3(DFF / 128, BS / 128), 256, GEMM_SMEM>>>(
        p_hn, p_w1T, b1, nullptr, p_ff, BS, DFF, DD);

    // FF2 + bias + residual(h) -> out (fp32)
    gemm_tc<0><<<dim3(DD / 128, BS / 128), 256, GEMM_SMEM>>>(
        p_ff, p_w2T, b2, p_h, out, BS, DD, DFF);
}

// round 16
// speedup vs baseline: 1.8948x; 1.0268x over previous
#include <cuda_runtime.h>
#include <cuda_fp16.h>
#include <cstdint>

// Problem constants
#define BB 2
#define SS 2048
#define DD 1024
#define HH 16
#define HSZ 64
#define BS (BB * SS)        // 4096 rows
#define D3 (3 * DD)         // 3072
#define DFF (4 * DD)        // 4096

// softmax scale folded with log2e, applied to q in the QKV GEMM epilogue
#define QSCALE 0.1803368801111721f   // 0.125 * log2(e)

// ---------------- scratch (static device memory; no allocations) ----------------
__device__ __half g_xn[BS * DD];
__device__ __half g_qkv[BS * D3];
__device__ __half g_attn[BS * DD];
__device__ float  g_h[BS * DD];
__device__ __half g_hn[BS * DD];
__device__ __half g_ff[BS * DFF];
__device__ __half g_wqkvT[D3 * DD];
__device__ __half g_wprojT[DD * DD];
__device__ __half g_w1T[DFF * DD];
__device__ __half g_w2T[DD * DFF];

// pack two fp32 into one f16x2 register (rn rounding)
__device__ __forceinline__ unsigned pack_h2(float lo, float hi) {
    unsigned r;
    asm("cvt.rn.f16x2.f32 %0, %1, %2;" : "=r"(r) : "f"(hi), "f"(lo));
    return r;
}

// bare exp2 (single MUFU.EX2)
__device__ __forceinline__ float ex2(float x) {
    float r;
    asm("ex2.approx.f32 %0, %1;" : "=f"(r) : "f"(x));
    return r;
}

// ---------------- LayerNorm body (single-pass, 2 barriers) ----------------
__device__ __forceinline__ void ln_body(const float* __restrict__ in,
                                        const float* __restrict__ gamma,
                                        const float* __restrict__ beta,
                                        __half* __restrict__ out, int row, int tid) {
    int lane = tid & 31, wid = tid >> 5;
    float4 xv = ((const float4*)(in + (size_t)row * DD))[tid];

    float s = xv.x + xv.y + xv.z + xv.w;
    float s2 = xv.x * xv.x + xv.y * xv.y + xv.z * xv.z + xv.w * xv.w;
    #pragma unroll
    for (int o = 16; o; o >>= 1) {
        s += __shfl_xor_sync(0xffffffffu, s, o);
        s2 += __shfl_xor_sync(0xffffffffu, s2, o);
    }

    __shared__ float red[16];
    __shared__ float stat[2];
    if (lane == 0) { red[wid] = s; red[8 + wid] = s2; }
    __syncthreads();
    if (tid < 32) {
        float a = (lane < 8) ? red[lane] : 0.0f;
        float b = (lane < 8) ? red[8 + lane] : 0.0f;
        #pragma unroll
        for (int o = 4; o; o >>= 1) {
            a += __shfl_xor_sync(0xffffffffu, a, o);
            b += __shfl_xor_sync(0xffffffffu, b, o);
        }
        if (lane == 0) {
            float mu = a * (1.0f / DD);
            float var = b * (1.0f / DD) - mu * mu;
            stat[0] = mu;
            stat[1] = rsqrtf(var + 1e-5f);
        }
    }
    __syncthreads();
    float mu = stat[0], rstd = stat[1];

    float4 gv = ((const float4*)gamma)[tid];
    float4 bv = ((const float4*)beta)[tid];
    __half2 h0 = __floats2half2_rn((xv.x - mu) * rstd * gv.x + bv.x,
                                   (xv.y - mu) * rstd * gv.y + bv.y);
    __half2 h1 = __floats2half2_rn((xv.z - mu) * rstd * gv.z + bv.z,
                                   (xv.w - mu) * rstd * gv.w + bv.w);
    ((__half2*)(out + (size_t)row * DD))[tid * 2] = h0;
    ((__half2*)(out + (size_t)row * DD))[tid * 2 + 1] = h1;
}

__global__ void ln_kernel(const float* __restrict__ in, const float* __restrict__ gamma,
                          const float* __restrict__ beta, __half* __restrict__ out) {
    ln_body(in, gamma, beta, out, blockIdx.x, threadIdx.x);
}

// ---------------- fused prep: weight transposes + wqkvT + LN1 ------------------
// blocks [0,1024): wproj; [1024,5120): w1; [5120,9216): w2;
// [9216,9984): wqkvT; [9984, 9984+BS): LN1 rows
__global__ void prep_kernel(
    const float* __restrict__ wq, const float* __restrict__ wk,
    const float* __restrict__ wv, __half* __restrict__ wqkvT,
    const float* __restrict__ wproj, __half* __restrict__ wprojT,
    const float* __restrict__ w1, __half* __restrict__ w1T,
    const float* __restrict__ w2, __half* __restrict__ w2T,
    const float* __restrict__ x, const float* __restrict__ ln1_g,
    const float* __restrict__ ln1_b, __half* __restrict__ xn) {
    int id = blockIdx.x;
    int tid = threadIdx.x;

    if (id >= 9984) {
        ln_body(x, ln1_g, ln1_b, xn, id - 9984, tid);
        return;
    }

    if (id >= 9216) {
        __shared__ float sm[64][65];
        int t = id - 9216;
        int dblk = t & 15;
        int h = (t >> 4) & 15;
        int part = t >> 8;
        const float* w = (part == 0) ? wq : (part == 1) ? wk : wv;
        int d0 = dblk * 64;

        int kk = tid & 63;
        int g4 = tid >> 6;
        #pragma unroll
        for (int i = 0; i < 16; i++) {
            int dl = g4 + i * 4;
            sm[dl][kk] = w[((size_t)(h * DD + d0 + dl)) * HSZ + kk];
        }
        __syncthreads();
        int dc = tid & 63;
        #pragma unroll
        for (int i = 0; i < 16; i++) {
            int kk2 = g4 + i * 4;
            wqkvT[(size_t)(part * DD + h * HSZ + kk2) * DD + d0 + dc] =
                __float2half_rn(sm[dc][kk2]);
        }
        return;
    }

    __shared__ float t[32][33];
    int tx = tid & 31, ty = tid >> 5;
    const float* in;
    __half* out;
    int bx, by, R, C;
    if (id < 1024) {
        in = wproj; out = wprojT; R = DD; C = DD;
        bx = id & 31; by = id >> 5;
    } else if (id < 5120) {
        int tgt = id - 1024;
        in = w1; out = w1T; R = DD; C = DFF;
        bx = tgt & 127; by = tgt >> 7;
    } else {
        int tgt = id - 5120;
        in = w2; out = w2T; R = DFF; C = DD;
        bx = tgt & 31; by = tgt >> 5;
    }

    int x2 = bx * 32 + tx;
    int y2 = by * 32 + ty;
    #pragma unroll
    for (int i = 0; i < 32; i += 8)
        t[ty + i][tx] = in[(size_t)(y2 + i) * C + x2];
    __syncthreads();
    x2 = by * 32 + tx;
    y2 = bx * 32 + ty;
    #pragma unroll
    for (int i = 0; i < 32; i += 8)
        out[(size_t)(y2 + i) * R + x2] = __float2half_rn(t[tx][ty + i]);
}

// ---------------- tensor-core helpers -------------------------------
__device__ __forceinline__ void ldsm_x4(unsigned& r0, unsigned& r1, unsigned& r2, unsigned& r3,
                                        unsigned addr) {
    asm volatile("ldmatrix.sync.aligned.m8n8.x4.shared.b16 {%0,%1,%2,%3}, [%4];"
                 : "=r"(r0), "=r"(r1), "=r"(r2), "=r"(r3) : "r"(addr));
}

__device__ __forceinline__ void mma_f16(float c[4], unsigned a0, unsigned a1, unsigned a2,
                                        unsigned a3, unsigned b0, unsigned b1) {
    asm volatile(
        "mma.sync.aligned.m16n8k16.row.col.f32.f16.f16.f32 "
        "{%0,%1,%2,%3}, {%4,%5,%6,%7}, {%8,%9}, {%0,%1,%2,%3};"
        : "+f"(c[0]), "+f"(c[1]), "+f"(c[2]), "+f"(c[3])
        : "r"(a0), "r"(a1), "r"(a2), "r"(a3), "r"(b0), "r"(b1));
}

#define CPA16(dst, src) \
    asm volatile("cp.async.cg.shared.global [%0], [%1], 16;" :: "r"(dst), "l"(src))

// ---------------- fp16 GEMM: 128x128 tile, BK=64 halves, 256 thr, 3-stage ------
#define GEMM_SMEM (3 * 32768)

// MODE: 0 = fp32 out (+res), 1 = fp16 out + relu,
//       2 = fp16 out with QSCALE applied to cols < DD (QKV gemm: scales q)
template <int MODE>
__global__ __launch_bounds__(256, 2)
void gemm_tc(const __half* __restrict__ A, const __half* __restrict__ Bt,
             const float* __restrict__ bias, const float* __restrict__ res,
             void* __restrict__ Cv, int M, int N, int K) {
    extern __shared__ unsigned smem_u[];
    unsigned sbase = (unsigned)__cvta_generic_to_shared(smem_u);

    int tid = threadIdx.x;
    int l = tid & 31;
    int wid = tid >> 5;
    int warp_m = wid >> 2;
    int warp_n = wid & 3;
    int bx = blockIdx.x * 128;
    int by = blockIdx.y * 128;

    float acc[4][4][4];
    #pragma unroll
    for (int i = 0; i < 4; i++)
        #pragma unroll
        for (int j = 0; j < 4; j++)
            #pragma unroll
            for (int k = 0; k < 4; k++) acc[i][j][k] = 0.0f;

    int lm = tid >> 3;
    int kc = tid & 7;
    unsigned physc = (unsigned)(kc ^ (lm & 7));
    const __half* aptr = A + (size_t)(by + lm) * K + kc * 8;
    const __half* bptr = Bt + (size_t)(bx + lm) * K + kc * 8;

    int NT = K / 64;

    int rowfrag = (l & 7) + ((l >> 3) & 1) * 8;
    int sel = (l >> 4) & 1;
    int l7 = l & 7;
    int rA = warp_m * 64 + rowfrag;
    int rB = warp_n * 32 + rowfrag;

    auto issue = [&](int kt, unsigned soff) {
        unsigned sA = sbase + soff;
        unsigned sB = sA + 16384u;
        const __half* ap = aptr + kt * 64;
        const __half* bp = bptr + kt * 64;
        #pragma unroll
        for (int i = 0; i < 4; i++) {
            unsigned off = ((unsigned)(lm + 32 * i) * 8 + physc) * 16;
            CPA16(sA + off, ap + (size_t)(32 * i) * K);
            CPA16(sB + off, bp + (size_t)(32 * i) * K);
        }
        asm volatile("cp.async.commit_group;");
    };

    issue(0, 0u);
    issue(1, 32768u);

    unsigned stComp = 0u;
    unsigned stIss = 65536u;

    #pragma unroll 1
    for (int kt = 0; kt < NT; kt++) {
        if (kt < NT - 1) {
            asm volatile("cp.async.wait_group 1;" ::: "memory");
        } else {
            asm volatile("cp.async.wait_group 0;" ::: "memory");
        }
        __syncthreads();

        unsigned sA = sbase + stComp;
        unsigned sB = sA + 16384u;
        stComp = (stComp == 65536u) ? 0u : stComp + 32768u;

        unsigned a[4][4], bf[2][4];
        {
            unsigned phys = (unsigned)(sel ^ l7) * 16u;
            unsigned aBase = sA + (unsigned)rA * 128u + phys;
            unsigned bBase = sB + (unsigned)rB * 128u + phys;
            #pragma unroll
            for (int mt = 0; mt < 4; mt++)
                ldsm_x4(a[mt][0], a[mt][1], a[mt][2], a[mt][3], aBase + mt * 2048u);
            #pragma unroll
            for (int np = 0; np < 2; np++)
                ldsm_x4(bf[np][0], bf[np][1], bf[np][2], bf[np][3], bBase + np * 2048u);
        }

        if (kt + 2 < NT) {
            issue(kt + 2, stIss);
            stIss = (stIss == 65536u) ? 0u : stIss + 32768u;
        }

        #pragma unroll
        for (int mt = 0; mt < 4; mt++)
            #pragma unroll
            for (int nt = 0; nt < 4; nt++)
                mma_f16(acc[mt][nt], a[mt][0], a[mt][1], a[mt][2], a[mt][3],
                        bf[nt >> 1][nt & 1], bf[nt >> 1][(nt & 1) + 2]);

        #pragma unroll
        for (int ks = 1; ks < 4; ks++) {
            unsigned phys = (unsigned)((2 * ks + sel) ^ l7) * 16u;
            unsigned aBase = sA + (unsigned)rA * 128u + phys;
            unsigned bBase = sB + (unsigned)rB * 128u + phys;
            #pragma unroll
            for (int mt = 0; mt < 4; mt++)
                ldsm_x4(a[mt][0], a[mt][1], a[mt][2], a[mt][3], aBase + mt * 2048u);
            #pragma unroll
            for (int np = 0; np < 2; np++)
                ldsm_x4(bf[np][0], bf[np][1], bf[np][2], bf[np][3], bBase + np * 2048u);
            #pragma unroll
            for (int mt = 0; mt < 4; mt++)
                #pragma unroll
                for (int nt = 0; nt < 4; nt++)
                    mma_f16(acc[mt][nt], a[mt][0], a[mt][1], a[mt][2], a[mt][3],
                            bf[nt >> 1][nt & 1], bf[nt >> 1][(nt & 1) + 2]);
        }
    }

    int g = l >> 2, tg = l & 3;
    #pragma unroll
    for (int mt = 0; mt < 4; mt++) {
        int r0 = by + warp_m * 64 + mt * 16 + g;
        #pragma unroll
        for (int nt = 0; nt < 4; nt++) {
            int col = bx + warp_n * 32 + nt * 8 + tg * 2;
            float2 v0 = make_float2(acc[mt][nt][0], acc[mt][nt][1]);
            float2 v1 = make_float2(acc[mt][nt][2], acc[mt][nt][3]);
            if (bias != nullptr) {
                float2 bv = *(const float2*)&bias[col];
                v0.x += bv.x; v0.y += bv.y; v1.x += bv.x; v1.y += bv.y;
            }
            if (MODE == 0) {
                if (res != nullptr) {
                    float2 q0 = *(const float2*)&res[(size_t)r0 * N + col];
                    float2 q1 = *(const float2*)&res[(size_t)(r0 + 8) * N + col];
                    v0.x += q0.x; v0.y += q0.y; v1.x += q1.x; v1.y += q1.y;
                }
                float* C = (float*)Cv;
                *(float2*)&C[(size_t)r0 * N + col] = v0;
                *(float2*)&C[(size_t)(r0 + 8) * N + col] = v1;
            } else {
                if (MODE == 1) {
                    v0.x = fmaxf(v0.x, 0.0f); v0.y = fmaxf(v0.y, 0.0f);
                    v1.x = fmaxf(v1.x, 0.0f); v1.y = fmaxf(v1.y, 0.0f);
                }
                if (MODE == 2 && col < DD) {
                    v0.x *= QSCALE; v0.y *= QSCALE;
                    v1.x *= QSCALE; v1.y *= QSCALE;
                }
                __half* C = (__half*)Cv;
                *(__half2*)&C[(size_t)r0 * N + col] = __floats2half2_rn(v0.x, v0.y);
                *(__half2*)&C[(size_t)(r0 + 8) * N + col] = __floats2half2_rn(v1.x, v1.y);
            }
        }
    }
}

// ---------------- fp16 flash attention, register P, K triple-buffered ----------
// q pre-scaled by QSCALE -> S in log2 domain. ONE barrier per key-tile.
// smem: Q[128][128B] @0 (16KB), K[3][64][128B] @16384 (8KB each, 24KB),
//       VT[2][64][128B] @40960 (8KB each, 16KB). total 56KB -> 2 CTAs/SM.
// K prefetch distance 2 with wait_group 1: K(kt) complete at tile kt's wait
// while K(kt+1) stays in flight. Buffer (kt+2)%3 last read tile kt-1 (drained
// by barrier kt). VT buffer kt&1 last read tile kt-2 (drained by barrier kt-1).
#define ATT_SMEM 57344

__global__ __launch_bounds__(256, 2)
void attn_tc(const __half* __restrict__ qkv, __half* __restrict__ out) {
    extern __shared__ char smc[];
    unsigned ub = (unsigned)__cvta_generic_to_shared(smc);
    unsigned uQ = ub;

    int tid = threadIdx.x;
    int l = tid & 31, w = tid >> 5;
    int b = blockIdx.y >> 4, h = blockIdx.y & 15;
    int q0 = ((int)gridDim.x - 1 - (int)blockIdx.x) * 128;
    int nk = q0 / 64 + 2;

    const __half* base = qkv + (size_t)b * SS * D3 + h * HSZ;

    int lr = tid >> 3, lc = tid & 7;
    unsigned lphys = (unsigned)(lc ^ (lr & 7)) * 16u;

    #pragma unroll
    for (int p = 0; p < 4; p++) {
        int row = lr + 32 * p;
        CPA16(uQ + (unsigned)row * 128u + lphys, base + (size_t)(q0 + row) * D3 + lc * 8);
    }
    auto issueK = [&](int kt, unsigned koff) {
        unsigned uK = ub + 16384u + koff;
        int k0 = kt * 64;
        #pragma unroll
        for (int p = 0; p < 2; p++) {
            int row = lr + 32 * p;
            CPA16(uK + (unsigned)row * 128u + lphys,
                  base + (size_t)(k0 + row) * D3 + DD + lc * 8);
        }
        asm volatile("cp.async.commit_group;");
    };

    int vs2 = (tid & 31) * 2, vdg = tid >> 5;
    uint4 vr0, vr1;
    auto loadV = [&](int k0) {
        const __half* vp = base + (size_t)(k0 + vs2) * D3 + 2 * DD + vdg * 8;
        vr0 = *(const uint4*)vp;
        vr1 = *(const uint4*)(vp + D3);
    };
    issueK(0, 0u);        // group: Q + K(0)
    if (nk > 1) issueK(1, 8192u);
    loadV(0);

    float m2[2] = {-1e30f, -1e30f};
    float l2[2] = {0.0f, 0.0f};
    float oacc[8][4];
    #pragma unroll
    for (int i = 0; i < 8; i++)
        #pragma unroll
        for (int j = 0; j < 4; j++) oacc[i][j] = 0.0f;

    int l7 = l & 7;
    int rowfrag = (l & 7) + ((l >> 3) & 1) * 8;
    int sel = (l >> 4) & 1;
    int rA = w * 16 + rowfrag;
    int rloc = w * 16 + (l >> 2);

    unsigned kComp = 0u;      // K stage offset for compute tile kt
    unsigned kIss = 16384u;   // K stage offset for prefetch tile kt+2

    // ---- hoist Q fragments. Q arrived in group 0 (with K(0)); wait all
    // outstanding (K(1) too if issued) then sync. ----
    unsigned aq[4][4];
    asm volatile("cp.async.wait_group 0;" ::: "memory");
    __syncthreads();
    #pragma unroll
    for (int ks = 0; ks < 4; ks++) {
        unsigned phys = (unsigned)((2 * ks + sel) ^ l7) * 16u;
        ldsm_x4(aq[ks][0], aq[ks][1], aq[ks][2], aq[ks][3], uQ + (unsigned)rA * 128u + phys);
    }

    for (int kt = 0; kt < nk; kt++) {
        int k0 = kt * 64;
        unsigned uK  = ub + 16384u + kComp;
        kComp = (kComp == 16384u) ? 0u : kComp + 8192u;
        unsigned uVT = ub + 40960u + (unsigned)(kt & 1) * 8192u;

        // store V transposed into VT[kt&1]
        {
            const __half* h0 = (const __half*)&vr0;
            const __half* h1 = (const __half*)&vr1;
            unsigned srow = (unsigned)(vs2 >> 3);
            unsigned scol = (unsigned)(vs2 & 7) * 2u;
            unsigned vtb = 40960u + (unsigned)(kt & 1) * 8192u;
            #pragma unroll
            for (int j = 0; j < 8; j++) {
                int d = vdg * 8 + j;
                unsigned phys = (srow ^ (unsigned)(d & 7)) * 16u;
                *(__half2*)(smc + vtb + (unsigned)d * 128u + phys + scol) =
                    __halves2half2(h0[j], h1[j]);
            }
        }
        if (kt < nk - 1) {
            asm volatile("cp.async.wait_group 1;" ::: "memory");
        } else {
            asm volatile("cp.async.wait_group 0;" ::: "memory");
        }
        __syncthreads();   // K(kt)+VT(kt) visible; prior-tile reads drained

        if (kt + 2 < nk) {
            issueK(kt + 2, kIss);
            kIss = (kIss == 16384u) ? 0u : kIss + 8192u;
        }
        if (kt + 1 < nk) loadV(k0 + 64);

        // ---- S = Q K^T (log2 domain) ----
        float sacc[8][4];
        #pragma unroll
        for (int i = 0; i < 8; i++)
            #pragma unroll
            for (int j = 0; j < 4; j++) sacc[i][j] = 0.0f;

        #pragma unroll
        for (int ks = 0; ks < 4; ks++) {
            unsigned phys = (unsigned)((2 * ks + sel) ^ l7) * 16u;
            unsigned bf[4][4];
            #pragma unroll
            for (int np = 0; np < 4; np++)
                ldsm_x4(bf[np][0], bf[np][1], bf[np][2], bf[np][3],
                        uK + (unsigned)(np * 16 + rowfrag) * 128u + phys);
            #pragma unroll
            for (int nt = 0; nt < 8; nt++)
                mma_f16(sacc[nt], aq[ks][0], aq[ks][1], aq[ks][2], aq[ks][3],
                        bf[nt >> 1][nt & 1], bf[nt >> 1][(nt & 1) + 2]);
        }

        if (kt >= nk - 2) {
            #pragma unroll
            for (int nt = 0; nt < 8; nt++)
                #pragma unroll
                for (int e = 0; e < 4; e++) {
                    int r = q0 + rloc + ((e >> 1) << 3);
                    int c = k0 + nt * 8 + 2 * (l & 3) + (e & 1);
                    if (c > r) sacc[nt][e] = -1e30f;
                }
        }

        // online softmax (exp2 domain; 2 rows per thread)
        #pragma unroll
        for (int i = 0; i < 2; i++) {
            float tm = -1e30f;
            #pragma unroll
            for (int nt = 0; nt < 8; nt++)
                tm = fmaxf(tm, fmaxf(sacc[nt][2 * i], sacc[nt][2 * i + 1]));
            tm = fmaxf(tm, __shfl_xor_sync(0xffffffffu, tm, 1));
            tm = fmaxf(tm, __shfl_xor_sync(0xffffffffu, tm, 2));
            float mn = fmaxf(m2[i], tm);
            float alpha = ex2(m2[i] - mn);
            m2[i] = mn;
            float ls = 0.0f;
            #pragma unroll
            for (int nt = 0; nt < 8; nt++) {
                float p0 = ex2(sacc[nt][2 * i] - mn);
                float p1 = ex2(sacc[nt][2 * i + 1] - mn);
                sacc[nt][2 * i] = p0;
                sacc[nt][2 * i + 1] = p1;
                ls += p0 + p1;
            }
            ls += __shfl_xor_sync(0xffffffffu, ls, 1);
            ls += __shfl_xor_sync(0xffffffffu, ls, 2);
            l2[i] = l2[i] * alpha + ls;
            #pragma unroll
            for (int nt = 0; nt < 8; nt++) {
                oacc[nt][2 * i] *= alpha;
                oacc[nt][2 * i + 1] *= alpha;
            }
        }

        // ---- convert P to fp16 A-fragments (in registers) ----
        unsigned pa[4][4];
        #pragma unroll
        for (int ks = 0; ks < 4; ks++) {
            pa[ks][0] = pack_h2(sacc[2 * ks][0], sacc[2 * ks][1]);
            pa[ks][1] = pack_h2(sacc[2 * ks][2], sacc[2 * ks][3]);
            pa[ks][2] = pack_h2(sacc[2 * ks + 1][0], sacc[2 * ks + 1][1]);
            pa[ks][3] = pack_h2(sacc[2 * ks + 1][2], sacc[2 * ks + 1][3]);
        }

        // ---- O += P @ VT^T ----
        #pragma unroll
        for (int ks = 0; ks < 4; ks++) {
            unsigned phys = (unsigned)((2 * ks + sel) ^ l7) * 16u;
            unsigned bf[4][4];
            #pragma unroll
            for (int np = 0; np < 4; np++)
                ldsm_x4(bf[np][0], bf[np][1], bf[np][2], bf[np][3],
                        uVT + (unsigned)(np * 16 + rowfrag) * 128u + phys);
            #pragma unroll
            for (int nt = 0; nt < 8; nt++)
                mma_f16(oacc[nt], pa[ks][0], pa[ks][1], pa[ks][2], pa[ks][3],
                        bf[nt >> 1][nt & 1], bf[nt >> 1][(nt & 1) + 2]);
        }
    }

    float inv0 = 1.0f / l2[0];
    float inv1 = 1.0f / l2[1];
    int r = q0 + rloc;
    int dcol = h * HSZ + 2 * (l & 3);
    #pragma unroll
    for (int nt = 0; nt < 8; nt++) {
        *(__half2*)&out[(size_t)(b * SS + r) * DD + dcol + nt * 8] =
            __floats2half2_rn(oacc[nt][0] * inv0, oacc[nt][1] * inv0);
        *(__half2*)&out[(size_t)(b * SS + r + 8) * DD + dcol + nt * 8] =
            __floats2half2_rn(oacc[nt][2] * inv1, oacc[nt][3] * inv1);
    }
}

// ---------------- launch ----------------
extern "C" void kernel_launch(void* const* d_in, const int* in_sizes, int n_in,
                              void* d_out, int out_size) {
    const float* x     = (const float*)d_in[0];
    const float* wq    = (const float*)d_in[1];
    const float* wk    = (const float*)d_in[2];
    const float* wv    = (const float*)d_in[3];
    const float* wproj = (const float*)d_in[4];
    const float* bproj = (const float*)d_in[5];
    const float* w1    = (const float*)d_in[6];
    const float* b1    = (const float*)d_in[7];
    const float* w2    = (const float*)d_in[8];
    const float* b2    = (const float*)d_in[9];
    const float* ln1_g = (const float*)d_in[10];
    const float* ln1_b = (const float*)d_in[11];
    const float* ln2_g = (const float*)d_in[12];
    const float* ln2_b = (const float*)d_in[13];
    float* out = (float*)d_out;

    __half *p_xn, *p_qkv, *p_attn, *p_hn, *p_ff;
    __half *p_wqkvT, *p_wprojT, *p_w1T, *p_w2T;
    float *p_h;
    cudaGetSymbolAddress((void**)&p_xn, g_xn);
    cudaGetSymbolAddress((void**)&p_qkv, g_qkv);
    cudaGetSymbolAddress((void**)&p_attn, g_attn);
    cudaGetSymbolAddress((void**)&p_h, g_h);
    cudaGetSymbolAddress((void**)&p_hn, g_hn);
    cudaGetSymbolAddress((void**)&p_ff, g_ff);
    cudaGetSymbolAddress((void**)&p_wqkvT, g_wqkvT);
    cudaGetSymbolAddress((void**)&p_wprojT, g_wprojT);
    cudaGetSymbolAddress((void**)&p_w1T, g_w1T);
    cudaGetSymbolAddress((void**)&p_w2T, g_w2T);

    cudaFuncSetAttribute(gemm_tc<0>, cudaFuncAttributeMaxDynamicSharedMemorySize, GEMM_SMEM);
    cudaFuncSetAttribute(gemm_tc<1>, cudaFuncAttributeMaxDynamicSharedMemorySize, GEMM_SMEM);
    cudaFuncSetAttribute(gemm_tc<2>, cudaFuncAttributeMaxDynamicSharedMemorySize, GEMM_SMEM);
    cudaFuncSetAttribute(attn_tc, cudaFuncAttributeMaxDynamicSharedMemorySize, ATT_SMEM);

    // prep: fused weight transposes + wqkvT + LN1 (one launch)
    prep_kernel<<<9984 + BS, 256>>>(wq, wk, wv, p_wqkvT, wproj, p_wprojT,
                                    w1, p_w1T, w2, p_w2T, x, ln1_g, ln1_b, p_xn);

    // QKV GEMM -> fp16 qkv (q pre-scaled by QSCALE)
    gemm_tc<2><<<dim3(D3 / 128, BS / 128), 256, GEMM_SMEM>>>(
        p_xn, p_wqkvT, nullptr, nullptr, p_qkv, BS, D3, DD);

    // fp16 flash attention (register-resident P, log2-domain S, K 3-buffered)
    attn_tc<<<dim3(SS / 128, BB * HH), 256, ATT_SMEM>>>(p_qkv, p_attn);

    // proj + bias + residual(x) -> h (fp32)
    gemm_tc<0><<<dim3(DD / 128, BS / 128), 256, GEMM_SMEM>>>(
        p_attn, p_wprojT, bproj, x, p_h, BS, DD, DD);

    // LN2 -> fp16 hn
    ln_kernel<<<BS, 256>>>(p_h, ln2_g, ln2_b, p_hn);

    // FF1 + bias + relu -> fp16 ff
    gemm_tc<1><<<dim3(DFF / 128, BS / 128), 256, GEMM_SMEM>>>(
        p_hn, p_w1T, b1, nullptr, p_ff, BS, DFF, DD);

    // FF2 + bias + residual(h) -> out (fp32)
    gemm_tc<0><<<dim3(DD / 128, BS / 128), 256, GEMM_SMEM>>>(
        p_ff, p_w2T, b2, p_h, out, BS, DD, DFF);
}